// round 6
// baseline (speedup 1.0000x reference)
#include <cuda_runtime.h>
#include <cstdint>

#define B_  4
#define C_  256
#define CQ_ 32
#define N_  4096
#define HW_ 64

// ---------------- scratch (device globals; no allocation) ----------------
__device__ float g_q[B_ * CQ_ * N_];
__device__ float g_k[B_ * CQ_ * N_];
__device__ float g_v[B_ * C_ * N_];
__device__ float g_cat[(size_t)B_ * 2 * C_ * N_];   // [b][512][4096]
__device__ float g_cattn[B_ * C_ * C_];
__device__ float g_y[(size_t)B_ * C_ * N_];
__device__ float g_mean[C_];
__device__ float g_rstd[C_];

// ---------------- PTX helpers (sm_80+ mma.sync / cp.async) ----------------
__device__ __forceinline__ uint32_t smem_to_u32(const void* p) {
    uint32_t a;
    asm("{ .reg .u64 t; cvta.to.shared.u64 t, %1; cvt.u32.u64 %0, t; }" : "=r"(a) : "l"(p));
    return a;
}
__device__ __forceinline__ void cp16(uint32_t dst, const void* src) {
    asm volatile("cp.async.cg.shared.global [%0], [%1], 16;" :: "r"(dst), "l"(src));
}
#define CP_COMMIT() asm volatile("cp.async.commit_group;" ::: "memory")
#define CP_WAIT(n)  asm volatile("cp.async.wait_group %0;" :: "n"(n) : "memory")

__device__ __forceinline__ uint32_t ld_tf32(const float* p) {
    uint32_t r;
    float f = *p;
    asm("cvt.rna.tf32.f32 %0, %1;" : "=r"(r) : "f"(f));
    return r;
}
__device__ __forceinline__ void mma_tf32(float c[4], uint32_t a0, uint32_t a1,
                                         uint32_t a2, uint32_t a3,
                                         uint32_t b0, uint32_t b1) {
    asm volatile(
        "mma.sync.aligned.m16n8k8.row.col.f32.tf32.tf32.f32 "
        "{%0,%1,%2,%3}, {%4,%5,%6,%7}, {%8,%9}, {%0,%1,%2,%3};"
        : "+f"(c[0]), "+f"(c[1]), "+f"(c[2]), "+f"(c[3])
        : "r"(a0), "r"(a1), "r"(a2), "r"(a3), "r"(b0), "r"(b1));
}

// =================================================================
// Fused flash attention (position attention path):
//   cat[b, c, i] = gamma_pa * (1/l_i) * sum_j v[b,c,j] * exp(s[i,j]) + x[b,c,i]
//   s[i,j] = sum_d q[d,i] k[d,j],  l_i = sum_j exp(s[i,j])
// No max-subtraction: |s| <= ~40 -> exp fits fp32; l <= ~2e18 fits fp32.
// CTA: i-block 128 (bx), c-tile 128 (by), batch (bz). 256 threads / 8 warps.
//   s-mma:  warp w -> i rows [w*16, w*16+16), j tile 64. q frags cached in regs.
//           k fragments read straight from global (L1-resident tile).
//   pv-mma: warp (wm=w&3, wn=w>>2) -> c rows wm*32+.., i cols wn*64+..
//           p goes through smem p_s[128][68] (conflict-free frag reads).
// =================================================================
__global__ void __launch_bounds__(256)
flash_pa(const float* __restrict__ qg, const float* __restrict__ kg,
         const float* __restrict__ vg, const float* __restrict__ x,
         const float* __restrict__ gpa, float* __restrict__ cat) {
    __shared__ float p_s[128 * 68 + 128];
    float* stats = p_s + 128 * 68;

    int tid = threadIdx.x, lane = tid & 31, w = tid >> 5;
    int wm = w & 3, wn = w >> 2;
    int b = blockIdx.z;
    int I0 = blockIdx.x * 128;
    int c0 = blockIdx.y * 128;
    const float* Qg = qg + (long)b * CQ_ * N_;
    const float* Kg = kg + (long)b * CQ_ * N_;
    const float* Vg = vg + (long)b * C_ * N_;

    // q fragments, loop-invariant. A[m=i][k=d] = q[d][i].
    uint32_t aq[4][4];
    {
        int i = I0 + w * 16 + (lane >> 2);
        #pragma unroll
        for (int k8 = 0; k8 < 4; k8++) {
            int d = k8 * 8 + (lane & 3);
            const float* qp = Qg + (long)d * N_ + i;
            aq[k8][0] = ld_tf32(qp);            // (i, d)
            aq[k8][1] = ld_tf32(qp + 8);        // (i+8, d)
            aq[k8][2] = ld_tf32(qp + 4 * N_);   // (i, d+4)
            aq[k8][3] = ld_tf32(qp + 4 * N_ + 8);
        }
    }

    float acc[2][8][4] = {};
    float l0 = 0.f, l1 = 0.f;   // per-thread partial row sums (quad-reduced at end)

    for (int jt = 0; jt < 64; jt++) {
        // ---- s = Q^T K tile (128 i x 64 j) ----
        float s[8][4] = {};
        #pragma unroll
        for (int k8 = 0; k8 < 4; k8++) {
            int d = k8 * 8 + (lane & 3);
            const float* kp = Kg + (long)d * N_ + jt * 64 + (lane >> 2);
            #pragma unroll
            for (int nt = 0; nt < 8; nt++) {
                uint32_t b0 = ld_tf32(kp + nt * 8);           // (n=j, k=d)
                uint32_t b1 = ld_tf32(kp + 4 * N_ + nt * 8);  // (n=j, k=d+4)
                mma_tf32(s[nt], aq[k8][0], aq[k8][1], aq[k8][2], aq[k8][3], b0, b1);
            }
        }
        // ---- p = exp(s); accumulate row sums; store p to smem ----
        int r0 = (w * 16 + (lane >> 2)) * 68 + 2 * (lane & 3);
        #pragma unroll
        for (int nt = 0; nt < 8; nt++) {
            float p0 = __expf(s[nt][0]), p1 = __expf(s[nt][1]);
            float p2 = __expf(s[nt][2]), p3 = __expf(s[nt][3]);
            l0 += p0 + p1;
            l1 += p2 + p3;
            *(float2*)&p_s[r0 + nt * 8] = make_float2(p0, p1);
            *(float2*)&p_s[r0 + 8 * 68 + nt * 8] = make_float2(p2, p3);
        }
        __syncthreads();
        // ---- acc += V(c,j) @ P(i,j)^T   (M=c, N=i, K=j=64) ----
        #pragma unroll
        for (int k8 = 0; k8 < 8; k8++) {
            uint32_t a[2][4];
            const float* vp = Vg + (long)(c0 + wm * 32 + (lane >> 2)) * N_
                              + jt * 64 + k8 * 8 + (lane & 3);
            #pragma unroll
            for (int mt = 0; mt < 2; mt++) {
                const float* ap = vp + (long)mt * 16 * N_;
                a[mt][0] = ld_tf32(ap);
                a[mt][1] = ld_tf32(ap + 8 * N_);
                a[mt][2] = ld_tf32(ap + 4);
                a[mt][3] = ld_tf32(ap + 8 * N_ + 4);
            }
            #pragma unroll
            for (int nt = 0; nt < 8; nt++) {
                const float* pp = &p_s[(wn * 64 + nt * 8 + (lane >> 2)) * 68
                                       + k8 * 8 + (lane & 3)];
                uint32_t b0 = ld_tf32(pp);
                uint32_t b1 = ld_tf32(pp + 4);
                #pragma unroll
                for (int mt = 0; mt < 2; mt++)
                    mma_tf32(acc[mt][nt], a[mt][0], a[mt][1], a[mt][2], a[mt][3], b0, b1);
            }
        }
        __syncthreads();
    }

    // finalize row sums: quad-reduce (lanes lane&3 share a row)
    l0 += __shfl_xor_sync(0xffffffffu, l0, 1);
    l0 += __shfl_xor_sync(0xffffffffu, l0, 2);
    l1 += __shfl_xor_sync(0xffffffffu, l1, 1);
    l1 += __shfl_xor_sync(0xffffffffu, l1, 2);
    if ((lane & 3) == 0) {
        stats[w * 16 + (lane >> 2)] = 1.f / l0;
        stats[w * 16 + 8 + (lane >> 2)] = 1.f / l1;
    }
    __syncthreads();

    // epilogue: normalize by 1/l_i, gamma * . + x
    float g = gpa[0];
    #pragma unroll
    for (int nt = 0; nt < 8; nt++) {
        int il = wn * 64 + nt * 8 + 2 * (lane & 3);
        float inv0 = stats[il], inv1 = stats[il + 1];
        #pragma unroll
        for (int mt = 0; mt < 2; mt++) {
            int row = c0 + wm * 32 + mt * 16 + (lane >> 2);
            int col = I0 + il;
            long xo = ((long)b * C_ + row) * N_ + col;
            long co = ((long)b * 2 * C_ + row) * N_ + col;
            *(float2*)(cat + co) = make_float2(
                fmaf(g, acc[mt][nt][0] * inv0, x[xo]),
                fmaf(g, acc[mt][nt][1] * inv1, x[xo + 1]));
            *(float2*)(cat + co + 8 * N_) = make_float2(
                fmaf(g, acc[mt][nt][2] * inv0, x[xo + 8 * N_]),
                fmaf(g, acc[mt][nt][3] * inv1, x[xo + 8 * N_ + 1]));
        }
    }
}

// =================================================================
// NN-GEMM (tf32 mma.sync): Out[m][n] = sum_k A[m][k] * B[k][n]
// A k-contiguous (lda=K), B n-contiguous (ldb=N_=4096). CTA 128x128, BK=32,
// cp.async double buffer. epi: 0 -> +bias[m]; 1 -> gamma*acc + res.
// Used for: v-projection (wv @ x + bv) and ca (cattn @ x, gamma_ca, +x).
// =================================================================
#define NN_SMEM_BYTES ((2 * 128 * 36 + 2 * 32 * 132) * 4)   // 70656

__global__ void __launch_bounds__(256)
gemm_nn_mma(const float* __restrict__ A, const float* __restrict__ B,
            float* __restrict__ Out, int K, int epi,
            const float* __restrict__ bias, const float* __restrict__ gsc,
            const float* __restrict__ res,
            long sA, long sB, long sO, long sR) {
    extern __shared__ float sm[];
    float* As = sm;                      // 2 x [128][36]
    float* Bs = sm + 2 * 128 * 36;       // 2 x [32][132]
    int tid = threadIdx.x, lane = tid & 31, w = tid >> 5;
    int wm = w & 3, wn = w >> 2;
    int b = blockIdx.z, m0 = blockIdx.y * 128, n0 = blockIdx.x * 128;
    const float* Ag = A + sA * b + (long)m0 * K;
    const float* Bg = B + sB * b + n0;
    uint32_t smu_a = smem_to_u32(As), smu_b = smem_to_u32(Bs);
    float acc[2][8][4] = {};
    int nchunks = K / 32;

    #pragma unroll
    for (int s = 0; s < 2; s++) {
        #pragma unroll
        for (int jj = 0; jj < 4; jj++) {
            int idx = tid + 256 * jj;
            int r = idx >> 3, kq = (idx & 7) * 4;
            cp16(smu_a + (s * 4608 + r * 36 + kq) * 4, Ag + (long)r * K + s * 32 + kq);
            int kk = idx >> 5, nq = (idx & 31) * 4;
            cp16(smu_b + (s * 4224 + kk * 132 + nq) * 4, Bg + (long)(s * 32 + kk) * N_ + nq);
        }
        CP_COMMIT();
    }

    for (int ch = 0; ch < nchunks; ch++) {
        if (ch < nchunks - 2) { CP_WAIT(1); } else { CP_WAIT(0); }
        __syncthreads();
        const float* As_ = As + (ch & 1) * 4608;
        const float* Bs_ = Bs + (ch & 1) * 4224;
        #pragma unroll
        for (int k8 = 0; k8 < 32; k8 += 8) {
            uint32_t a[2][4], bb[8][2];
            #pragma unroll
            for (int mt = 0; mt < 2; mt++) {
                const float* ap = As_ + (wm * 32 + mt * 16 + (lane >> 2)) * 36 + k8 + (lane & 3);
                a[mt][0] = ld_tf32(ap);
                a[mt][1] = ld_tf32(ap + 8 * 36);
                a[mt][2] = ld_tf32(ap + 4);
                a[mt][3] = ld_tf32(ap + 8 * 36 + 4);
            }
            #pragma unroll
            for (int nt = 0; nt < 8; nt++) {
                const float* bp = Bs_ + (k8 + (lane & 3)) * 132 + wn * 64 + nt * 8 + (lane >> 2);
                bb[nt][0] = ld_tf32(bp);
                bb[nt][1] = ld_tf32(bp + 4 * 132);
            }
            #pragma unroll
            for (int mt = 0; mt < 2; mt++)
                #pragma unroll
                for (int nt = 0; nt < 8; nt++)
                    mma_tf32(acc[mt][nt], a[mt][0], a[mt][1], a[mt][2], a[mt][3],
                             bb[nt][0], bb[nt][1]);
        }
        __syncthreads();
        if (ch + 2 < nchunks) {
            int s = ch & 1;
            #pragma unroll
            for (int jj = 0; jj < 4; jj++) {
                int idx = tid + 256 * jj;
                int r = idx >> 3, kq = (idx & 7) * 4;
                cp16(smu_a + (s * 4608 + r * 36 + kq) * 4,
                     Ag + (long)r * K + (ch + 2) * 32 + kq);
                int kk = idx >> 5, nq = (idx & 31) * 4;
                cp16(smu_b + (s * 4224 + kk * 132 + nq) * 4,
                     Bg + (long)((ch + 2) * 32 + kk) * N_ + nq);
            }
            CP_COMMIT();
        }
    }

    float g = gsc ? *gsc : 0.f;
    const float* resb = res ? res + sR * b : nullptr;
    float* Ob = Out + sO * b;
    #pragma unroll
    for (int mt = 0; mt < 2; mt++) {
        int row = m0 + wm * 32 + mt * 16 + (lane >> 2);
        #pragma unroll
        for (int nt = 0; nt < 8; nt++) {
            int col = n0 + wn * 64 + nt * 8 + 2 * (lane & 3);
            long o = (long)row * N_ + col;
            if (epi == 0) {
                float bv = bias[row], bv8 = bias[row + 8];
                *(float2*)(Ob + o) = make_float2(acc[mt][nt][0] + bv, acc[mt][nt][1] + bv);
                *(float2*)(Ob + o + 8 * N_) =
                    make_float2(acc[mt][nt][2] + bv8, acc[mt][nt][3] + bv8);
            } else {
                *(float2*)(Ob + o) = make_float2(
                    fmaf(g, acc[mt][nt][0], resb[o]), fmaf(g, acc[mt][nt][1], resb[o + 1]));
                *(float2*)(Ob + o + 8 * N_) = make_float2(
                    fmaf(g, acc[mt][nt][2], resb[o + 8 * N_]),
                    fmaf(g, acc[mt][nt][3], resb[o + 8 * N_ + 1]));
            }
        }
    }
}

// ---------------- helpers ----------------
__device__ __forceinline__ float warpMax(float v) {
    #pragma unroll
    for (int o = 16; o; o >>= 1) v = fmaxf(v, __shfl_xor_sync(0xffffffffu, v, o));
    return v;
}
__device__ __forceinline__ float warpSum(float v) {
    #pragma unroll
    for (int o = 16; o; o >>= 1) v += __shfl_xor_sync(0xffffffffu, v, o);
    return v;
}

// 64x64 tile compute: acc[4][4] += As[k][m] * Bs[k][n]
__device__ __forceinline__ void mma_tile(const float (*As)[64], const float (*Bs)[64],
                                         float acc[4][4], int ty, int tx) {
    #pragma unroll
    for (int k = 0; k < 16; k++) {
        float4 a = *(const float4*)&As[k][ty * 4];
        float4 b = *(const float4*)&Bs[k][tx * 4];
        float ar[4] = {a.x, a.y, a.z, a.w};
        float br[4] = {b.x, b.y, b.z, b.w};
        #pragma unroll
        for (int i = 0; i < 4; i++)
            #pragma unroll
            for (int j = 0; j < 4; j++)
                acc[i][j] = fmaf(ar[i], br[j], acc[i][j]);
    }
}

__device__ __forceinline__ void epilogue(float* Out, int M, int N, int m0, int n0,
                                         int ty, int tx, float acc[4][4], int epi,
                                         const float* bias, const float* gsc,
                                         const float* res) {
    float g = gsc ? *gsc : 0.f;
    #pragma unroll
    for (int i = 0; i < 4; i++) {
        int m = m0 + ty * 4 + i;
        if (m < M) {
            long off = (long)m * N + n0 + tx * 4;
            float4 o;
            if (epi == 0) {
                float bv = bias[m];
                o = make_float4(acc[i][0] + bv, acc[i][1] + bv, acc[i][2] + bv, acc[i][3] + bv);
            } else if (epi == 1) {
                float4 r = *(const float4*)(res + off);
                o = make_float4(fmaf(g, acc[i][0], r.x), fmaf(g, acc[i][1], r.y),
                                fmaf(g, acc[i][2], r.z), fmaf(g, acc[i][3], r.w));
            } else {
                o = make_float4(acc[i][0], acc[i][1], acc[i][2], acc[i][3]);
            }
            *(float4*)(Out + off) = o;
        }
    }
}

// ---------------- fp32 SIMT GEMMs (small ops: q/k proj, channel logits) ----------------

__global__ void gemm_nn_k(const float* __restrict__ A, const float* __restrict__ Bm,
                          float* __restrict__ Out, int M, int N, int K, int epi,
                          const float* __restrict__ bias, const float* __restrict__ gsc,
                          const float* __restrict__ res,
                          long sA, long sB, long sO, long sR) {
    int b = blockIdx.z;
    A += sA * b; Bm += sB * b; Out += sO * b;
    const float* resb = res ? res + sR * b : nullptr;
    __shared__ float As[16][64];
    __shared__ float Bs[16][64];
    int tid = threadIdx.x;
    int tx = tid & 15, ty = tid >> 4;
    int m0 = blockIdx.y * 64, n0 = blockIdx.x * 64;
    int arow = tid >> 2, ak = (tid & 3) * 4;
    int brow = tid >> 4, bn = (tid & 15) * 4;
    float acc[4][4] = {};
    for (int k0 = 0; k0 < K; k0 += 16) {
        float4 av = make_float4(0.f, 0.f, 0.f, 0.f);
        if (m0 + arow < M) av = *(const float4*)(A + (long)(m0 + arow) * K + k0 + ak);
        As[ak + 0][arow] = av.x; As[ak + 1][arow] = av.y;
        As[ak + 2][arow] = av.z; As[ak + 3][arow] = av.w;
        *(float4*)&Bs[brow][bn] = *(const float4*)(Bm + (long)(k0 + brow) * N + n0 + bn);
        __syncthreads();
        mma_tile(As, Bs, acc, ty, tx);
        __syncthreads();
    }
    epilogue(Out, M, N, m0, n0, ty, tx, acc, epi, bias, gsc, resb);
}

__global__ void gemm_nt_k(const float* __restrict__ A, const float* __restrict__ Bm,
                          float* __restrict__ Out, int M, int N, int K, int epi,
                          const float* __restrict__ bias, const float* __restrict__ gsc,
                          const float* __restrict__ res,
                          long sA, long sB, long sO, long sR) {
    int b = blockIdx.z;
    A += sA * b; Bm += sB * b; Out += sO * b;
    const float* resb = res ? res + sR * b : nullptr;
    __shared__ float As[16][64];
    __shared__ float Bs[16][64];
    int tid = threadIdx.x;
    int tx = tid & 15, ty = tid >> 4;
    int m0 = blockIdx.y * 64, n0 = blockIdx.x * 64;
    int arow = tid >> 2, ak = (tid & 3) * 4;
    float acc[4][4] = {};
    for (int k0 = 0; k0 < K; k0 += 16) {
        float4 av = make_float4(0.f, 0.f, 0.f, 0.f);
        if (m0 + arow < M) av = *(const float4*)(A + (long)(m0 + arow) * K + k0 + ak);
        As[ak + 0][arow] = av.x; As[ak + 1][arow] = av.y;
        As[ak + 2][arow] = av.z; As[ak + 3][arow] = av.w;
        float4 bv = *(const float4*)(Bm + (long)(n0 + arow) * K + k0 + ak);
        Bs[ak + 0][arow] = bv.x; Bs[ak + 1][arow] = bv.y;
        Bs[ak + 2][arow] = bv.z; Bs[ak + 3][arow] = bv.w;
        __syncthreads();
        mma_tile(As, Bs, acc, ty, tx);
        __syncthreads();
    }
    epilogue(Out, M, N, m0, n0, ty, tx, acc, epi, bias, gsc, resb);
}

// ---------------- softmax over 256 (channel attention) ----------------
__global__ void softmax256(float* __restrict__ data) {
    __shared__ float sh[8];
    float* p = data + (size_t)blockIdx.x * 256;
    int tid = threadIdx.x;
    float v = p[tid];
    float m = warpMax(v);
    if ((tid & 31) == 0) sh[tid >> 5] = m;
    __syncthreads();
    m = sh[tid & 7];
    #pragma unroll
    for (int o = 4; o; o >>= 1) m = fmaxf(m, __shfl_xor_sync(0xffffffffu, m, o));
    __syncthreads();
    float e = __expf(v - m);
    float s = warpSum(e);
    if ((tid & 31) == 0) sh[tid >> 5] = s;
    __syncthreads();
    s = sh[tid & 7];
    #pragma unroll
    for (int o = 4; o; o >>= 1) s += __shfl_xor_sync(0xffffffffu, s, o);
    p[tid] = e / s;
}

// =================================================================
// 3x3 conv 512 -> 256 as implicit GEMM (tf32 mma.sync)
// =================================================================
#define CV_SMEM_BYTES ((9728 + 9728 + 2112) * 4)   // 86272

__global__ void __launch_bounds__(256)
conv_mma(const float* __restrict__ cat, const float* __restrict__ wf,
         float* __restrict__ y) {
    extern __shared__ float sm[];
    float* As = sm;             // 128*76
    float* Bs = sm + 9728;      // 128*76
    float* patch = sm + 19456;  // 8*4*66
    int tid = threadIdx.x, lane = tid & 31, wid = tid >> 5;
    int wm = wid & 3, wn = wid >> 2;
    int b = blockIdx.z, o0 = blockIdx.y * 128, p0 = blockIdx.x * 128;
    int h0 = blockIdx.x * 2;
    uint32_t smu = smem_to_u32(sm);

    float c[2][8][4] = {};

    for (int chunk = 0; chunk < 64; chunk++) {
        __syncthreads();
        #pragma unroll
        for (int j = 0; j < 9; j++) {
            int flat = tid + 256 * j;
            int r = flat / 18, q = (flat % 18) * 4;
            cp16(smu + (r * 76 + q) * 4, wf + (long)(o0 + r) * 4608 + chunk * 72 + q);
        }
        CP_COMMIT();
        int ci0 = chunk * 8;
        #pragma unroll
        for (int p = 0; p < 8; p++) {
            int flat = p * 256 + tid;
            int ci = flat >> 8, row = (flat >> 6) & 3, w = flat & 63;
            int h = h0 - 1 + row;
            float val = (h >= 0 && h < 64)
                ? cat[((long)b * 512 + ci0 + ci) * 4096 + h * 64 + w] : 0.f;
            patch[ci * 264 + row * 66 + w + 1] = val;
        }
        if (tid < 64) {
            int ci = tid >> 3, row = (tid >> 1) & 3, side = tid & 1;
            patch[ci * 264 + row * 66 + side * 65] = 0.f;
        }
        CP_WAIT(0);
        __syncthreads();
        {
            int n = tid >> 1, half = tid & 1;
            int hh = n >> 6, w = n & 63;
            const float* pb = patch + half * 4 * 264 + hh * 66 + w;
            float* brow = Bs + n * 76 + half * 36;
            #pragma unroll
            for (int ci_l = 0; ci_l < 4; ci_l++)
                #pragma unroll
                for (int kh = 0; kh < 3; kh++)
                    #pragma unroll
                    for (int kw = 0; kw < 3; kw++)
                        brow[ci_l * 9 + kh * 3 + kw] = pb[ci_l * 264 + kh * 66 + kw];
        }
        __syncthreads();
        #pragma unroll
        for (int k8 = 0; k8 < 72; k8 += 8) {
            uint32_t a[2][4], bb[8][2];
            #pragma unroll
            for (int mt = 0; mt < 2; mt++) {
                const float* ap = As + (wm * 32 + mt * 16 + (lane >> 2)) * 76 + k8 + (lane & 3);
                a[mt][0] = ld_tf32(ap);
                a[mt][1] = ld_tf32(ap + 8 * 76);
                a[mt][2] = ld_tf32(ap + 4);
                a[mt][3] = ld_tf32(ap + 8 * 76 + 4);
            }
            #pragma unroll
            for (int nt = 0; nt < 8; nt++) {
                const float* bp = Bs + (wn * 64 + nt * 8 + (lane >> 2)) * 76 + k8 + (lane & 3);
                bb[nt][0] = ld_tf32(bp);
                bb[nt][1] = ld_tf32(bp + 4);
            }
            #pragma unroll
            for (int mt = 0; mt < 2; mt++)
                #pragma unroll
                for (int nt = 0; nt < 8; nt++)
                    mma_tf32(c[mt][nt], a[mt][0], a[mt][1], a[mt][2], a[mt][3],
                             bb[nt][0], bb[nt][1]);
        }
    }

    #pragma unroll
    for (int mt = 0; mt < 2; mt++) {
        #pragma unroll
        for (int nt = 0; nt < 8; nt++) {
            int row = o0 + wm * 32 + mt * 16 + (lane >> 2);
            int col = p0 + wn * 64 + nt * 8 + 2 * (lane & 3);
            long yo = ((long)b * 256 + row) * 4096 + col;
            *(float2*)(y + yo) = make_float2(c[mt][nt][0], c[mt][nt][1]);
            *(float2*)(y + yo + 8 * 4096) = make_float2(c[mt][nt][2], c[mt][nt][3]);
        }
    }
}

// ---------------- BN (train-mode batch stats) + ReLU ----------------
__global__ void bnstats(const float* __restrict__ y, float* __restrict__ meanp,
                        float* __restrict__ rstdp) {
    __shared__ float sh[16];
    int o = blockIdx.x, tid = threadIdx.x;
    float s = 0.f, sq = 0.f;
    for (int b = 0; b < 4; b++) {
        const float4* p = (const float4*)(y + ((size_t)b * 256 + o) * 4096);
        for (int i = tid; i < 1024; i += 256) {
            float4 v = p[i];
            s += v.x + v.y + v.z + v.w;
            sq += v.x * v.x + v.y * v.y + v.z * v.z + v.w * v.w;
        }
    }
    s = warpSum(s); sq = warpSum(sq);
    if ((tid & 31) == 0) { sh[tid >> 5] = s; sh[8 + (tid >> 5)] = sq; }
    __syncthreads();
    if (tid == 0) {
        float S = 0.f, SQ = 0.f;
        for (int i = 0; i < 8; i++) { S += sh[i]; SQ += sh[8 + i]; }
        float mean = S / 16384.f;
        float var = SQ / 16384.f - mean * mean;
        meanp[o] = mean;
        rstdp[o] = rsqrtf(var + 1e-5f);
    }
}

__global__ void bnapply(const float* __restrict__ y, const float* __restrict__ gam,
                        const float* __restrict__ bet, const float* __restrict__ meanp,
                        const float* __restrict__ rstdp, float* __restrict__ out) {
    size_t i = (size_t)blockIdx.x * 256 + threadIdx.x;  // float4 index
    int o = (int)((i >> 10) & 255);
    float mu = meanp[o], rs = rstdp[o], g = gam[o], be = bet[o];
    float4 v = ((const float4*)y)[i];
    float4 r;
    r.x = fmaxf(0.f, fmaf((v.x - mu) * rs, g, be));
    r.y = fmaxf(0.f, fmaf((v.y - mu) * rs, g, be));
    r.z = fmaxf(0.f, fmaf((v.z - mu) * rs, g, be));
    r.w = fmaxf(0.f, fmaf((v.w - mu) * rs, g, be));
    ((float4*)out)[i] = r;
}

// ---------------- launcher ----------------
extern "C" void kernel_launch(void* const* d_in, const int* in_sizes, int n_in,
                              void* d_out, int out_size) {
    const float* x   = (const float*)d_in[0];
    const float* wq  = (const float*)d_in[1];
    const float* bq  = (const float*)d_in[2];
    const float* wk  = (const float*)d_in[3];
    const float* bk  = (const float*)d_in[4];
    const float* wv  = (const float*)d_in[5];
    const float* bv  = (const float*)d_in[6];
    const float* gpa = (const float*)d_in[7];
    const float* gca = (const float*)d_in[8];
    const float* wf  = (const float*)d_in[9];
    const float* bng = (const float*)d_in[10];
    const float* bnb = (const float*)d_in[11];
    float* out = (float*)d_out;

    float *q, *k, *v, *cat, *cattn, *y, *mean, *rstd;
    cudaGetSymbolAddress((void**)&q, g_q);
    cudaGetSymbolAddress((void**)&k, g_k);
    cudaGetSymbolAddress((void**)&v, g_v);
    cudaGetSymbolAddress((void**)&cat, g_cat);
    cudaGetSymbolAddress((void**)&cattn, g_cattn);
    cudaGetSymbolAddress((void**)&y, g_y);
    cudaGetSymbolAddress((void**)&mean, g_mean);
    cudaGetSymbolAddress((void**)&rstd, g_rstd);

    cudaFuncSetAttribute(gemm_nn_mma, cudaFuncAttributeMaxDynamicSharedMemorySize,
                         NN_SMEM_BYTES);
    cudaFuncSetAttribute(conv_mma, cudaFuncAttributeMaxDynamicSharedMemorySize,
                         CV_SMEM_BYTES);

    dim3 blk(256);
    long sx = (long)C_ * N_;
    long sqk = (long)CQ_ * N_;
    long scat = (long)2 * C_ * N_;

    // q, k projections (small; fp32 SIMT)
    gemm_nn_k<<<dim3(64, 1, 4), blk>>>(wq, x, q, CQ_, N_, C_, 0, bq, nullptr, nullptr,
                                       0, sx, sqk, 0);
    gemm_nn_k<<<dim3(64, 1, 4), blk>>>(wk, x, k, CQ_, N_, C_, 0, bk, nullptr, nullptr,
                                       0, sx, sqk, 0);
    // v projection on tensor cores
    gemm_nn_mma<<<dim3(32, 2, 4), blk, NN_SMEM_BYTES>>>(
        wv, x, v, C_, 0, bv, nullptr, nullptr, 0, sx, sx, 0);
    // fused logits + softmax + PA -> cat[:, 0:256]
    flash_pa<<<dim3(32, 2, 4), blk>>>(q, k, v, x, gpa, cat);
    // channel attention: logits, softmax, apply -> cat[:, 256:512]
    gemm_nt_k<<<dim3(4, 4, 4), blk>>>(x, x, cattn, C_, C_, N_, 2, nullptr, nullptr,
                                      nullptr, sx, sx, (long)C_ * C_, 0);
    softmax256<<<B_ * C_, 256>>>(cattn);
    gemm_nn_mma<<<dim3(32, 2, 4), blk, NN_SMEM_BYTES>>>(
        cattn, x, cat + (size_t)C_ * N_, C_, 1, nullptr, gca, x,
        (long)C_ * C_, sx, scat, sx);
    // 3x3 conv 512->256 (implicit GEMM, tensor cores)
    conv_mma<<<dim3(32, 2, 4), blk, CV_SMEM_BYTES>>>(cat, wf, y);
    // BN train-mode + ReLU
    bnstats<<<256, 256>>>(y, mean, rstd);
    bnapply<<<4096, 256>>>(y, bng, bnb, mean, rstd, out);
}

// round 7
// speedup vs baseline: 1.4737x; 1.4737x over previous
#include <cuda_runtime.h>
#include <cstdint>

#define B_  4
#define C_  256
#define CQ_ 32
#define N_  4096
#define HW_ 64

// ---------------- scratch (device globals; no allocation) ----------------
__device__ float g_q[B_ * CQ_ * N_];
__device__ float g_k[B_ * CQ_ * N_];
__device__ float g_v[B_ * C_ * N_];
__device__ float g_attn[(size_t)B_ * N_ * N_];      // exp(logits), 256 MB
__device__ float g_cat[(size_t)B_ * 2 * C_ * N_];   // [b][512][4096]
__device__ float g_cattn[B_ * C_ * C_];
__device__ float g_y[(size_t)B_ * C_ * N_];
__device__ float g_mean[C_];
__device__ float g_rstd[C_];

// ---------------- PTX helpers (sm_80+ mma.sync / cp.async) ----------------
__device__ __forceinline__ uint32_t smem_to_u32(const void* p) {
    uint32_t a;
    asm("{ .reg .u64 t; cvta.to.shared.u64 t, %1; cvt.u32.u64 %0, t; }" : "=r"(a) : "l"(p));
    return a;
}
__device__ __forceinline__ void cp16(uint32_t dst, const void* src) {
    asm volatile("cp.async.cg.shared.global [%0], [%1], 16;" :: "r"(dst), "l"(src));
}
#define CP_COMMIT() asm volatile("cp.async.commit_group;" ::: "memory")
#define CP_WAIT(n)  asm volatile("cp.async.wait_group %0;" :: "n"(n) : "memory")

__device__ __forceinline__ uint32_t ld_tf32(const float* p) {
    uint32_t r;
    float f = *p;
    asm("cvt.rna.tf32.f32 %0, %1;" : "=r"(r) : "f"(f));
    return r;
}
__device__ __forceinline__ void mma_tf32(float c[4], uint32_t a0, uint32_t a1,
                                         uint32_t a2, uint32_t a3,
                                         uint32_t b0, uint32_t b1) {
    asm volatile(
        "mma.sync.aligned.m16n8k8.row.col.f32.tf32.tf32.f32 "
        "{%0,%1,%2,%3}, {%4,%5,%6,%7}, {%8,%9}, {%0,%1,%2,%3};"
        : "+f"(c[0]), "+f"(c[1]), "+f"(c[2]), "+f"(c[3])
        : "r"(a0), "r"(a1), "r"(a2), "r"(a3), "r"(b0), "r"(b1));
}

// =================================================================
// qk_exp (tf32 mma): attn[b,i,j] = exp( sum_d q[b,d,i] * k[b,d,j] )
// CTA 128(i) x 128(j), K=32 (one pass). q/k tiles staged in smem
// [32 d][132 pad] (coalesced loads; conflict-free fragment reads).
// No max-subtraction: |s| <= ~40 so exp fits fp32.
// =================================================================
__global__ void __launch_bounds__(256)
qk_exp(const float* __restrict__ qg, const float* __restrict__ kg,
       float* __restrict__ attn) {
    __shared__ float qs[32 * 132];
    __shared__ float ks[32 * 132];
    int tid = threadIdx.x, lane = tid & 31, w = tid >> 5;
    int wm = w & 3, wn = w >> 2;
    int b = blockIdx.z;
    int I0 = blockIdx.y * 128, J0 = blockIdx.x * 128;
    const float* Qg = qg + (long)b * CQ_ * N_;
    const float* Kg = kg + (long)b * CQ_ * N_;

    #pragma unroll
    for (int jj = 0; jj < 4; jj++) {
        int idx = tid + 256 * jj;           // 0..1023
        int d = idx >> 5, c4 = (idx & 31) * 4;
        *(float4*)&qs[d * 132 + c4] = *(const float4*)(Qg + (long)d * N_ + I0 + c4);
        *(float4*)&ks[d * 132 + c4] = *(const float4*)(Kg + (long)d * N_ + J0 + c4);
    }
    __syncthreads();

    float acc[2][8][4] = {};
    #pragma unroll
    for (int k8 = 0; k8 < 32; k8 += 8) {
        uint32_t a[2][4], bb[8][2];
        int d0 = k8 + (lane & 3);
        #pragma unroll
        for (int mt = 0; mt < 2; mt++) {
            int i = wm * 32 + mt * 16 + (lane >> 2);
            a[mt][0] = ld_tf32(&qs[d0 * 132 + i]);
            a[mt][1] = ld_tf32(&qs[d0 * 132 + i + 8]);
            a[mt][2] = ld_tf32(&qs[(d0 + 4) * 132 + i]);
            a[mt][3] = ld_tf32(&qs[(d0 + 4) * 132 + i + 8]);
        }
        #pragma unroll
        for (int nt = 0; nt < 8; nt++) {
            int j = wn * 64 + nt * 8 + (lane >> 2);
            bb[nt][0] = ld_tf32(&ks[d0 * 132 + j]);
            bb[nt][1] = ld_tf32(&ks[(d0 + 4) * 132 + j]);
        }
        #pragma unroll
        for (int mt = 0; mt < 2; mt++)
            #pragma unroll
            for (int nt = 0; nt < 8; nt++)
                mma_tf32(acc[mt][nt], a[mt][0], a[mt][1], a[mt][2], a[mt][3],
                         bb[nt][0], bb[nt][1]);
    }

    // exp + store
    #pragma unroll
    for (int mt = 0; mt < 2; mt++) {
        int row = I0 + wm * 32 + mt * 16 + (lane >> 2);
        #pragma unroll
        for (int nt = 0; nt < 8; nt++) {
            int col = J0 + wn * 64 + nt * 8 + 2 * (lane & 3);
            long o = (long)b * N_ * N_ + (long)row * N_ + col;
            *(float2*)(attn + o) =
                make_float2(__expf(acc[mt][nt][0]), __expf(acc[mt][nt][1]));
            *(float2*)(attn + o + 8 * N_) =
                make_float2(__expf(acc[mt][nt][2]), __expf(acc[mt][nt][3]));
        }
    }
}

// =================================================================
// PA GEMM (tf32 mma) with fused softmax-normalization:
//   cat[b,c,i] = gamma_pa * (1/l_i) * sum_j v[b,c,j]*attn[b,i,j] + x[b,c,i]
//   l_i = sum_j attn[b,i,j]  (computed in-kernel from the staged B tiles)
// CTA 128(c) x 128(i), K=4096, BK=32, cp.async double buffer.
// =================================================================
#define PA_SMEM_BYTES (4 * 128 * 36 * 4)   // 73728

__global__ void __launch_bounds__(256)
pa_mma(const float* __restrict__ v, const float* __restrict__ attn,
       const float* __restrict__ x, const float* __restrict__ gpa,
       float* __restrict__ cat) {
    extern __shared__ float sm[];
    __shared__ float red[256];
    int tid = threadIdx.x, lane = tid & 31, wid = tid >> 5;
    int wm = wid & 3, wn = wid >> 2;
    int b = blockIdx.z, m0 = blockIdx.y * 128, n0 = blockIdx.x * 128;
    const float* Ag = v + (long)b * C_ * N_ + (long)m0 * N_;
    const float* Bg = attn + (long)b * N_ * N_ + (long)n0 * N_;
    uint32_t smu = smem_to_u32(sm);

    float c[2][8][4] = {};
    float part = 0.f;                       // row-sum strip: row=tid>>1, k=(tid&1)*16..+15
    int srow = tid >> 1, skoff = (tid & 1) * 16;

    int flat_r[4], flat_q[4];
    #pragma unroll
    for (int j = 0; j < 4; j++) { int f = tid + 256 * j; flat_r[j] = f >> 3; flat_q[j] = (f & 7) * 4; }

    #pragma unroll
    for (int s = 0; s < 2; s++) {
        int k0 = s * 32;
        #pragma unroll
        for (int j = 0; j < 4; j++) {
            int r = flat_r[j], q = flat_q[j];
            cp16(smu + (s * 4608 + r * 36 + q) * 4, Ag + (long)r * N_ + k0 + q);
            cp16(smu + (9216 + s * 4608 + r * 36 + q) * 4, Bg + (long)r * N_ + k0 + q);
        }
        CP_COMMIT();
    }

    for (int ch = 0; ch < 128; ch++) {
        if (ch < 126) { CP_WAIT(1); } else { CP_WAIT(0); }
        __syncthreads();
        const float* As_ = sm + (ch & 1) * 4608;
        const float* Bs_ = sm + 9216 + (ch & 1) * 4608;
        // accumulate row sums l_i from the staged attn tile
        {
            const float* bp = Bs_ + srow * 36 + skoff;
            #pragma unroll
            for (int kk = 0; kk < 16; kk++) part += bp[kk];
        }
        #pragma unroll
        for (int k8 = 0; k8 < 32; k8 += 8) {
            uint32_t a[2][4], bb[8][2];
            #pragma unroll
            for (int mt = 0; mt < 2; mt++) {
                const float* ap = As_ + (wm * 32 + mt * 16 + (lane >> 2)) * 36 + k8 + (lane & 3);
                a[mt][0] = ld_tf32(ap);
                a[mt][1] = ld_tf32(ap + 8 * 36);
                a[mt][2] = ld_tf32(ap + 4);
                a[mt][3] = ld_tf32(ap + 8 * 36 + 4);
            }
            #pragma unroll
            for (int nt = 0; nt < 8; nt++) {
                const float* bp = Bs_ + (wn * 64 + nt * 8 + (lane >> 2)) * 36 + k8 + (lane & 3);
                bb[nt][0] = ld_tf32(bp);
                bb[nt][1] = ld_tf32(bp + 4);
            }
            #pragma unroll
            for (int mt = 0; mt < 2; mt++)
                #pragma unroll
                for (int nt = 0; nt < 8; nt++)
                    mma_tf32(c[mt][nt], a[mt][0], a[mt][1], a[mt][2], a[mt][3],
                             bb[nt][0], bb[nt][1]);
        }
        __syncthreads();
        if (ch + 2 < 128) {
            int s = ch & 1;
            int k0 = (ch + 2) * 32;
            #pragma unroll
            for (int j = 0; j < 4; j++) {
                int r = flat_r[j], q = flat_q[j];
                cp16(smu + (s * 4608 + r * 36 + q) * 4, Ag + (long)r * N_ + k0 + q);
                cp16(smu + (9216 + s * 4608 + r * 36 + q) * 4, Bg + (long)r * N_ + k0 + q);
            }
            CP_COMMIT();
        }
    }

    // combine row-sum halves: l(row) = red[2*row] + red[2*row+1]
    red[tid] = part;
    __syncthreads();

    float g = gpa[0];
    #pragma unroll
    for (int nt = 0; nt < 8; nt++) {
        int cl = wn * 64 + nt * 8 + 2 * (lane & 3);
        float inv0 = 1.f / (red[2 * cl] + red[2 * cl + 1]);
        float inv1 = 1.f / (red[2 * cl + 2] + red[2 * cl + 3]);
        #pragma unroll
        for (int mt = 0; mt < 2; mt++) {
            int row = m0 + wm * 32 + mt * 16 + (lane >> 2);
            int col = n0 + cl;
            long xo = ((long)b * C_ + row) * N_ + col;
            long co = ((long)b * 2 * C_ + row) * N_ + col;
            *(float2*)(cat + co) = make_float2(
                fmaf(g, c[mt][nt][0] * inv0, x[xo]),
                fmaf(g, c[mt][nt][1] * inv1, x[xo + 1]));
            *(float2*)(cat + co + 8 * N_) = make_float2(
                fmaf(g, c[mt][nt][2] * inv0, x[xo + 8 * N_]),
                fmaf(g, c[mt][nt][3] * inv1, x[xo + 8 * N_ + 1]));
        }
    }
}

// =================================================================
// NN-GEMM (tf32 mma): Out[m][n] = sum_k A[m][k] * B[k][n]
// A k-contiguous (lda=K), B n-contiguous (ldb=N_). CTA 128x128, BK=32.
// epi: 0 -> +bias[m]; 1 -> gamma*acc + res.
// =================================================================
#define NN_SMEM_BYTES ((2 * 128 * 36 + 2 * 32 * 132) * 4)   // 70656

__global__ void __launch_bounds__(256)
gemm_nn_mma(const float* __restrict__ A, const float* __restrict__ B,
            float* __restrict__ Out, int K, int epi,
            const float* __restrict__ bias, const float* __restrict__ gsc,
            const float* __restrict__ res,
            long sA, long sB, long sO, long sR) {
    extern __shared__ float sm[];
    float* As = sm;                      // 2 x [128][36]
    float* Bs = sm + 2 * 128 * 36;       // 2 x [32][132]
    int tid = threadIdx.x, lane = tid & 31, w = tid >> 5;
    int wm = w & 3, wn = w >> 2;
    int b = blockIdx.z, m0 = blockIdx.y * 128, n0 = blockIdx.x * 128;
    const float* Ag = A + sA * b + (long)m0 * K;
    const float* Bg = B + sB * b + n0;
    uint32_t smu_a = smem_to_u32(As), smu_b = smem_to_u32(Bs);
    float acc[2][8][4] = {};
    int nchunks = K / 32;

    #pragma unroll
    for (int s = 0; s < 2; s++) {
        #pragma unroll
        for (int jj = 0; jj < 4; jj++) {
            int idx = tid + 256 * jj;
            int r = idx >> 3, kq = (idx & 7) * 4;
            cp16(smu_a + (s * 4608 + r * 36 + kq) * 4, Ag + (long)r * K + s * 32 + kq);
            int kk = idx >> 5, nq = (idx & 31) * 4;
            cp16(smu_b + (s * 4224 + kk * 132 + nq) * 4, Bg + (long)(s * 32 + kk) * N_ + nq);
        }
        CP_COMMIT();
    }

    for (int ch = 0; ch < nchunks; ch++) {
        if (ch < nchunks - 2) { CP_WAIT(1); } else { CP_WAIT(0); }
        __syncthreads();
        const float* As_ = As + (ch & 1) * 4608;
        const float* Bs_ = Bs + (ch & 1) * 4224;
        #pragma unroll
        for (int k8 = 0; k8 < 32; k8 += 8) {
            uint32_t a[2][4], bb[8][2];
            #pragma unroll
            for (int mt = 0; mt < 2; mt++) {
                const float* ap = As_ + (wm * 32 + mt * 16 + (lane >> 2)) * 36 + k8 + (lane & 3);
                a[mt][0] = ld_tf32(ap);
                a[mt][1] = ld_tf32(ap + 8 * 36);
                a[mt][2] = ld_tf32(ap + 4);
                a[mt][3] = ld_tf32(ap + 8 * 36 + 4);
            }
            #pragma unroll
            for (int nt = 0; nt < 8; nt++) {
                const float* bp = Bs_ + (k8 + (lane & 3)) * 132 + wn * 64 + nt * 8 + (lane >> 2);
                bb[nt][0] = ld_tf32(bp);
                bb[nt][1] = ld_tf32(bp + 4 * 132);
            }
            #pragma unroll
            for (int mt = 0; mt < 2; mt++)
                #pragma unroll
                for (int nt = 0; nt < 8; nt++)
                    mma_tf32(acc[mt][nt], a[mt][0], a[mt][1], a[mt][2], a[mt][3],
                             bb[nt][0], bb[nt][1]);
        }
        __syncthreads();
        if (ch + 2 < nchunks) {
            int s = ch & 1;
            #pragma unroll
            for (int jj = 0; jj < 4; jj++) {
                int idx = tid + 256 * jj;
                int r = idx >> 3, kq = (idx & 7) * 4;
                cp16(smu_a + (s * 4608 + r * 36 + kq) * 4,
                     Ag + (long)r * K + (ch + 2) * 32 + kq);
                int kk = idx >> 5, nq = (idx & 31) * 4;
                cp16(smu_b + (s * 4224 + kk * 132 + nq) * 4,
                     Bg + (long)((ch + 2) * 32 + kk) * N_ + nq);
            }
            CP_COMMIT();
        }
    }

    float g = gsc ? *gsc : 0.f;
    const float* resb = res ? res + sR * b : nullptr;
    float* Ob = Out + sO * b;
    #pragma unroll
    for (int mt = 0; mt < 2; mt++) {
        int row = m0 + wm * 32 + mt * 16 + (lane >> 2);
        #pragma unroll
        for (int nt = 0; nt < 8; nt++) {
            int col = n0 + wn * 64 + nt * 8 + 2 * (lane & 3);
            long o = (long)row * N_ + col;
            if (epi == 0) {
                float bv = bias[row], bv8 = bias[row + 8];
                *(float2*)(Ob + o) = make_float2(acc[mt][nt][0] + bv, acc[mt][nt][1] + bv);
                *(float2*)(Ob + o + 8 * N_) =
                    make_float2(acc[mt][nt][2] + bv8, acc[mt][nt][3] + bv8);
            } else {
                *(float2*)(Ob + o) = make_float2(
                    fmaf(g, acc[mt][nt][0], resb[o]), fmaf(g, acc[mt][nt][1], resb[o + 1]));
                *(float2*)(Ob + o + 8 * N_) = make_float2(
                    fmaf(g, acc[mt][nt][2], resb[o + 8 * N_]),
                    fmaf(g, acc[mt][nt][3], resb[o + 8 * N_ + 1]));
            }
        }
    }
}

// ---------------- helpers ----------------
__device__ __forceinline__ float warpMax(float v) {
    #pragma unroll
    for (int o = 16; o; o >>= 1) v = fmaxf(v, __shfl_xor_sync(0xffffffffu, v, o));
    return v;
}
__device__ __forceinline__ float warpSum(float v) {
    #pragma unroll
    for (int o = 16; o; o >>= 1) v += __shfl_xor_sync(0xffffffffu, v, o);
    return v;
}

__device__ __forceinline__ void mma_tile(const float (*As)[64], const float (*Bs)[64],
                                         float acc[4][4], int ty, int tx) {
    #pragma unroll
    for (int k = 0; k < 16; k++) {
        float4 a = *(const float4*)&As[k][ty * 4];
        float4 b = *(const float4*)&Bs[k][tx * 4];
        float ar[4] = {a.x, a.y, a.z, a.w};
        float br[4] = {b.x, b.y, b.z, b.w};
        #pragma unroll
        for (int i = 0; i < 4; i++)
            #pragma unroll
            for (int j = 0; j < 4; j++)
                acc[i][j] = fmaf(ar[i], br[j], acc[i][j]);
    }
}

__device__ __forceinline__ void epilogue(float* Out, int M, int N, int m0, int n0,
                                         int ty, int tx, float acc[4][4], int epi,
                                         const float* bias, const float* gsc,
                                         const float* res) {
    float g = gsc ? *gsc : 0.f;
    #pragma unroll
    for (int i = 0; i < 4; i++) {
        int m = m0 + ty * 4 + i;
        if (m < M) {
            long off = (long)m * N + n0 + tx * 4;
            float4 o;
            if (epi == 0) {
                float bv = bias[m];
                o = make_float4(acc[i][0] + bv, acc[i][1] + bv, acc[i][2] + bv, acc[i][3] + bv);
            } else if (epi == 1) {
                float4 r = *(const float4*)(res + off);
                o = make_float4(fmaf(g, acc[i][0], r.x), fmaf(g, acc[i][1], r.y),
                                fmaf(g, acc[i][2], r.z), fmaf(g, acc[i][3], r.w));
            } else {
                o = make_float4(acc[i][0], acc[i][1], acc[i][2], acc[i][3]);
            }
            *(float4*)(Out + off) = o;
        }
    }
}

// ---------------- fp32 SIMT GEMMs (small ops: q/k proj, channel logits) ----------------

__global__ void gemm_nn_k(const float* __restrict__ A, const float* __restrict__ Bm,
                          float* __restrict__ Out, int M, int N, int K, int epi,
                          const float* __restrict__ bias, const float* __restrict__ gsc,
                          const float* __restrict__ res,
                          long sA, long sB, long sO, long sR) {
    int b = blockIdx.z;
    A += sA * b; Bm += sB * b; Out += sO * b;
    const float* resb = res ? res + sR * b : nullptr;
    __shared__ float As[16][64];
    __shared__ float Bs[16][64];
    int tid = threadIdx.x;
    int tx = tid & 15, ty = tid >> 4;
    int m0 = blockIdx.y * 64, n0 = blockIdx.x * 64;
    int arow = tid >> 2, ak = (tid & 3) * 4;
    int brow = tid >> 4, bn = (tid & 15) * 4;
    float acc[4][4] = {};
    for (int k0 = 0; k0 < K; k0 += 16) {
        float4 av = make_float4(0.f, 0.f, 0.f, 0.f);
        if (m0 + arow < M) av = *(const float4*)(A + (long)(m0 + arow) * K + k0 + ak);
        As[ak + 0][arow] = av.x; As[ak + 1][arow] = av.y;
        As[ak + 2][arow] = av.z; As[ak + 3][arow] = av.w;
        *(float4*)&Bs[brow][bn] = *(const float4*)(Bm + (long)(k0 + brow) * N + n0 + bn);
        __syncthreads();
        mma_tile(As, Bs, acc, ty, tx);
        __syncthreads();
    }
    epilogue(Out, M, N, m0, n0, ty, tx, acc, epi, bias, gsc, resb);
}

__global__ void gemm_nt_k(const float* __restrict__ A, const float* __restrict__ Bm,
                          float* __restrict__ Out, int M, int N, int K, int epi,
                          const float* __restrict__ bias, const float* __restrict__ gsc,
                          const float* __restrict__ res,
                          long sA, long sB, long sO, long sR) {
    int b = blockIdx.z;
    A += sA * b; Bm += sB * b; Out += sO * b;
    const float* resb = res ? res + sR * b : nullptr;
    __shared__ float As[16][64];
    __shared__ float Bs[16][64];
    int tid = threadIdx.x;
    int tx = tid & 15, ty = tid >> 4;
    int m0 = blockIdx.y * 64, n0 = blockIdx.x * 64;
    int arow = tid >> 2, ak = (tid & 3) * 4;
    float acc[4][4] = {};
    for (int k0 = 0; k0 < K; k0 += 16) {
        float4 av = make_float4(0.f, 0.f, 0.f, 0.f);
        if (m0 + arow < M) av = *(const float4*)(A + (long)(m0 + arow) * K + k0 + ak);
        As[ak + 0][arow] = av.x; As[ak + 1][arow] = av.y;
        As[ak + 2][arow] = av.z; As[ak + 3][arow] = av.w;
        float4 bv = *(const float4*)(Bm + (long)(n0 + arow) * K + k0 + ak);
        Bs[ak + 0][arow] = bv.x; Bs[ak + 1][arow] = bv.y;
        Bs[ak + 2][arow] = bv.z; Bs[ak + 3][arow] = bv.w;
        __syncthreads();
        mma_tile(As, Bs, acc, ty, tx);
        __syncthreads();
    }
    epilogue(Out, M, N, m0, n0, ty, tx, acc, epi, bias, gsc, resb);
}

// ---------------- softmax over 256 (channel attention) ----------------
__global__ void softmax256(float* __restrict__ data) {
    __shared__ float sh[8];
    float* p = data + (size_t)blockIdx.x * 256;
    int tid = threadIdx.x;
    float v = p[tid];
    float m = warpMax(v);
    if ((tid & 31) == 0) sh[tid >> 5] = m;
    __syncthreads();
    m = sh[tid & 7];
    #pragma unroll
    for (int o = 4; o; o >>= 1) m = fmaxf(m, __shfl_xor_sync(0xffffffffu, m, o));
    __syncthreads();
    float e = __expf(v - m);
    float s = warpSum(e);
    if ((tid & 31) == 0) sh[tid >> 5] = s;
    __syncthreads();
    s = sh[tid & 7];
    #pragma unroll
    for (int o = 4; o; o >>= 1) s += __shfl_xor_sync(0xffffffffu, s, o);
    p[tid] = e / s;
}

// =================================================================
// 3x3 conv 512 -> 256 as implicit GEMM (tf32 mma.sync)
// =================================================================
#define CV_SMEM_BYTES ((9728 + 9728 + 2112) * 4)   // 86272

__global__ void __launch_bounds__(256)
conv_mma(const float* __restrict__ cat, const float* __restrict__ wf,
         float* __restrict__ y) {
    extern __shared__ float sm[];
    float* As = sm;             // 128*76
    float* Bs = sm + 9728;      // 128*76
    float* patch = sm + 19456;  // 8*4*66
    int tid = threadIdx.x, lane = tid & 31, wid = tid >> 5;
    int wm = wid & 3, wn = wid >> 2;
    int b = blockIdx.z, o0 = blockIdx.y * 128, p0 = blockIdx.x * 128;
    int h0 = blockIdx.x * 2;
    uint32_t smu = smem_to_u32(sm);

    float c[2][8][4] = {};

    for (int chunk = 0; chunk < 64; chunk++) {
        __syncthreads();
        #pragma unroll
        for (int j = 0; j < 9; j++) {
            int flat = tid + 256 * j;
            int r = flat / 18, q = (flat % 18) * 4;
            cp16(smu + (r * 76 + q) * 4, wf + (long)(o0 + r) * 4608 + chunk * 72 + q);
        }
        CP_COMMIT();
        int ci0 = chunk * 8;
        #pragma unroll
        for (int p = 0; p < 8; p++) {
            int flat = p * 256 + tid;
            int ci = flat >> 8, row = (flat >> 6) & 3, w = flat & 63;
            int h = h0 - 1 + row;
            float val = (h >= 0 && h < 64)
                ? cat[((long)b * 512 + ci0 + ci) * 4096 + h * 64 + w] : 0.f;
            patch[ci * 264 + row * 66 + w + 1] = val;
        }
        if (tid < 64) {
            int ci = tid >> 3, row = (tid >> 1) & 3, side = tid & 1;
            patch[ci * 264 + row * 66 + side * 65] = 0.f;
        }
        CP_WAIT(0);
        __syncthreads();
        {
            int n = tid >> 1, half = tid & 1;
            int hh = n >> 6, w = n & 63;
            const float* pb = patch + half * 4 * 264 + hh * 66 + w;
            float* brow = Bs + n * 76 + half * 36;
            #pragma unroll
            for (int ci_l = 0; ci_l < 4; ci_l++)
                #pragma unroll
                for (int kh = 0; kh < 3; kh++)
                    #pragma unroll
                    for (int kw = 0; kw < 3; kw++)
                        brow[ci_l * 9 + kh * 3 + kw] = pb[ci_l * 264 + kh * 66 + kw];
        }
        __syncthreads();
        #pragma unroll
        for (int k8 = 0; k8 < 72; k8 += 8) {
            uint32_t a[2][4], bb[8][2];
            #pragma unroll
            for (int mt = 0; mt < 2; mt++) {
                const float* ap = As + (wm * 32 + mt * 16 + (lane >> 2)) * 76 + k8 + (lane & 3);
                a[mt][0] = ld_tf32(ap);
                a[mt][1] = ld_tf32(ap + 8 * 76);
                a[mt][2] = ld_tf32(ap + 4);
                a[mt][3] = ld_tf32(ap + 8 * 76 + 4);
            }
            #pragma unroll
            for (int nt = 0; nt < 8; nt++) {
                const float* bp = Bs + (wn * 64 + nt * 8 + (lane >> 2)) * 76 + k8 + (lane & 3);
                bb[nt][0] = ld_tf32(bp);
                bb[nt][1] = ld_tf32(bp + 4);
            }
            #pragma unroll
            for (int mt = 0; mt < 2; mt++)
                #pragma unroll
                for (int nt = 0; nt < 8; nt++)
                    mma_tf32(c[mt][nt], a[mt][0], a[mt][1], a[mt][2], a[mt][3],
                             bb[nt][0], bb[nt][1]);
        }
    }

    #pragma unroll
    for (int mt = 0; mt < 2; mt++) {
        #pragma unroll
        for (int nt = 0; nt < 8; nt++) {
            int row = o0 + wm * 32 + mt * 16 + (lane >> 2);
            int col = p0 + wn * 64 + nt * 8 + 2 * (lane & 3);
            long yo = ((long)b * 256 + row) * 4096 + col;
            *(float2*)(y + yo) = make_float2(c[mt][nt][0], c[mt][nt][1]);
            *(float2*)(y + yo + 8 * 4096) = make_float2(c[mt][nt][2], c[mt][nt][3]);
        }
    }
}

// ---------------- BN (train-mode batch stats) + ReLU ----------------
__global__ void bnstats(const float* __restrict__ y, float* __restrict__ meanp,
                        float* __restrict__ rstdp) {
    __shared__ float sh[16];
    int o = blockIdx.x, tid = threadIdx.x;
    float s = 0.f, sq = 0.f;
    for (int b = 0; b < 4; b++) {
        const float4* p = (const float4*)(y + ((size_t)b * 256 + o) * 4096);
        for (int i = tid; i < 1024; i += 256) {
            float4 v = p[i];
            s += v.x + v.y + v.z + v.w;
            sq += v.x * v.x + v.y * v.y + v.z * v.z + v.w * v.w;
        }
    }
    s = warpSum(s); sq = warpSum(sq);
    if ((tid & 31) == 0) { sh[tid >> 5] = s; sh[8 + (tid >> 5)] = sq; }
    __syncthreads();
    if (tid == 0) {
        float S = 0.f, SQ = 0.f;
        for (int i = 0; i < 8; i++) { S += sh[i]; SQ += sh[8 + i]; }
        float mean = S / 16384.f;
        float var = SQ / 16384.f - mean * mean;
        meanp[o] = mean;
        rstdp[o] = rsqrtf(var + 1e-5f);
    }
}

__global__ void bnapply(const float* __restrict__ y, const float* __restrict__ gam,
                        const float* __restrict__ bet, const float* __restrict__ meanp,
                        const float* __restrict__ rstdp, float* __restrict__ out) {
    size_t i = (size_t)blockIdx.x * 256 + threadIdx.x;  // float4 index
    int o = (int)((i >> 10) & 255);
    float mu = meanp[o], rs = rstdp[o], g = gam[o], be = bet[o];
    float4 v = ((const float4*)y)[i];
    float4 r;
    r.x = fmaxf(0.f, fmaf((v.x - mu) * rs, g, be));
    r.y = fmaxf(0.f, fmaf((v.y - mu) * rs, g, be));
    r.z = fmaxf(0.f, fmaf((v.z - mu) * rs, g, be));
    r.w = fmaxf(0.f, fmaf((v.w - mu) * rs, g, be));
    ((float4*)out)[i] = r;
}

// ---------------- launcher ----------------
extern "C" void kernel_launch(void* const* d_in, const int* in_sizes, int n_in,
                              void* d_out, int out_size) {
    const float* x   = (const float*)d_in[0];
    const float* wq  = (const float*)d_in[1];
    const float* bq  = (const float*)d_in[2];
    const float* wk  = (const float*)d_in[3];
    const float* bk  = (const float*)d_in[4];
    const float* wv  = (const float*)d_in[5];
    const float* bv  = (const float*)d_in[6];
    const float* gpa = (const float*)d_in[7];
    const float* gca = (const float*)d_in[8];
    const float* wf  = (const float*)d_in[9];
    const float* bng = (const float*)d_in[10];
    const float* bnb = (const float*)d_in[11];
    float* out = (float*)d_out;

    float *q, *k, *v, *attn, *cat, *cattn, *y, *mean, *rstd;
    cudaGetSymbolAddress((void**)&q, g_q);
    cudaGetSymbolAddress((void**)&k, g_k);
    cudaGetSymbolAddress((void**)&v, g_v);
    cudaGetSymbolAddress((void**)&attn, g_attn);
    cudaGetSymbolAddress((void**)&cat, g_cat);
    cudaGetSymbolAddress((void**)&cattn, g_cattn);
    cudaGetSymbolAddress((void**)&y, g_y);
    cudaGetSymbolAddress((void**)&mean, g_mean);
    cudaGetSymbolAddress((void**)&rstd, g_rstd);

    cudaFuncSetAttribute(pa_mma, cudaFuncAttributeMaxDynamicSharedMemorySize,
                         PA_SMEM_BYTES);
    cudaFuncSetAttribute(gemm_nn_mma, cudaFuncAttributeMaxDynamicSharedMemorySize,
                         NN_SMEM_BYTES);
    cudaFuncSetAttribute(conv_mma, cudaFuncAttributeMaxDynamicSharedMemorySize,
                         CV_SMEM_BYTES);

    dim3 blk(256);
    long sx = (long)C_ * N_;
    long sqk = (long)CQ_ * N_;
    long scat = (long)2 * C_ * N_;

    // q, k projections (small; fp32 SIMT)
    gemm_nn_k<<<dim3(64, 1, 4), blk>>>(wq, x, q, CQ_, N_, C_, 0, bq, nullptr, nullptr,
                                       0, sx, sqk, 0);
    gemm_nn_k<<<dim3(64, 1, 4), blk>>>(wk, x, k, CQ_, N_, C_, 0, bk, nullptr, nullptr,
                                       0, sx, sqk, 0);
    // v projection on tensor cores
    gemm_nn_mma<<<dim3(32, 2, 4), blk, NN_SMEM_BYTES>>>(
        wv, x, v, C_, 0, bv, nullptr, nullptr, 0, sx, sx, 0);
    // logits + exp (no separate softmax pass)
    qk_exp<<<dim3(32, 32, 4), blk>>>(q, k, attn);
    // PA with fused 1/l normalization -> cat[:, 0:256]
    pa_mma<<<dim3(32, 2, 4), blk, PA_SMEM_BYTES>>>(v, attn, x, gpa, cat);
    // channel attention: logits, softmax, apply -> cat[:, 256:512]
    gemm_nt_k<<<dim3(4, 4, 4), blk>>>(x, x, cattn, C_, C_, N_, 2, nullptr, nullptr,
                                      nullptr, sx, sx, (long)C_ * C_, 0);
    softmax256<<<B_ * C_, 256>>>(cattn);
    gemm_nn_mma<<<dim3(32, 2, 4), blk, NN_SMEM_BYTES>>>(
        cattn, x, cat + (size_t)C_ * N_, C_, 1, nullptr, gca, x,
        (long)C_ * C_, sx, scat, sx);
    // 3x3 conv 512->256 (implicit GEMM, tensor cores)
    conv_mma<<<dim3(32, 2, 4), blk, CV_SMEM_BYTES>>>(cat, wf, y);
    // BN train-mode + ReLU
    bnstats<<<256, 256>>>(y, mean, rstd);
    bnapply<<<4096, 256>>>(y, bng, bnb, mean, rstd, out);
}

// round 8
// speedup vs baseline: 1.7770x; 1.2058x over previous
#include <cuda_runtime.h>
#include <cstdint>

#define B_  4
#define C_  256
#define CQ_ 32
#define N_  4096
#define HW_ 64

// ---------------- scratch (device globals; no allocation) ----------------
__device__ float g_q[B_ * CQ_ * N_];
__device__ float g_k[B_ * CQ_ * N_];
__device__ float g_v[B_ * C_ * N_];
__device__ float g_attn[(size_t)B_ * N_ * N_];      // exp(logits), 256 MB
__device__ float g_cat[(size_t)B_ * 2 * C_ * N_];   // [b][512][4096]
__device__ float g_cattn[B_ * C_ * C_];
__device__ float g_y[(size_t)B_ * C_ * N_];
__device__ float g_mean[C_];
__device__ float g_rstd[C_];

// ---------------- PTX helpers (sm_80+ mma.sync / cp.async) ----------------
__device__ __forceinline__ uint32_t smem_to_u32(const void* p) {
    uint32_t a;
    asm("{ .reg .u64 t; cvta.to.shared.u64 t, %1; cvt.u32.u64 %0, t; }" : "=r"(a) : "l"(p));
    return a;
}
__device__ __forceinline__ void cp16(uint32_t dst, const void* src) {
    asm volatile("cp.async.cg.shared.global [%0], [%1], 16;" :: "r"(dst), "l"(src));
}
#define CP_COMMIT() asm volatile("cp.async.commit_group;" ::: "memory")
#define CP_WAIT(n)  asm volatile("cp.async.wait_group %0;" :: "n"(n) : "memory")

__device__ __forceinline__ uint32_t ld_tf32(const float* p) {
    uint32_t r;
    float f = *p;
    asm("cvt.rna.tf32.f32 %0, %1;" : "=r"(r) : "f"(f));
    return r;
}
__device__ __forceinline__ void mma_tf32(float c[4], uint32_t a0, uint32_t a1,
                                         uint32_t a2, uint32_t a3,
                                         uint32_t b0, uint32_t b1) {
    asm volatile(
        "mma.sync.aligned.m16n8k8.row.col.f32.tf32.tf32.f32 "
        "{%0,%1,%2,%3}, {%4,%5,%6,%7}, {%8,%9}, {%0,%1,%2,%3};"
        : "+f"(c[0]), "+f"(c[1]), "+f"(c[2]), "+f"(c[3])
        : "r"(a0), "r"(a1), "r"(a2), "r"(a3), "r"(b0), "r"(b1));
}

// =================================================================
// qk_exp (tf32 mma): attn[b,i,j] = exp( sum_d q[b,d,i] * k[b,d,j] )
// =================================================================
__global__ void __launch_bounds__(256)
qk_exp(const float* __restrict__ qg, const float* __restrict__ kg,
       float* __restrict__ attn) {
    __shared__ float qs[32 * 132];
    __shared__ float ks[32 * 132];
    int tid = threadIdx.x, lane = tid & 31, w = tid >> 5;
    int wm = w & 3, wn = w >> 2;
    int b = blockIdx.z;
    int I0 = blockIdx.y * 128, J0 = blockIdx.x * 128;
    const float* Qg = qg + (long)b * CQ_ * N_;
    const float* Kg = kg + (long)b * CQ_ * N_;

    #pragma unroll
    for (int jj = 0; jj < 4; jj++) {
        int idx = tid + 256 * jj;           // 0..1023
        int d = idx >> 5, c4 = (idx & 31) * 4;
        *(float4*)&qs[d * 132 + c4] = *(const float4*)(Qg + (long)d * N_ + I0 + c4);
        *(float4*)&ks[d * 132 + c4] = *(const float4*)(Kg + (long)d * N_ + J0 + c4);
    }
    __syncthreads();

    float acc[2][8][4] = {};
    #pragma unroll
    for (int k8 = 0; k8 < 32; k8 += 8) {
        uint32_t a[2][4], bb[8][2];
        int d0 = k8 + (lane & 3);
        #pragma unroll
        for (int mt = 0; mt < 2; mt++) {
            int i = wm * 32 + mt * 16 + (lane >> 2);
            a[mt][0] = ld_tf32(&qs[d0 * 132 + i]);
            a[mt][1] = ld_tf32(&qs[d0 * 132 + i + 8]);
            a[mt][2] = ld_tf32(&qs[(d0 + 4) * 132 + i]);
            a[mt][3] = ld_tf32(&qs[(d0 + 4) * 132 + i + 8]);
        }
        #pragma unroll
        for (int nt = 0; nt < 8; nt++) {
            int j = wn * 64 + nt * 8 + (lane >> 2);
            bb[nt][0] = ld_tf32(&ks[d0 * 132 + j]);
            bb[nt][1] = ld_tf32(&ks[(d0 + 4) * 132 + j]);
        }
        #pragma unroll
        for (int mt = 0; mt < 2; mt++)
            #pragma unroll
            for (int nt = 0; nt < 8; nt++)
                mma_tf32(acc[mt][nt], a[mt][0], a[mt][1], a[mt][2], a[mt][3],
                         bb[nt][0], bb[nt][1]);
    }

    #pragma unroll
    for (int mt = 0; mt < 2; mt++) {
        int row = I0 + wm * 32 + mt * 16 + (lane >> 2);
        #pragma unroll
        for (int nt = 0; nt < 8; nt++) {
            int col = J0 + wn * 64 + nt * 8 + 2 * (lane & 3);
            long o = (long)b * N_ * N_ + (long)row * N_ + col;
            *(float2*)(attn + o) =
                make_float2(__expf(acc[mt][nt][0]), __expf(acc[mt][nt][1]));
            *(float2*)(attn + o + 8 * N_) =
                make_float2(__expf(acc[mt][nt][2]), __expf(acc[mt][nt][3]));
        }
    }
}

// =================================================================
// PA GEMM (tf32 mma) with fused softmax-normalization. M=256 version:
//   one CTA covers ALL 256 channels for a 128-wide i tile -> attn tile
//   read exactly once. K=4096, BK=32, cp.async double buffer.
//   cat[b,c,i] = gamma_pa*(1/l_i)*sum_j v[b,c,j]*attn[b,i,j] + x[b,c,i]
// smem: As 2x[256][36], Bs 2x[128][36]. Warp grid 4(m)x2(n), warp tile 64x64.
// =================================================================
#define PA_SMEM_BYTES ((2 * 256 * 36 + 2 * 128 * 36) * 4)   // 110592

__global__ void __launch_bounds__(256)
pa_mma(const float* __restrict__ v, const float* __restrict__ attn,
       const float* __restrict__ x, const float* __restrict__ gpa,
       float* __restrict__ cat) {
    extern __shared__ float sm[];
    float* Asm = sm;                   // 2 x 256*36
    float* Bsm = sm + 2 * 256 * 36;    // 2 x 128*36
    __shared__ float red[256];
    int tid = threadIdx.x, lane = tid & 31, wid = tid >> 5;
    int wm = wid & 3, wn = wid >> 2;
    int b = blockIdx.z, n0 = blockIdx.x * 128;
    const float* Ag = v + (long)b * C_ * N_;
    const float* Bg = attn + (long)b * N_ * N_ + (long)n0 * N_;
    uint32_t smu_a = smem_to_u32(Asm), smu_b = smem_to_u32(Bsm);

    float c[4][8][4] = {};
    float part = 0.f;                  // row-sum strip: row=tid>>1, k=(tid&1)*16..+15
    int srow = tid >> 1, skoff = (tid & 1) * 16;

    #pragma unroll
    for (int s = 0; s < 2; s++) {
        int k0 = s * 32;
        #pragma unroll
        for (int j = 0; j < 8; j++) {            // A: 256 rows x 8 quads
            int f = tid + 256 * j;
            int r = f >> 3, q = (f & 7) * 4;
            cp16(smu_a + (s * 9216 + r * 36 + q) * 4, Ag + (long)r * N_ + k0 + q);
        }
        #pragma unroll
        for (int j = 0; j < 4; j++) {            // B: 128 rows x 8 quads
            int f = tid + 256 * j;
            int r = f >> 3, q = (f & 7) * 4;
            cp16(smu_b + (s * 4608 + r * 36 + q) * 4, Bg + (long)r * N_ + k0 + q);
        }
        CP_COMMIT();
    }

    for (int ch = 0; ch < 128; ch++) {
        if (ch < 126) { CP_WAIT(1); } else { CP_WAIT(0); }
        __syncthreads();
        const float* As_ = Asm + (ch & 1) * 9216;
        const float* Bs_ = Bsm + (ch & 1) * 4608;
        // accumulate row sums l_i from the staged attn tile
        {
            const float* bp = Bs_ + srow * 36 + skoff;
            #pragma unroll
            for (int kk = 0; kk < 16; kk++) part += bp[kk];
        }
        #pragma unroll
        for (int k8 = 0; k8 < 32; k8 += 8) {
            uint32_t a[4][4], bb[8][2];
            #pragma unroll
            for (int mt = 0; mt < 4; mt++) {
                const float* ap = As_ + (wm * 64 + mt * 16 + (lane >> 2)) * 36 + k8 + (lane & 3);
                a[mt][0] = ld_tf32(ap);
                a[mt][1] = ld_tf32(ap + 8 * 36);
                a[mt][2] = ld_tf32(ap + 4);
                a[mt][3] = ld_tf32(ap + 8 * 36 + 4);
            }
            #pragma unroll
            for (int nt = 0; nt < 8; nt++) {
                const float* bp = Bs_ + (wn * 64 + nt * 8 + (lane >> 2)) * 36 + k8 + (lane & 3);
                bb[nt][0] = ld_tf32(bp);
                bb[nt][1] = ld_tf32(bp + 4);
            }
            #pragma unroll
            for (int mt = 0; mt < 4; mt++)
                #pragma unroll
                for (int nt = 0; nt < 8; nt++)
                    mma_tf32(c[mt][nt], a[mt][0], a[mt][1], a[mt][2], a[mt][3],
                             bb[nt][0], bb[nt][1]);
        }
        __syncthreads();
        if (ch + 2 < 128) {
            int s = ch & 1;
            int k0 = (ch + 2) * 32;
            #pragma unroll
            for (int j = 0; j < 8; j++) {
                int f = tid + 256 * j;
                int r = f >> 3, q = (f & 7) * 4;
                cp16(smu_a + (s * 9216 + r * 36 + q) * 4, Ag + (long)r * N_ + k0 + q);
            }
            #pragma unroll
            for (int j = 0; j < 4; j++) {
                int f = tid + 256 * j;
                int r = f >> 3, q = (f & 7) * 4;
                cp16(smu_b + (s * 4608 + r * 36 + q) * 4, Bg + (long)r * N_ + k0 + q);
            }
            CP_COMMIT();
        }
    }

    red[tid] = part;
    __syncthreads();

    float g = gpa[0];
    #pragma unroll
    for (int nt = 0; nt < 8; nt++) {
        int cl = wn * 64 + nt * 8 + 2 * (lane & 3);
        float inv0 = 1.f / (red[2 * cl] + red[2 * cl + 1]);
        float inv1 = 1.f / (red[2 * cl + 2] + red[2 * cl + 3]);
        #pragma unroll
        for (int mt = 0; mt < 4; mt++) {
            int row = wm * 64 + mt * 16 + (lane >> 2);
            int col = n0 + cl;
            long xo = ((long)b * C_ + row) * N_ + col;
            long co = ((long)b * 2 * C_ + row) * N_ + col;
            *(float2*)(cat + co) = make_float2(
                fmaf(g, c[mt][nt][0] * inv0, x[xo]),
                fmaf(g, c[mt][nt][1] * inv1, x[xo + 1]));
            *(float2*)(cat + co + 8 * N_) = make_float2(
                fmaf(g, c[mt][nt][2] * inv0, x[xo + 8 * N_]),
                fmaf(g, c[mt][nt][3] * inv1, x[xo + 8 * N_ + 1]));
        }
    }
}

// =================================================================
// NN-GEMM (tf32 mma): Out[m][n] = sum_k A[m][k] * B[k][n]
// =================================================================
#define NN_SMEM_BYTES ((2 * 128 * 36 + 2 * 32 * 132) * 4)   // 70656

__global__ void __launch_bounds__(256)
gemm_nn_mma(const float* __restrict__ A, const float* __restrict__ B,
            float* __restrict__ Out, int K, int epi,
            const float* __restrict__ bias, const float* __restrict__ gsc,
            const float* __restrict__ res,
            long sA, long sB, long sO, long sR) {
    extern __shared__ float sm[];
    float* As = sm;                      // 2 x [128][36]
    float* Bs = sm + 2 * 128 * 36;       // 2 x [32][132]
    int tid = threadIdx.x, lane = tid & 31, w = tid >> 5;
    int wm = w & 3, wn = w >> 2;
    int b = blockIdx.z, m0 = blockIdx.y * 128, n0 = blockIdx.x * 128;
    const float* Ag = A + sA * b + (long)m0 * K;
    const float* Bg = B + sB * b + n0;
    uint32_t smu_a = smem_to_u32(As), smu_b = smem_to_u32(Bs);
    float acc[2][8][4] = {};
    int nchunks = K / 32;

    #pragma unroll
    for (int s = 0; s < 2; s++) {
        #pragma unroll
        for (int jj = 0; jj < 4; jj++) {
            int idx = tid + 256 * jj;
            int r = idx >> 3, kq = (idx & 7) * 4;
            cp16(smu_a + (s * 4608 + r * 36 + kq) * 4, Ag + (long)r * K + s * 32 + kq);
            int kk = idx >> 5, nq = (idx & 31) * 4;
            cp16(smu_b + (s * 4224 + kk * 132 + nq) * 4, Bg + (long)(s * 32 + kk) * N_ + nq);
        }
        CP_COMMIT();
    }

    for (int ch = 0; ch < nchunks; ch++) {
        if (ch < nchunks - 2) { CP_WAIT(1); } else { CP_WAIT(0); }
        __syncthreads();
        const float* As_ = As + (ch & 1) * 4608;
        const float* Bs_ = Bs + (ch & 1) * 4224;
        #pragma unroll
        for (int k8 = 0; k8 < 32; k8 += 8) {
            uint32_t a[2][4], bb[8][2];
            #pragma unroll
            for (int mt = 0; mt < 2; mt++) {
                const float* ap = As_ + (wm * 32 + mt * 16 + (lane >> 2)) * 36 + k8 + (lane & 3);
                a[mt][0] = ld_tf32(ap);
                a[mt][1] = ld_tf32(ap + 8 * 36);
                a[mt][2] = ld_tf32(ap + 4);
                a[mt][3] = ld_tf32(ap + 8 * 36 + 4);
            }
            #pragma unroll
            for (int nt = 0; nt < 8; nt++) {
                const float* bp = Bs_ + (k8 + (lane & 3)) * 132 + wn * 64 + nt * 8 + (lane >> 2);
                bb[nt][0] = ld_tf32(bp);
                bb[nt][1] = ld_tf32(bp + 4 * 132);
            }
            #pragma unroll
            for (int mt = 0; mt < 2; mt++)
                #pragma unroll
                for (int nt = 0; nt < 8; nt++)
                    mma_tf32(acc[mt][nt], a[mt][0], a[mt][1], a[mt][2], a[mt][3],
                             bb[nt][0], bb[nt][1]);
        }
        __syncthreads();
        if (ch + 2 < nchunks) {
            int s = ch & 1;
            #pragma unroll
            for (int jj = 0; jj < 4; jj++) {
                int idx = tid + 256 * jj;
                int r = idx >> 3, kq = (idx & 7) * 4;
                cp16(smu_a + (s * 4608 + r * 36 + kq) * 4,
                     Ag + (long)r * K + (ch + 2) * 32 + kq);
                int kk = idx >> 5, nq = (idx & 31) * 4;
                cp16(smu_b + (s * 4224 + kk * 132 + nq) * 4,
                     Bg + (long)((ch + 2) * 32 + kk) * N_ + nq);
            }
            CP_COMMIT();
        }
    }

    float g = gsc ? *gsc : 0.f;
    const float* resb = res ? res + sR * b : nullptr;
    float* Ob = Out + sO * b;
    #pragma unroll
    for (int mt = 0; mt < 2; mt++) {
        int row = m0 + wm * 32 + mt * 16 + (lane >> 2);
        #pragma unroll
        for (int nt = 0; nt < 8; nt++) {
            int col = n0 + wn * 64 + nt * 8 + 2 * (lane & 3);
            long o = (long)row * N_ + col;
            if (epi == 0) {
                float bv = bias[row], bv8 = bias[row + 8];
                *(float2*)(Ob + o) = make_float2(acc[mt][nt][0] + bv, acc[mt][nt][1] + bv);
                *(float2*)(Ob + o + 8 * N_) =
                    make_float2(acc[mt][nt][2] + bv8, acc[mt][nt][3] + bv8);
            } else {
                *(float2*)(Ob + o) = make_float2(
                    fmaf(g, acc[mt][nt][0], resb[o]), fmaf(g, acc[mt][nt][1], resb[o + 1]));
                *(float2*)(Ob + o + 8 * N_) = make_float2(
                    fmaf(g, acc[mt][nt][2], resb[o + 8 * N_]),
                    fmaf(g, acc[mt][nt][3], resb[o + 8 * N_ + 1]));
            }
        }
    }
}

// =================================================================
// 3x3 conv 512 -> 256, implicit GEMM v2 (tf32 mma):
//  - K reordered as k = pos*8 + ci  (pos = kh*3+kw). B-fragments read
//    DIRECTLY from the raw input patch (no im2col materialization).
//  - weights kept in natural wf layout [o][72]; A-fragment index =
//    (lane&3)*9 + pos (conflict-free with 76-float row stride).
//  - patch staged via cp.async, double buffered, halo at +4-float
//    offset (16B-aligned cp dst), ci-stride 296 (conflict-free).
// CTA: 128(o) x 128(p = 2 h-rows); 64 ci-chunks of 8.
// =================================================================
#define CV_AS_FLOATS  (128 * 76)         // 9728 per buffer
#define CV_PT_FLOATS  (8 * 296)          // 2368 per buffer
#define CV_SMEM_BYTES ((2 * CV_AS_FLOATS + 2 * CV_PT_FLOATS) * 4)   // 96768

__global__ void __launch_bounds__(256)
conv_mma(const float* __restrict__ cat, const float* __restrict__ wf,
         float* __restrict__ y) {
    extern __shared__ float sm[];
    float* Asm = sm;                         // 2 x [128][76]
    float* Pt = sm + 2 * CV_AS_FLOATS;       // 2 x [8][296]
    int tid = threadIdx.x, lane = tid & 31, wid = tid >> 5;
    int wm = wid & 3, wn = wid >> 2;
    int b = blockIdx.z, o0 = blockIdx.y * 128, p0 = blockIdx.x * 128;
    int h0 = blockIdx.x * 2;
    uint32_t smu_a = smem_to_u32(Asm), smu_p = smem_to_u32(Pt);

    // zero both patch buffers (covers halo cols + out-of-image rows)
    for (int i = tid; i < 2 * CV_PT_FLOATS; i += 256) Pt[i] = 0.f;
    __syncthreads();

    float c[4 == 4 ? 2 : 2][8][4] = {};   // [mt 2][nt 8][4]

    // prologue: chunks 0,1
    #pragma unroll
    for (int s = 0; s < 2; s++) {
        #pragma unroll
        for (int j = 0; j < 9; j++) {        // weights: 128 rows x 18 cp16
            int f = tid + 256 * j;
            int r = f / 18, q = (f % 18) * 4;
            cp16(smu_a + (s * CV_AS_FLOATS + r * 76 + q) * 4,
                 wf + (long)(o0 + r) * 4608 + s * 72 + q);
        }
        #pragma unroll
        for (int j = 0; j < 2; j++) {        // patch: 8ci x 4row x 16 cp16
            int f = tid + 256 * j;
            int ci = f >> 6, rq = (f >> 4) & 3, q = (f & 15) * 4;
            int h = h0 - 1 + rq;
            if (h >= 0 && h < 64)
                cp16(smu_p + (s * CV_PT_FLOATS + ci * 296 + rq * 72 + 4 + q) * 4,
                     cat + ((long)b * 512 + s * 8 + ci) * 4096 + h * 64 + q);
        }
        CP_COMMIT();
    }

    for (int chunk = 0; chunk < 64; chunk++) {
        if (chunk < 62) { CP_WAIT(1); } else { CP_WAIT(0); }
        __syncthreads();
        const float* As_ = Asm + (chunk & 1) * CV_AS_FLOATS;
        const float* Pt_ = Pt + (chunk & 1) * CV_PT_FLOATS;

        #pragma unroll
        for (int pos = 0; pos < 9; pos++) {
            const int kh = pos / 3, kw = pos % 3;
            uint32_t a[2][4], bb[8][2];
            #pragma unroll
            for (int mt = 0; mt < 2; mt++) {
                const float* ap = As_ + (wm * 32 + mt * 16 + (lane >> 2)) * 76
                                  + (lane & 3) * 9 + pos;
                a[mt][0] = ld_tf32(ap);
                a[mt][1] = ld_tf32(ap + 8 * 76);
                a[mt][2] = ld_tf32(ap + 36);          // ci + 4
                a[mt][3] = ld_tf32(ap + 8 * 76 + 36);
            }
            {
                int nbase = wn * 64 + (lane >> 2);
                int hh = nbase >> 6;                   // constant within warp
                const float* pb = Pt_ + (lane & 3) * 296 + (hh + kh) * 72;
                #pragma unroll
                for (int nt = 0; nt < 8; nt++) {
                    int wpos = ((nbase + nt * 8) & 63) + kw + 3;
                    bb[nt][0] = ld_tf32(pb + wpos);
                    bb[nt][1] = ld_tf32(pb + 4 * 296 + wpos);
                }
            }
            #pragma unroll
            for (int mt = 0; mt < 2; mt++)
                #pragma unroll
                for (int nt = 0; nt < 8; nt++)
                    mma_tf32(c[mt][nt], a[mt][0], a[mt][1], a[mt][2], a[mt][3],
                             bb[nt][0], bb[nt][1]);
        }
        __syncthreads();
        if (chunk + 2 < 64) {
            int s = chunk & 1;
            #pragma unroll
            for (int j = 0; j < 9; j++) {
                int f = tid + 256 * j;
                int r = f / 18, q = (f % 18) * 4;
                cp16(smu_a + (s * CV_AS_FLOATS + r * 76 + q) * 4,
                     wf + (long)(o0 + r) * 4608 + (chunk + 2) * 72 + q);
            }
            #pragma unroll
            for (int j = 0; j < 2; j++) {
                int f = tid + 256 * j;
                int ci = f >> 6, rq = (f >> 4) & 3, q = (f & 15) * 4;
                int h = h0 - 1 + rq;
                if (h >= 0 && h < 64)
                    cp16(smu_p + (s * CV_PT_FLOATS + ci * 296 + rq * 72 + 4 + q) * 4,
                         cat + ((long)b * 512 + (chunk + 2) * 8 + ci) * 4096 + h * 64 + q);
            }
            CP_COMMIT();
        }
    }

    #pragma unroll
    for (int mt = 0; mt < 2; mt++) {
        #pragma unroll
        for (int nt = 0; nt < 8; nt++) {
            int row = o0 + wm * 32 + mt * 16 + (lane >> 2);
            int col = p0 + wn * 64 + nt * 8 + 2 * (lane & 3);
            long yo = ((long)b * 256 + row) * 4096 + col;
            *(float2*)(y + yo) = make_float2(c[mt][nt][0], c[mt][nt][1]);
            *(float2*)(y + yo + 8 * 4096) = make_float2(c[mt][nt][2], c[mt][nt][3]);
        }
    }
}

// ---------------- helpers ----------------
__device__ __forceinline__ float warpMax(float v) {
    #pragma unroll
    for (int o = 16; o; o >>= 1) v = fmaxf(v, __shfl_xor_sync(0xffffffffu, v, o));
    return v;
}
__device__ __forceinline__ float warpSum(float v) {
    #pragma unroll
    for (int o = 16; o; o >>= 1) v += __shfl_xor_sync(0xffffffffu, v, o);
    return v;
}

__device__ __forceinline__ void mma_tile(const float (*As)[64], const float (*Bs)[64],
                                         float acc[4][4], int ty, int tx) {
    #pragma unroll
    for (int k = 0; k < 16; k++) {
        float4 a = *(const float4*)&As[k][ty * 4];
        float4 b = *(const float4*)&Bs[k][tx * 4];
        float ar[4] = {a.x, a.y, a.z, a.w};
        float br[4] = {b.x, b.y, b.z, b.w};
        #pragma unroll
        for (int i = 0; i < 4; i++)
            #pragma unroll
            for (int j = 0; j < 4; j++)
                acc[i][j] = fmaf(ar[i], br[j], acc[i][j]);
    }
}

__device__ __forceinline__ void epilogue(float* Out, int M, int N, int m0, int n0,
                                         int ty, int tx, float acc[4][4], int epi,
                                         const float* bias, const float* gsc,
                                         const float* res) {
    float g = gsc ? *gsc : 0.f;
    #pragma unroll
    for (int i = 0; i < 4; i++) {
        int m = m0 + ty * 4 + i;
        if (m < M) {
            long off = (long)m * N + n0 + tx * 4;
            float4 o;
            if (epi == 0) {
                float bv = bias[m];
                o = make_float4(acc[i][0] + bv, acc[i][1] + bv, acc[i][2] + bv, acc[i][3] + bv);
            } else if (epi == 1) {
                float4 r = *(const float4*)(res + off);
                o = make_float4(fmaf(g, acc[i][0], r.x), fmaf(g, acc[i][1], r.y),
                                fmaf(g, acc[i][2], r.z), fmaf(g, acc[i][3], r.w));
            } else {
                o = make_float4(acc[i][0], acc[i][1], acc[i][2], acc[i][3]);
            }
            *(float4*)(Out + off) = o;
        }
    }
}

// ---------------- fp32 SIMT GEMMs (small ops) ----------------

__global__ void gemm_nn_k(const float* __restrict__ A, const float* __restrict__ Bm,
                          float* __restrict__ Out, int M, int N, int K, int epi,
                          const float* __restrict__ bias, const float* __restrict__ gsc,
                          const float* __restrict__ res,
                          long sA, long sB, long sO, long sR) {
    int b = blockIdx.z;
    A += sA * b; Bm += sB * b; Out += sO * b;
    const float* resb = res ? res + sR * b : nullptr;
    __shared__ float As[16][64];
    __shared__ float Bs[16][64];
    int tid = threadIdx.x;
    int tx = tid & 15, ty = tid >> 4;
    int m0 = blockIdx.y * 64, n0 = blockIdx.x * 64;
    int arow = tid >> 2, ak = (tid & 3) * 4;
    int brow = tid >> 4, bn = (tid & 15) * 4;
    float acc[4][4] = {};
    for (int k0 = 0; k0 < K; k0 += 16) {
        float4 av = make_float4(0.f, 0.f, 0.f, 0.f);
        if (m0 + arow < M) av = *(const float4*)(A + (long)(m0 + arow) * K + k0 + ak);
        As[ak + 0][arow] = av.x; As[ak + 1][arow] = av.y;
        As[ak + 2][arow] = av.z; As[ak + 3][arow] = av.w;
        *(float4*)&Bs[brow][bn] = *(const float4*)(Bm + (long)(k0 + brow) * N + n0 + bn);
        __syncthreads();
        mma_tile(As, Bs, acc, ty, tx);
        __syncthreads();
    }
    epilogue(Out, M, N, m0, n0, ty, tx, acc, epi, bias, gsc, resb);
}

__global__ void gemm_nt_k(const float* __restrict__ A, const float* __restrict__ Bm,
                          float* __restrict__ Out, int M, int N, int K, int epi,
                          const float* __restrict__ bias, const float* __restrict__ gsc,
                          const float* __restrict__ res,
                          long sA, long sB, long sO, long sR) {
    int b = blockIdx.z;
    A += sA * b; Bm += sB * b; Out += sO * b;
    const float* resb = res ? res + sR * b : nullptr;
    __shared__ float As[16][64];
    __shared__ float Bs[16][64];
    int tid = threadIdx.x;
    int tx = tid & 15, ty = tid >> 4;
    int m0 = blockIdx.y * 64, n0 = blockIdx.x * 64;
    int arow = tid >> 2, ak = (tid & 3) * 4;
    float acc[4][4] = {};
    for (int k0 = 0; k0 < K; k0 += 16) {
        float4 av = make_float4(0.f, 0.f, 0.f, 0.f);
        if (m0 + arow < M) av = *(const float4*)(A + (long)(m0 + arow) * K + k0 + ak);
        As[ak + 0][arow] = av.x; As[ak + 1][arow] = av.y;
        As[ak + 2][arow] = av.z; As[ak + 3][arow] = av.w;
        float4 bv = *(const float4*)(Bm + (long)(n0 + arow) * K + k0 + ak);
        Bs[ak + 0][arow] = bv.x; Bs[ak + 1][arow] = bv.y;
        Bs[ak + 2][arow] = bv.z; Bs[ak + 3][arow] = bv.w;
        __syncthreads();
        mma_tile(As, Bs, acc, ty, tx);
        __syncthreads();
    }
    epilogue(Out, M, N, m0, n0, ty, tx, acc, epi, bias, gsc, resb);
}

// ---------------- softmax over 256 (channel attention) ----------------
__global__ void softmax256(float* __restrict__ data) {
    __shared__ float sh[8];
    float* p = data + (size_t)blockIdx.x * 256;
    int tid = threadIdx.x;
    float v = p[tid];
    float m = warpMax(v);
    if ((tid & 31) == 0) sh[tid >> 5] = m;
    __syncthreads();
    m = sh[tid & 7];
    #pragma unroll
    for (int o = 4; o; o >>= 1) m = fmaxf(m, __shfl_xor_sync(0xffffffffu, m, o));
    __syncthreads();
    float e = __expf(v - m);
    float s = warpSum(e);
    if ((tid & 31) == 0) sh[tid >> 5] = s;
    __syncthreads();
    s = sh[tid & 7];
    #pragma unroll
    for (int o = 4; o; o >>= 1) s += __shfl_xor_sync(0xffffffffu, s, o);
    p[tid] = e / s;
}

// ---------------- BN (train-mode batch stats) + ReLU ----------------
__global__ void bnstats(const float* __restrict__ y, float* __restrict__ meanp,
                        float* __restrict__ rstdp) {
    __shared__ float sh[16];
    int o = blockIdx.x, tid = threadIdx.x;
    float s = 0.f, sq = 0.f;
    for (int b = 0; b < 4; b++) {
        const float4* p = (const float4*)(y + ((size_t)b * 256 + o) * 4096);
        for (int i = tid; i < 1024; i += 256) {
            float4 v = p[i];
            s += v.x + v.y + v.z + v.w;
            sq += v.x * v.x + v.y * v.y + v.z * v.z + v.w * v.w;
        }
    }
    s = warpSum(s); sq = warpSum(sq);
    if ((tid & 31) == 0) { sh[tid >> 5] = s; sh[8 + (tid >> 5)] = sq; }
    __syncthreads();
    if (tid == 0) {
        float S = 0.f, SQ = 0.f;
        for (int i = 0; i < 8; i++) { S += sh[i]; SQ += sh[8 + i]; }
        float mean = S / 16384.f;
        float var = SQ / 16384.f - mean * mean;
        meanp[o] = mean;
        rstdp[o] = rsqrtf(var + 1e-5f);
    }
}

__global__ void bnapply(const float* __restrict__ y, const float* __restrict__ gam,
                        const float* __restrict__ bet, const float* __restrict__ meanp,
                        const float* __restrict__ rstdp, float* __restrict__ out) {
    size_t i = (size_t)blockIdx.x * 256 + threadIdx.x;  // float4 index
    int o = (int)((i >> 10) & 255);
    float mu = meanp[o], rs = rstdp[o], g = gam[o], be = bet[o];
    float4 v = ((const float4*)y)[i];
    float4 r;
    r.x = fmaxf(0.f, fmaf((v.x - mu) * rs, g, be));
    r.y = fmaxf(0.f, fmaf((v.y - mu) * rs, g, be));
    r.z = fmaxf(0.f, fmaf((v.z - mu) * rs, g, be));
    r.w = fmaxf(0.f, fmaf((v.w - mu) * rs, g, be));
    ((float4*)out)[i] = r;
}

// ---------------- launcher ----------------
extern "C" void kernel_launch(void* const* d_in, const int* in_sizes, int n_in,
                              void* d_out, int out_size) {
    const float* x   = (const float*)d_in[0];
    const float* wq  = (const float*)d_in[1];
    const float* bq  = (const float*)d_in[2];
    const float* wk  = (const float*)d_in[3];
    const float* bk  = (const float*)d_in[4];
    const float* wv  = (const float*)d_in[5];
    const float* bv  = (const float*)d_in[6];
    const float* gpa = (const float*)d_in[7];
    const float* gca = (const float*)d_in[8];
    const float* wf  = (const float*)d_in[9];
    const float* bng = (const float*)d_in[10];
    const float* bnb = (const float*)d_in[11];
    float* out = (float*)d_out;

    float *q, *k, *v, *attn, *cat, *cattn, *y, *mean, *rstd;
    cudaGetSymbolAddress((void**)&q, g_q);
    cudaGetSymbolAddress((void**)&k, g_k);
    cudaGetSymbolAddress((void**)&v, g_v);
    cudaGetSymbolAddress((void**)&attn, g_attn);
    cudaGetSymbolAddress((void**)&cat, g_cat);
    cudaGetSymbolAddress((void**)&cattn, g_cattn);
    cudaGetSymbolAddress((void**)&y, g_y);
    cudaGetSymbolAddress((void**)&mean, g_mean);
    cudaGetSymbolAddress((void**)&rstd, g_rstd);

    cudaFuncSetAttribute(pa_mma, cudaFuncAttributeMaxDynamicSharedMemorySize,
                         PA_SMEM_BYTES);
    cudaFuncSetAttribute(gemm_nn_mma, cudaFuncAttributeMaxDynamicSharedMemorySize,
                         NN_SMEM_BYTES);
    cudaFuncSetAttribute(conv_mma, cudaFuncAttributeMaxDynamicSharedMemorySize,
                         CV_SMEM_BYTES);

    dim3 blk(256);
    long sx = (long)C_ * N_;
    long sqk = (long)CQ_ * N_;
    long scat = (long)2 * C_ * N_;

    // q, k projections (small; fp32 SIMT)
    gemm_nn_k<<<dim3(64, 1, 4), blk>>>(wq, x, q, CQ_, N_, C_, 0, bq, nullptr, nullptr,
                                       0, sx, sqk, 0);
    gemm_nn_k<<<dim3(64, 1, 4), blk>>>(wk, x, k, CQ_, N_, C_, 0, bk, nullptr, nullptr,
                                       0, sx, sqk, 0);
    // v projection on tensor cores
    gemm_nn_mma<<<dim3(32, 2, 4), blk, NN_SMEM_BYTES>>>(
        wv, x, v, C_, 0, bv, nullptr, nullptr, 0, sx, sx, 0);
    // logits + exp (no separate softmax pass)
    qk_exp<<<dim3(32, 32, 4), blk>>>(q, k, attn);
    // PA (M=256, attn read once) with fused 1/l normalization -> cat[:, 0:256]
    pa_mma<<<dim3(32, 1, 4), blk, PA_SMEM_BYTES>>>(v, attn, x, gpa, cat);
    // channel attention: logits, softmax, apply -> cat[:, 256:512]
    gemm_nt_k<<<dim3(4, 4, 4), blk>>>(x, x, cattn, C_, C_, N_, 2, nullptr, nullptr,
                                      nullptr, sx, sx, (long)C_ * C_, 0);
    softmax256<<<B_ * C_, 256>>>(cattn);
    gemm_nn_mma<<<dim3(32, 2, 4), blk, NN_SMEM_BYTES>>>(
        cattn, x, cat + (size_t)C_ * N_, C_, 1, nullptr, gca, x,
        (long)C_ * C_, sx, scat, sx);
    // 3x3 conv 512->256 (implicit GEMM v2, tensor cores)
    conv_mma<<<dim3(32, 2, 4), blk, CV_SMEM_BYTES>>>(cat, wf, y);
    // BN train-mode + ReLU
    bnstats<<<256, 256>>>(y, mean, rstd);
    bnapply<<<4096, 256>>>(y, bng, bnb, mean, rstd, out);
}

// round 9
// speedup vs baseline: 2.2647x; 1.2745x over previous
#include <cuda_runtime.h>
#include <cuda_bf16.h>
#include <cstdint>

#define B_  4
#define C_  256
#define CQ_ 32
#define N_  4096
#define HW_ 64

// ---------------- scratch (device globals; no allocation) ----------------
__device__ float g_q[B_ * CQ_ * N_];
__device__ float g_k[B_ * CQ_ * N_];
__device__ float g_v[B_ * C_ * N_];
__device__ __nv_bfloat16 g_attn[(size_t)B_ * N_ * N_];   // exp(logits), bf16, 128 MB
__device__ float g_cat[(size_t)B_ * 2 * C_ * N_];        // [b][512][4096]
__device__ float g_cattn_part[32 * C_ * C_];             // split-K partials, 8 MB
__device__ float g_cattn[B_ * C_ * C_];
__device__ float g_y[(size_t)B_ * C_ * N_];
__device__ float g_mean[C_];
__device__ float g_rstd[C_];

// ---------------- PTX helpers (sm_80+ mma.sync / cp.async) ----------------
__device__ __forceinline__ uint32_t smem_to_u32(const void* p) {
    uint32_t a;
    asm("{ .reg .u64 t; cvta.to.shared.u64 t, %1; cvt.u32.u64 %0, t; }" : "=r"(a) : "l"(p));
    return a;
}
__device__ __forceinline__ void cp16(uint32_t dst, const void* src) {
    asm volatile("cp.async.cg.shared.global [%0], [%1], 16;" :: "r"(dst), "l"(src));
}
#define CP_COMMIT() asm volatile("cp.async.commit_group;" ::: "memory")
#define CP_WAIT(n)  asm volatile("cp.async.wait_group %0;" :: "n"(n) : "memory")

__device__ __forceinline__ uint32_t ld_tf32(const float* p) {
    uint32_t r;
    float f = *p;
    asm("cvt.rna.tf32.f32 %0, %1;" : "=r"(r) : "f"(f));
    return r;
}
__device__ __forceinline__ uint32_t bf_tf32(const __nv_bfloat16* p) {
    uint32_t r;
    float f = __bfloat162float(*p);
    asm("cvt.rna.tf32.f32 %0, %1;" : "=r"(r) : "f"(f));
    return r;
}
__device__ __forceinline__ void mma_tf32(float c[4], uint32_t a0, uint32_t a1,
                                         uint32_t a2, uint32_t a3,
                                         uint32_t b0, uint32_t b1) {
    asm volatile(
        "mma.sync.aligned.m16n8k8.row.col.f32.tf32.tf32.f32 "
        "{%0,%1,%2,%3}, {%4,%5,%6,%7}, {%8,%9}, {%0,%1,%2,%3};"
        : "+f"(c[0]), "+f"(c[1]), "+f"(c[2]), "+f"(c[3])
        : "r"(a0), "r"(a1), "r"(a2), "r"(a3), "r"(b0), "r"(b1));
}

// =================================================================
// qk_exp (tf32 mma): attn[b,i,j] = bf16( exp( sum_d q[b,d,i]*k[b,d,j] ) )
// =================================================================
__global__ void __launch_bounds__(256)
qk_exp(const float* __restrict__ qg, const float* __restrict__ kg,
       __nv_bfloat16* __restrict__ attn) {
    __shared__ float qs[32 * 132];
    __shared__ float ks[32 * 132];
    int tid = threadIdx.x, lane = tid & 31, w = tid >> 5;
    int wm = w & 3, wn = w >> 2;
    int b = blockIdx.z;
    int I0 = blockIdx.y * 128, J0 = blockIdx.x * 128;
    const float* Qg = qg + (long)b * CQ_ * N_;
    const float* Kg = kg + (long)b * CQ_ * N_;

    #pragma unroll
    for (int jj = 0; jj < 4; jj++) {
        int idx = tid + 256 * jj;           // 0..1023
        int d = idx >> 5, c4 = (idx & 31) * 4;
        *(float4*)&qs[d * 132 + c4] = *(const float4*)(Qg + (long)d * N_ + I0 + c4);
        *(float4*)&ks[d * 132 + c4] = *(const float4*)(Kg + (long)d * N_ + J0 + c4);
    }
    __syncthreads();

    float acc[2][8][4] = {};
    #pragma unroll
    for (int k8 = 0; k8 < 32; k8 += 8) {
        uint32_t a[2][4], bb[8][2];
        int d0 = k8 + (lane & 3);
        #pragma unroll
        for (int mt = 0; mt < 2; mt++) {
            int i = wm * 32 + mt * 16 + (lane >> 2);
            a[mt][0] = ld_tf32(&qs[d0 * 132 + i]);
            a[mt][1] = ld_tf32(&qs[d0 * 132 + i + 8]);
            a[mt][2] = ld_tf32(&qs[(d0 + 4) * 132 + i]);
            a[mt][3] = ld_tf32(&qs[(d0 + 4) * 132 + i + 8]);
        }
        #pragma unroll
        for (int nt = 0; nt < 8; nt++) {
            int j = wn * 64 + nt * 8 + (lane >> 2);
            bb[nt][0] = ld_tf32(&ks[d0 * 132 + j]);
            bb[nt][1] = ld_tf32(&ks[(d0 + 4) * 132 + j]);
        }
        #pragma unroll
        for (int mt = 0; mt < 2; mt++)
            #pragma unroll
            for (int nt = 0; nt < 8; nt++)
                mma_tf32(acc[mt][nt], a[mt][0], a[mt][1], a[mt][2], a[mt][3],
                         bb[nt][0], bb[nt][1]);
    }

    #pragma unroll
    for (int mt = 0; mt < 2; mt++) {
        int row = I0 + wm * 32 + mt * 16 + (lane >> 2);
        #pragma unroll
        for (int nt = 0; nt < 8; nt++) {
            int col = J0 + wn * 64 + nt * 8 + 2 * (lane & 3);
            long o = (long)b * N_ * N_ + (long)row * N_ + col;
            *(__nv_bfloat162*)(attn + o) =
                __floats2bfloat162_rn(__expf(acc[mt][nt][0]), __expf(acc[mt][nt][1]));
            *(__nv_bfloat162*)(attn + o + 8 * N_) =
                __floats2bfloat162_rn(__expf(acc[mt][nt][2]), __expf(acc[mt][nt][3]));
        }
    }
}

// =================================================================
// PA GEMM (tf32 mma, bf16 attn) with fused softmax-normalization.
// M=256: one CTA covers all channels for a 128-wide i tile.
//   cat[b,c,i] = gamma_pa*(1/l_i)*sum_j v[b,c,j]*attn[b,i,j] + x[b,c,i]
// smem: As 2x[256][36] f32, Bs 2x[128][40] bf16 (stride 40 -> conflict-free).
// =================================================================
#define PA_BS_ELE (128 * 40)                              // bf16 per buffer
#define PA_SMEM_BYTES ((2 * 256 * 36) * 4 + 2 * PA_BS_ELE * 2)   // 94208

__global__ void __launch_bounds__(256)
pa_mma(const float* __restrict__ v, const __nv_bfloat16* __restrict__ attn,
       const float* __restrict__ x, const float* __restrict__ gpa,
       float* __restrict__ cat) {
    extern __shared__ float sm[];
    float* Asm = sm;                                       // 2 x 256*36 f32
    __nv_bfloat16* Bsm = (__nv_bfloat16*)(sm + 2 * 256 * 36);  // 2 x 128*40 bf16
    __shared__ float red[256];
    int tid = threadIdx.x, lane = tid & 31, wid = tid >> 5;
    int wm = wid & 3, wn = wid >> 2;
    int b = blockIdx.z, n0 = blockIdx.x * 128;
    const float* Ag = v + (long)b * C_ * N_;
    const __nv_bfloat16* Bg = attn + (long)b * N_ * N_ + (long)n0 * N_;
    uint32_t smu_a = smem_to_u32(Asm), smu_b = smem_to_u32(Bsm);

    float c[4][8][4] = {};
    float part = 0.f;                  // row-sum strip: row=tid>>1, k=(tid&1)*16..+15
    int srow = tid >> 1, skoff = (tid & 1) * 16;

    #pragma unroll
    for (int s = 0; s < 2; s++) {
        int k0 = s * 32;
        #pragma unroll
        for (int j = 0; j < 8; j++) {            // A: 256 rows x 8 quads (f32)
            int f = tid + 256 * j;
            int r = f >> 3, q = (f & 7) * 4;
            cp16(smu_a + (s * 9216 + r * 36 + q) * 4, Ag + (long)r * N_ + k0 + q);
        }
        #pragma unroll
        for (int j = 0; j < 2; j++) {            // B: 128 rows x 4 oct (bf16)
            int f = tid + 256 * j;
            int r = f >> 2, q = (f & 3) * 8;
            cp16(smu_b + (s * PA_BS_ELE + r * 40 + q) * 2, Bg + (long)r * N_ + k0 + q);
        }
        CP_COMMIT();
    }

    for (int ch = 0; ch < 128; ch++) {
        if (ch < 126) { CP_WAIT(1); } else { CP_WAIT(0); }
        __syncthreads();
        const float* As_ = Asm + (ch & 1) * 9216;
        const __nv_bfloat16* Bs_ = Bsm + (ch & 1) * PA_BS_ELE;
        // accumulate row sums l_i from the staged attn tile
        {
            const __nv_bfloat162* bp =
                (const __nv_bfloat162*)(Bs_ + srow * 40 + skoff);
            #pragma unroll
            for (int kk = 0; kk < 8; kk++) {
                float2 f2 = __bfloat1622float2(bp[kk]);
                part += f2.x + f2.y;
            }
        }
        #pragma unroll
        for (int k8 = 0; k8 < 32; k8 += 8) {
            uint32_t a[4][4], bb[8][2];
            #pragma unroll
            for (int mt = 0; mt < 4; mt++) {
                const float* ap = As_ + (wm * 64 + mt * 16 + (lane >> 2)) * 36 + k8 + (lane & 3);
                a[mt][0] = ld_tf32(ap);
                a[mt][1] = ld_tf32(ap + 8 * 36);
                a[mt][2] = ld_tf32(ap + 4);
                a[mt][3] = ld_tf32(ap + 8 * 36 + 4);
            }
            #pragma unroll
            for (int nt = 0; nt < 8; nt++) {
                const __nv_bfloat16* bp = Bs_ + (wn * 64 + nt * 8 + (lane >> 2)) * 40
                                          + k8 + (lane & 3);
                bb[nt][0] = bf_tf32(bp);
                bb[nt][1] = bf_tf32(bp + 4);
            }
            #pragma unroll
            for (int mt = 0; mt < 4; mt++)
                #pragma unroll
                for (int nt = 0; nt < 8; nt++)
                    mma_tf32(c[mt][nt], a[mt][0], a[mt][1], a[mt][2], a[mt][3],
                             bb[nt][0], bb[nt][1]);
        }
        __syncthreads();
        if (ch + 2 < 128) {
            int s = ch & 1;
            int k0 = (ch + 2) * 32;
            #pragma unroll
            for (int j = 0; j < 8; j++) {
                int f = tid + 256 * j;
                int r = f >> 3, q = (f & 7) * 4;
                cp16(smu_a + (s * 9216 + r * 36 + q) * 4, Ag + (long)r * N_ + k0 + q);
            }
            #pragma unroll
            for (int j = 0; j < 2; j++) {
                int f = tid + 256 * j;
                int r = f >> 2, q = (f & 3) * 8;
                cp16(smu_b + (s * PA_BS_ELE + r * 40 + q) * 2, Bg + (long)r * N_ + k0 + q);
            }
            CP_COMMIT();
        }
    }

    red[tid] = part;
    __syncthreads();

    float g = gpa[0];
    #pragma unroll
    for (int nt = 0; nt < 8; nt++) {
        int cl = wn * 64 + nt * 8 + 2 * (lane & 3);
        float inv0 = 1.f / (red[2 * cl] + red[2 * cl + 1]);
        float inv1 = 1.f / (red[2 * cl + 2] + red[2 * cl + 3]);
        #pragma unroll
        for (int mt = 0; mt < 4; mt++) {
            int row = wm * 64 + mt * 16 + (lane >> 2);
            int col = n0 + cl;
            long xo = ((long)b * C_ + row) * N_ + col;
            long co = ((long)b * 2 * C_ + row) * N_ + col;
            *(float2*)(cat + co) = make_float2(
                fmaf(g, c[mt][nt][0] * inv0, x[xo]),
                fmaf(g, c[mt][nt][1] * inv1, x[xo + 1]));
            *(float2*)(cat + co + 8 * N_) = make_float2(
                fmaf(g, c[mt][nt][2] * inv0, x[xo + 8 * N_]),
                fmaf(g, c[mt][nt][3] * inv1, x[xo + 8 * N_ + 1]));
        }
    }
}

// =================================================================
// xxT_mma: split-K channel-logits partials (tf32 mma, NT):
//   part[z][i][j] = sum_{n in ks-slice} x[b,i,n] * x[b,j,n],  z = b*8+ks
// CTA 128x128, K=512 per split, BK=32, double buffer.
// =================================================================
#define XT_SMEM_BYTES ((2 * 128 * 36 * 2) * 4)   // 73728

__global__ void __launch_bounds__(256)
xxT_mma(const float* __restrict__ x, float* __restrict__ part) {
    extern __shared__ float sm[];
    float* Asm = sm;                   // 2 x 128*36
    float* Bsm = sm + 2 * 128 * 36;    // 2 x 128*36
    int tid = threadIdx.x, lane = tid & 31, wid = tid >> 5;
    int wm = wid & 3, wn = wid >> 2;
    int z = blockIdx.z, b = z >> 3, ks = z & 7;
    int m0 = blockIdx.y * 128, n0 = blockIdx.x * 128;
    const float* Ag = x + (long)b * C_ * N_ + (long)m0 * N_ + ks * 512;
    const float* Bg = x + (long)b * C_ * N_ + (long)n0 * N_ + ks * 512;
    uint32_t smu_a = smem_to_u32(Asm), smu_b = smem_to_u32(Bsm);
    float c[2][8][4] = {};

    #pragma unroll
    for (int s = 0; s < 2; s++) {
        int k0 = s * 32;
        #pragma unroll
        for (int j = 0; j < 4; j++) {
            int f = tid + 256 * j;
            int r = f >> 3, q = (f & 7) * 4;
            cp16(smu_a + (s * 4608 + r * 36 + q) * 4, Ag + (long)r * N_ + k0 + q);
            cp16(smu_b + (s * 4608 + r * 36 + q) * 4, Bg + (long)r * N_ + k0 + q);
        }
        CP_COMMIT();
    }

    for (int ch = 0; ch < 16; ch++) {
        if (ch < 14) { CP_WAIT(1); } else { CP_WAIT(0); }
        __syncthreads();
        const float* As_ = Asm + (ch & 1) * 4608;
        const float* Bs_ = Bsm + (ch & 1) * 4608;
        #pragma unroll
        for (int k8 = 0; k8 < 32; k8 += 8) {
            uint32_t a[2][4], bb[8][2];
            #pragma unroll
            for (int mt = 0; mt < 2; mt++) {
                const float* ap = As_ + (wm * 32 + mt * 16 + (lane >> 2)) * 36 + k8 + (lane & 3);
                a[mt][0] = ld_tf32(ap);
                a[mt][1] = ld_tf32(ap + 8 * 36);
                a[mt][2] = ld_tf32(ap + 4);
                a[mt][3] = ld_tf32(ap + 8 * 36 + 4);
            }
            #pragma unroll
            for (int nt = 0; nt < 8; nt++) {
                const float* bp = Bs_ + (wn * 64 + nt * 8 + (lane >> 2)) * 36 + k8 + (lane & 3);
                bb[nt][0] = ld_tf32(bp);
                bb[nt][1] = ld_tf32(bp + 4);
            }
            #pragma unroll
            for (int mt = 0; mt < 2; mt++)
                #pragma unroll
                for (int nt = 0; nt < 8; nt++)
                    mma_tf32(c[mt][nt], a[mt][0], a[mt][1], a[mt][2], a[mt][3],
                             bb[nt][0], bb[nt][1]);
        }
        __syncthreads();
        if (ch + 2 < 16) {
            int s = ch & 1;
            int k0 = (ch + 2) * 32;
            #pragma unroll
            for (int j = 0; j < 4; j++) {
                int f = tid + 256 * j;
                int r = f >> 3, q = (f & 7) * 4;
                cp16(smu_a + (s * 4608 + r * 36 + q) * 4, Ag + (long)r * N_ + k0 + q);
                cp16(smu_b + (s * 4608 + r * 36 + q) * 4, Bg + (long)r * N_ + k0 + q);
            }
            CP_COMMIT();
        }
    }

    float* Ob = part + (long)z * C_ * C_;
    #pragma unroll
    for (int mt = 0; mt < 2; mt++) {
        int row = m0 + wm * 32 + mt * 16 + (lane >> 2);
        #pragma unroll
        for (int nt = 0; nt < 8; nt++) {
            int col = n0 + wn * 64 + nt * 8 + 2 * (lane & 3);
            long o = (long)row * C_ + col;
            *(float2*)(Ob + o) = make_float2(c[mt][nt][0], c[mt][nt][1]);
            *(float2*)(Ob + o + 8 * C_) = make_float2(c[mt][nt][2], c[mt][nt][3]);
        }
    }
}

// =================================================================
// NN-GEMM (tf32 mma): Out[m][n] = sum_k A[m][k] * B[k][n]
// =================================================================
#define NN_SMEM_BYTES ((2 * 128 * 36 + 2 * 32 * 132) * 4)   // 70656

__global__ void __launch_bounds__(256)
gemm_nn_mma(const float* __restrict__ A, const float* __restrict__ B,
            float* __restrict__ Out, int K, int epi,
            const float* __restrict__ bias, const float* __restrict__ gsc,
            const float* __restrict__ res,
            long sA, long sB, long sO, long sR) {
    extern __shared__ float sm[];
    float* As = sm;                      // 2 x [128][36]
    float* Bs = sm + 2 * 128 * 36;       // 2 x [32][132]
    int tid = threadIdx.x, lane = tid & 31, w = tid >> 5;
    int wm = w & 3, wn = w >> 2;
    int b = blockIdx.z, m0 = blockIdx.y * 128, n0 = blockIdx.x * 128;
    const float* Ag = A + sA * b + (long)m0 * K;
    const float* Bg = B + sB * b + n0;
    uint32_t smu_a = smem_to_u32(As), smu_b = smem_to_u32(Bs);
    float acc[2][8][4] = {};
    int nchunks = K / 32;

    #pragma unroll
    for (int s = 0; s < 2; s++) {
        #pragma unroll
        for (int jj = 0; jj < 4; jj++) {
            int idx = tid + 256 * jj;
            int r = idx >> 3, kq = (idx & 7) * 4;
            cp16(smu_a + (s * 4608 + r * 36 + kq) * 4, Ag + (long)r * K + s * 32 + kq);
            int kk = idx >> 5, nq = (idx & 31) * 4;
            cp16(smu_b + (s * 4224 + kk * 132 + nq) * 4, Bg + (long)(s * 32 + kk) * N_ + nq);
        }
        CP_COMMIT();
    }

    for (int ch = 0; ch < nchunks; ch++) {
        if (ch < nchunks - 2) { CP_WAIT(1); } else { CP_WAIT(0); }
        __syncthreads();
        const float* As_ = As + (ch & 1) * 4608;
        const float* Bs_ = Bs + (ch & 1) * 4224;
        #pragma unroll
        for (int k8 = 0; k8 < 32; k8 += 8) {
            uint32_t a[2][4], bb[8][2];
            #pragma unroll
            for (int mt = 0; mt < 2; mt++) {
                const float* ap = As_ + (wm * 32 + mt * 16 + (lane >> 2)) * 36 + k8 + (lane & 3);
                a[mt][0] = ld_tf32(ap);
                a[mt][1] = ld_tf32(ap + 8 * 36);
                a[mt][2] = ld_tf32(ap + 4);
                a[mt][3] = ld_tf32(ap + 8 * 36 + 4);
            }
            #pragma unroll
            for (int nt = 0; nt < 8; nt++) {
                const float* bp = Bs_ + (k8 + (lane & 3)) * 132 + wn * 64 + nt * 8 + (lane >> 2);
                bb[nt][0] = ld_tf32(bp);
                bb[nt][1] = ld_tf32(bp + 4 * 132);
            }
            #pragma unroll
            for (int mt = 0; mt < 2; mt++)
                #pragma unroll
                for (int nt = 0; nt < 8; nt++)
                    mma_tf32(acc[mt][nt], a[mt][0], a[mt][1], a[mt][2], a[mt][3],
                             bb[nt][0], bb[nt][1]);
        }
        __syncthreads();
        if (ch + 2 < nchunks) {
            int s = ch & 1;
            #pragma unroll
            for (int jj = 0; jj < 4; jj++) {
                int idx = tid + 256 * jj;
                int r = idx >> 3, kq = (idx & 7) * 4;
                cp16(smu_a + (s * 4608 + r * 36 + kq) * 4,
                     Ag + (long)r * K + (ch + 2) * 32 + kq);
                int kk = idx >> 5, nq = (idx & 31) * 4;
                cp16(smu_b + (s * 4224 + kk * 132 + nq) * 4,
                     Bg + (long)((ch + 2) * 32 + kk) * N_ + nq);
            }
            CP_COMMIT();
        }
    }

    float g = gsc ? *gsc : 0.f;
    const float* resb = res ? res + sR * b : nullptr;
    float* Ob = Out + sO * b;
    #pragma unroll
    for (int mt = 0; mt < 2; mt++) {
        int row = m0 + wm * 32 + mt * 16 + (lane >> 2);
        #pragma unroll
        for (int nt = 0; nt < 8; nt++) {
            int col = n0 + wn * 64 + nt * 8 + 2 * (lane & 3);
            long o = (long)row * N_ + col;
            if (epi == 0) {
                float bv = bias[row], bv8 = bias[row + 8];
                *(float2*)(Ob + o) = make_float2(acc[mt][nt][0] + bv, acc[mt][nt][1] + bv);
                *(float2*)(Ob + o + 8 * N_) =
                    make_float2(acc[mt][nt][2] + bv8, acc[mt][nt][3] + bv8);
            } else {
                *(float2*)(Ob + o) = make_float2(
                    fmaf(g, acc[mt][nt][0], resb[o]), fmaf(g, acc[mt][nt][1], resb[o + 1]));
                *(float2*)(Ob + o + 8 * N_) = make_float2(
                    fmaf(g, acc[mt][nt][2], resb[o + 8 * N_]),
                    fmaf(g, acc[mt][nt][3], resb[o + 8 * N_ + 1]));
            }
        }
    }
}

// =================================================================
// 3x3 conv 512 -> 256, implicit GEMM v2 (tf32 mma)
// =================================================================
#define CV_AS_FLOATS  (128 * 76)         // 9728 per buffer
#define CV_PT_FLOATS  (8 * 296)          // 2368 per buffer
#define CV_SMEM_BYTES ((2 * CV_AS_FLOATS + 2 * CV_PT_FLOATS) * 4)   // 96768

__global__ void __launch_bounds__(256)
conv_mma(const float* __restrict__ cat, const float* __restrict__ wf,
         float* __restrict__ y) {
    extern __shared__ float sm[];
    float* Asm = sm;                         // 2 x [128][76]
    float* Pt = sm + 2 * CV_AS_FLOATS;       // 2 x [8][296]
    int tid = threadIdx.x, lane = tid & 31, wid = tid >> 5;
    int wm = wid & 3, wn = wid >> 2;
    int b = blockIdx.z, o0 = blockIdx.y * 128, p0 = blockIdx.x * 128;
    int h0 = blockIdx.x * 2;
    uint32_t smu_a = smem_to_u32(Asm), smu_p = smem_to_u32(Pt);

    for (int i = tid; i < 2 * CV_PT_FLOATS; i += 256) Pt[i] = 0.f;
    __syncthreads();

    float c[2][8][4] = {};

    #pragma unroll
    for (int s = 0; s < 2; s++) {
        #pragma unroll
        for (int j = 0; j < 9; j++) {
            int f = tid + 256 * j;
            int r = f / 18, q = (f % 18) * 4;
            cp16(smu_a + (s * CV_AS_FLOATS + r * 76 + q) * 4,
                 wf + (long)(o0 + r) * 4608 + s * 72 + q);
        }
        #pragma unroll
        for (int j = 0; j < 2; j++) {
            int f = tid + 256 * j;
            int ci = f >> 6, rq = (f >> 4) & 3, q = (f & 15) * 4;
            int h = h0 - 1 + rq;
            if (h >= 0 && h < 64)
                cp16(smu_p + (s * CV_PT_FLOATS + ci * 296 + rq * 72 + 4 + q) * 4,
                     cat + ((long)b * 512 + s * 8 + ci) * 4096 + h * 64 + q);
        }
        CP_COMMIT();
    }

    for (int chunk = 0; chunk < 64; chunk++) {
        if (chunk < 62) { CP_WAIT(1); } else { CP_WAIT(0); }
        __syncthreads();
        const float* As_ = Asm + (chunk & 1) * CV_AS_FLOATS;
        const float* Pt_ = Pt + (chunk & 1) * CV_PT_FLOATS;

        #pragma unroll
        for (int pos = 0; pos < 9; pos++) {
            const int kh = pos / 3, kw = pos % 3;
            uint32_t a[2][4], bb[8][2];
            #pragma unroll
            for (int mt = 0; mt < 2; mt++) {
                const float* ap = As_ + (wm * 32 + mt * 16 + (lane >> 2)) * 76
                                  + (lane & 3) * 9 + pos;
                a[mt][0] = ld_tf32(ap);
                a[mt][1] = ld_tf32(ap + 8 * 76);
                a[mt][2] = ld_tf32(ap + 36);          // ci + 4
                a[mt][3] = ld_tf32(ap + 8 * 76 + 36);
            }
            {
                int nbase = wn * 64 + (lane >> 2);
                int hh = nbase >> 6;
                const float* pb = Pt_ + (lane & 3) * 296 + (hh + kh) * 72;
                #pragma unroll
                for (int nt = 0; nt < 8; nt++) {
                    int wpos = ((nbase + nt * 8) & 63) + kw + 3;
                    bb[nt][0] = ld_tf32(pb + wpos);
                    bb[nt][1] = ld_tf32(pb + 4 * 296 + wpos);
                }
            }
            #pragma unroll
            for (int mt = 0; mt < 2; mt++)
                #pragma unroll
                for (int nt = 0; nt < 8; nt++)
                    mma_tf32(c[mt][nt], a[mt][0], a[mt][1], a[mt][2], a[mt][3],
                             bb[nt][0], bb[nt][1]);
        }
        __syncthreads();
        if (chunk + 2 < 64) {
            int s = chunk & 1;
            #pragma unroll
            for (int j = 0; j < 9; j++) {
                int f = tid + 256 * j;
                int r = f / 18, q = (f % 18) * 4;
                cp16(smu_a + (s * CV_AS_FLOATS + r * 76 + q) * 4,
                     wf + (long)(o0 + r) * 4608 + (chunk + 2) * 72 + q);
            }
            #pragma unroll
            for (int j = 0; j < 2; j++) {
                int f = tid + 256 * j;
                int ci = f >> 6, rq = (f >> 4) & 3, q = (f & 15) * 4;
                int h = h0 - 1 + rq;
                if (h >= 0 && h < 64)
                    cp16(smu_p + (s * CV_PT_FLOATS + ci * 296 + rq * 72 + 4 + q) * 4,
                         cat + ((long)b * 512 + (chunk + 2) * 8 + ci) * 4096 + h * 64 + q);
            }
            CP_COMMIT();
        }
    }

    #pragma unroll
    for (int mt = 0; mt < 2; mt++) {
        #pragma unroll
        for (int nt = 0; nt < 8; nt++) {
            int row = o0 + wm * 32 + mt * 16 + (lane >> 2);
            int col = p0 + wn * 64 + nt * 8 + 2 * (lane & 3);
            long yo = ((long)b * 256 + row) * 4096 + col;
            *(float2*)(y + yo) = make_float2(c[mt][nt][0], c[mt][nt][1]);
            *(float2*)(y + yo + 8 * 4096) = make_float2(c[mt][nt][2], c[mt][nt][3]);
        }
    }
}

// ---------------- helpers ----------------
__device__ __forceinline__ float warpMax(float v) {
    #pragma unroll
    for (int o = 16; o; o >>= 1) v = fmaxf(v, __shfl_xor_sync(0xffffffffu, v, o));
    return v;
}
__device__ __forceinline__ float warpSum(float v) {
    #pragma unroll
    for (int o = 16; o; o >>= 1) v += __shfl_xor_sync(0xffffffffu, v, o);
    return v;
}

__device__ __forceinline__ void mma_tile(const float (*As)[64], const float (*Bs)[64],
                                         float acc[4][4], int ty, int tx) {
    #pragma unroll
    for (int k = 0; k < 16; k++) {
        float4 a = *(const float4*)&As[k][ty * 4];
        float4 b = *(const float4*)&Bs[k][tx * 4];
        float ar[4] = {a.x, a.y, a.z, a.w};
        float br[4] = {b.x, b.y, b.z, b.w};
        #pragma unroll
        for (int i = 0; i < 4; i++)
            #pragma unroll
            for (int j = 0; j < 4; j++)
                acc[i][j] = fmaf(ar[i], br[j], acc[i][j]);
    }
}

__device__ __forceinline__ void epilogue(float* Out, int M, int N, int m0, int n0,
                                         int ty, int tx, float acc[4][4], int epi,
                                         const float* bias, const float* gsc,
                                         const float* res) {
    float g = gsc ? *gsc : 0.f;
    #pragma unroll
    for (int i = 0; i < 4; i++) {
        int m = m0 + ty * 4 + i;
        if (m < M) {
            long off = (long)m * N + n0 + tx * 4;
            float4 o;
            if (epi == 0) {
                float bv = bias[m];
                o = make_float4(acc[i][0] + bv, acc[i][1] + bv, acc[i][2] + bv, acc[i][3] + bv);
            } else if (epi == 1) {
                float4 r = *(const float4*)(res + off);
                o = make_float4(fmaf(g, acc[i][0], r.x), fmaf(g, acc[i][1], r.y),
                                fmaf(g, acc[i][2], r.z), fmaf(g, acc[i][3], r.w));
            } else {
                o = make_float4(acc[i][0], acc[i][1], acc[i][2], acc[i][3]);
            }
            *(float4*)(Out + off) = o;
        }
    }
}

// ---------------- fp32 SIMT GEMM (q/k projections) ----------------
__global__ void gemm_nn_k(const float* __restrict__ A, const float* __restrict__ Bm,
                          float* __restrict__ Out, int M, int N, int K, int epi,
                          const float* __restrict__ bias, const float* __restrict__ gsc,
                          const float* __restrict__ res,
                          long sA, long sB, long sO, long sR) {
    int b = blockIdx.z;
    A += sA * b; Bm += sB * b; Out += sO * b;
    const float* resb = res ? res + sR * b : nullptr;
    __shared__ float As[16][64];
    __shared__ float Bs[16][64];
    int tid = threadIdx.x;
    int tx = tid & 15, ty = tid >> 4;
    int m0 = blockIdx.y * 64, n0 = blockIdx.x * 64;
    int arow = tid >> 2, ak = (tid & 3) * 4;
    int brow = tid >> 4, bn = (tid & 15) * 4;
    float acc[4][4] = {};
    for (int k0 = 0; k0 < K; k0 += 16) {
        float4 av = make_float4(0.f, 0.f, 0.f, 0.f);
        if (m0 + arow < M) av = *(const float4*)(A + (long)(m0 + arow) * K + k0 + ak);
        As[ak + 0][arow] = av.x; As[ak + 1][arow] = av.y;
        As[ak + 2][arow] = av.z; As[ak + 3][arow] = av.w;
        *(float4*)&Bs[brow][bn] = *(const float4*)(Bm + (long)(k0 + brow) * N + n0 + bn);
        __syncthreads();
        mma_tile(As, Bs, acc, ty, tx);
        __syncthreads();
    }
    epilogue(Out, M, N, m0, n0, ty, tx, acc, epi, bias, gsc, resb);
}

// ---------------- softmax over 256 with split-K reduction ----------------
__global__ void softmax256(const float* __restrict__ part, float* __restrict__ out) {
    __shared__ float sh[8];
    int tid = threadIdx.x;
    int row = blockIdx.x;                 // b*256 + i
    int b = row >> 8, i = row & 255;
    float v = 0.f;
    #pragma unroll
    for (int ks = 0; ks < 8; ks++)
        v += part[((long)(b * 8 + ks) * C_ + i) * C_ + tid];
    float m = warpMax(v);
    if ((tid & 31) == 0) sh[tid >> 5] = m;
    __syncthreads();
    m = sh[tid & 7];
    #pragma unroll
    for (int o = 4; o; o >>= 1) m = fmaxf(m, __shfl_xor_sync(0xffffffffu, m, o));
    __syncthreads();
    float e = __expf(v - m);
    float s = warpSum(e);
    if ((tid & 31) == 0) sh[tid >> 5] = s;
    __syncthreads();
    s = sh[tid & 7];
    #pragma unroll
    for (int o = 4; o; o >>= 1) s += __shfl_xor_sync(0xffffffffu, s, o);
    out[(long)row * 256 + tid] = e / s;
}

// ---------------- BN (train-mode batch stats) + ReLU ----------------
__global__ void bnstats(const float* __restrict__ y, float* __restrict__ meanp,
                        float* __restrict__ rstdp) {
    __shared__ float sh[16];
    int o = blockIdx.x, tid = threadIdx.x;
    float s = 0.f, sq = 0.f;
    for (int b = 0; b < 4; b++) {
        const float4* p = (const float4*)(y + ((size_t)b * 256 + o) * 4096);
        for (int i = tid; i < 1024; i += 256) {
            float4 v = p[i];
            s += v.x + v.y + v.z + v.w;
            sq += v.x * v.x + v.y * v.y + v.z * v.z + v.w * v.w;
        }
    }
    s = warpSum(s); sq = warpSum(sq);
    if ((tid & 31) == 0) { sh[tid >> 5] = s; sh[8 + (tid >> 5)] = sq; }
    __syncthreads();
    if (tid == 0) {
        float S = 0.f, SQ = 0.f;
        for (int i = 0; i < 8; i++) { S += sh[i]; SQ += sh[8 + i]; }
        float mean = S / 16384.f;
        float var = SQ / 16384.f - mean * mean;
        meanp[o] = mean;
        rstdp[o] = rsqrtf(var + 1e-5f);
    }
}

__global__ void bnapply(const float* __restrict__ y, const float* __restrict__ gam,
                        const float* __restrict__ bet, const float* __restrict__ meanp,
                        const float* __restrict__ rstdp, float* __restrict__ out) {
    size_t i = (size_t)blockIdx.x * 256 + threadIdx.x;  // float4 index
    int o = (int)((i >> 10) & 255);
    float mu = meanp[o], rs = rstdp[o], g = gam[o], be = bet[o];
    float4 v = ((const float4*)y)[i];
    float4 r;
    r.x = fmaxf(0.f, fmaf((v.x - mu) * rs, g, be));
    r.y = fmaxf(0.f, fmaf((v.y - mu) * rs, g, be));
    r.z = fmaxf(0.f, fmaf((v.z - mu) * rs, g, be));
    r.w = fmaxf(0.f, fmaf((v.w - mu) * rs, g, be));
    ((float4*)out)[i] = r;
}

// ---------------- launcher ----------------
extern "C" void kernel_launch(void* const* d_in, const int* in_sizes, int n_in,
                              void* d_out, int out_size) {
    const float* x   = (const float*)d_in[0];
    const float* wq  = (const float*)d_in[1];
    const float* bq  = (const float*)d_in[2];
    const float* wk  = (const float*)d_in[3];
    const float* bk  = (const float*)d_in[4];
    const float* wv  = (const float*)d_in[5];
    const float* bv  = (const float*)d_in[6];
    const float* gpa = (const float*)d_in[7];
    const float* gca = (const float*)d_in[8];
    const float* wf  = (const float*)d_in[9];
    const float* bng = (const float*)d_in[10];
    const float* bnb = (const float*)d_in[11];
    float* out = (float*)d_out;

    float *q, *k, *v, *cat, *cattn, *cattn_part, *y, *mean, *rstd;
    __nv_bfloat16* attn;
    cudaGetSymbolAddress((void**)&q, g_q);
    cudaGetSymbolAddress((void**)&k, g_k);
    cudaGetSymbolAddress((void**)&v, g_v);
    cudaGetSymbolAddress((void**)&attn, g_attn);
    cudaGetSymbolAddress((void**)&cat, g_cat);
    cudaGetSymbolAddress((void**)&cattn, g_cattn);
    cudaGetSymbolAddress((void**)&cattn_part, g_cattn_part);
    cudaGetSymbolAddress((void**)&y, g_y);
    cudaGetSymbolAddress((void**)&mean, g_mean);
    cudaGetSymbolAddress((void**)&rstd, g_rstd);

    cudaFuncSetAttribute(pa_mma, cudaFuncAttributeMaxDynamicSharedMemorySize,
                         PA_SMEM_BYTES);
    cudaFuncSetAttribute(gemm_nn_mma, cudaFuncAttributeMaxDynamicSharedMemorySize,
                         NN_SMEM_BYTES);
    cudaFuncSetAttribute(xxT_mma, cudaFuncAttributeMaxDynamicSharedMemorySize,
                         XT_SMEM_BYTES);
    cudaFuncSetAttribute(conv_mma, cudaFuncAttributeMaxDynamicSharedMemorySize,
                         CV_SMEM_BYTES);

    dim3 blk(256);
    long sx = (long)C_ * N_;
    long sqk = (long)CQ_ * N_;
    long scat = (long)2 * C_ * N_;

    // q, k projections (small; fp32 SIMT)
    gemm_nn_k<<<dim3(64, 1, 4), blk>>>(wq, x, q, CQ_, N_, C_, 0, bq, nullptr, nullptr,
                                       0, sx, sqk, 0);
    gemm_nn_k<<<dim3(64, 1, 4), blk>>>(wk, x, k, CQ_, N_, C_, 0, bk, nullptr, nullptr,
                                       0, sx, sqk, 0);
    // v projection on tensor cores
    gemm_nn_mma<<<dim3(32, 2, 4), blk, NN_SMEM_BYTES>>>(
        wv, x, v, C_, 0, bv, nullptr, nullptr, 0, sx, sx, 0);
    // logits + exp -> bf16 attn (no separate softmax pass)
    qk_exp<<<dim3(32, 32, 4), blk>>>(q, k, attn);
    // PA (M=256, bf16 attn read once) with fused 1/l normalization -> cat[:,0:256]
    pa_mma<<<dim3(32, 1, 4), blk, PA_SMEM_BYTES>>>(v, attn, x, gpa, cat);
    // channel attention: split-K x.xT partials, fused-reduce softmax, apply
    xxT_mma<<<dim3(2, 2, 32), blk, XT_SMEM_BYTES>>>(x, cattn_part);
    softmax256<<<B_ * C_, 256>>>(cattn_part, cattn);
    gemm_nn_mma<<<dim3(32, 2, 4), blk, NN_SMEM_BYTES>>>(
        cattn, x, cat + (size_t)C_ * N_, C_, 1, nullptr, gca, x,
        (long)C_ * C_, sx, scat, sx);
    // 3x3 conv 512->256 (implicit GEMM v2, tensor cores)
    conv_mma<<<dim3(32, 2, 4), blk, CV_SMEM_BYTES>>>(cat, wf, y);
    // BN train-mode + ReLU
    bnstats<<<256, 256>>>(y, mean, rstd);
    bnapply<<<4096, 256>>>(y, bng, bnb, mean, rstd, out);
}

// round 10
// speedup vs baseline: 2.2648x; 1.0000x over previous
#include <cuda_runtime.h>
#include <cuda_bf16.h>
#include <cstdint>

#define B_  4
#define C_  256
#define CQ_ 32
#define N_  4096
#define HW_ 64

// ---------------- scratch (device globals; no allocation) ----------------
__device__ float g_q[B_ * CQ_ * N_];
__device__ float g_k[B_ * CQ_ * N_];
__device__ float g_v[B_ * C_ * N_];
__device__ __nv_bfloat16 g_attn[(size_t)B_ * N_ * N_];   // exp(logits), bf16, 128 MB
__device__ float g_cat[(size_t)B_ * 2 * C_ * N_];        // [b][512][4096]
__device__ float g_cattn_part[32 * C_ * C_];             // split-K partials, 8 MB
__device__ float g_cattn[B_ * C_ * C_];
__device__ float g_y[(size_t)B_ * C_ * N_];
__device__ float g_mean[C_];
__device__ float g_rstd[C_];

// ---------------- PTX helpers (sm_80+ mma.sync / cp.async) ----------------
__device__ __forceinline__ uint32_t smem_to_u32(const void* p) {
    uint32_t a;
    asm("{ .reg .u64 t; cvta.to.shared.u64 t, %1; cvt.u32.u64 %0, t; }" : "=r"(a) : "l"(p));
    return a;
}
__device__ __forceinline__ void cp16(uint32_t dst, const void* src) {
    asm volatile("cp.async.cg.shared.global [%0], [%1], 16;" :: "r"(dst), "l"(src));
}
#define CP_COMMIT() asm volatile("cp.async.commit_group;" ::: "memory")
#define CP_WAIT(n)  asm volatile("cp.async.wait_group %0;" :: "n"(n) : "memory")

__device__ __forceinline__ uint32_t ld_tf32(const float* p) {
    uint32_t r;
    float f = *p;
    asm("cvt.rna.tf32.f32 %0, %1;" : "=r"(r) : "f"(f));
    return r;
}
__device__ __forceinline__ uint32_t bf_tf32(const __nv_bfloat16* p) {
    uint32_t r;
    float f = __bfloat162float(*p);
    asm("cvt.rna.tf32.f32 %0, %1;" : "=r"(r) : "f"(f));
    return r;
}
__device__ __forceinline__ void mma_tf32(float c[4], uint32_t a0, uint32_t a1,
                                         uint32_t a2, uint32_t a3,
                                         uint32_t b0, uint32_t b1) {
    asm volatile(
        "mma.sync.aligned.m16n8k8.row.col.f32.tf32.tf32.f32 "
        "{%0,%1,%2,%3}, {%4,%5,%6,%7}, {%8,%9}, {%0,%1,%2,%3};"
        : "+f"(c[0]), "+f"(c[1]), "+f"(c[2]), "+f"(c[3])
        : "r"(a0), "r"(a1), "r"(a2), "r"(a3), "r"(b0), "r"(b1));
}

// =================================================================
// qk_exp (tf32 mma): attn[b,i,j] = bf16( exp( sum_d q[b,d,i]*k[b,d,j] ) )
// =================================================================
__global__ void __launch_bounds__(256)
qk_exp(const float* __restrict__ qg, const float* __restrict__ kg,
       __nv_bfloat16* __restrict__ attn) {
    __shared__ float qs[32 * 132];
    __shared__ float ks[32 * 132];
    int tid = threadIdx.x, lane = tid & 31, w = tid >> 5;
    int wm = w & 3, wn = w >> 2;
    int b = blockIdx.z;
    int I0 = blockIdx.y * 128, J0 = blockIdx.x * 128;
    const float* Qg = qg + (long)b * CQ_ * N_;
    const float* Kg = kg + (long)b * CQ_ * N_;

    #pragma unroll
    for (int jj = 0; jj < 4; jj++) {
        int idx = tid + 256 * jj;           // 0..1023
        int d = idx >> 5, c4 = (idx & 31) * 4;
        *(float4*)&qs[d * 132 + c4] = *(const float4*)(Qg + (long)d * N_ + I0 + c4);
        *(float4*)&ks[d * 132 + c4] = *(const float4*)(Kg + (long)d * N_ + J0 + c4);
    }
    __syncthreads();

    float acc[2][8][4] = {};
    #pragma unroll
    for (int k8 = 0; k8 < 32; k8 += 8) {
        uint32_t a[2][4], bb[8][2];
        int d0 = k8 + (lane & 3);
        #pragma unroll
        for (int mt = 0; mt < 2; mt++) {
            int i = wm * 32 + mt * 16 + (lane >> 2);
            a[mt][0] = ld_tf32(&qs[d0 * 132 + i]);
            a[mt][1] = ld_tf32(&qs[d0 * 132 + i + 8]);
            a[mt][2] = ld_tf32(&qs[(d0 + 4) * 132 + i]);
            a[mt][3] = ld_tf32(&qs[(d0 + 4) * 132 + i + 8]);
        }
        #pragma unroll
        for (int nt = 0; nt < 8; nt++) {
            int j = wn * 64 + nt * 8 + (lane >> 2);
            bb[nt][0] = ld_tf32(&ks[d0 * 132 + j]);
            bb[nt][1] = ld_tf32(&ks[(d0 + 4) * 132 + j]);
        }
        #pragma unroll
        for (int mt = 0; mt < 2; mt++)
            #pragma unroll
            for (int nt = 0; nt < 8; nt++)
                mma_tf32(acc[mt][nt], a[mt][0], a[mt][1], a[mt][2], a[mt][3],
                         bb[nt][0], bb[nt][1]);
    }

    #pragma unroll
    for (int mt = 0; mt < 2; mt++) {
        int row = I0 + wm * 32 + mt * 16 + (lane >> 2);
        #pragma unroll
        for (int nt = 0; nt < 8; nt++) {
            int col = J0 + wn * 64 + nt * 8 + 2 * (lane & 3);
            long o = (long)b * N_ * N_ + (long)row * N_ + col;
            *(__nv_bfloat162*)(attn + o) =
                __floats2bfloat162_rn(__expf(acc[mt][nt][0]), __expf(acc[mt][nt][1]));
            *(__nv_bfloat162*)(attn + o + 8 * N_) =
                __floats2bfloat162_rn(__expf(acc[mt][nt][2]), __expf(acc[mt][nt][3]));
        }
    }
}

// =================================================================
// PA GEMM (tf32 mma, bf16 attn) with fused softmax-normalization.
// M=256: one CTA covers all channels for a 128-wide i tile.
//   cat[b,c,i] = gamma_pa*(1/l_i)*sum_j v[b,c,j]*attn[b,i,j] + x[b,c,i]
// smem: As 2x[256][36] f32, Bs 2x[128][40] bf16 (stride 40 -> conflict-free).
// =================================================================
#define PA_BS_ELE (128 * 40)                              // bf16 per buffer
#define PA_SMEM_BYTES ((2 * 256 * 36) * 4 + 2 * PA_BS_ELE * 2)   // 94208

__global__ void __launch_bounds__(256)
pa_mma(const float* __restrict__ v, const __nv_bfloat16* __restrict__ attn,
       const float* __restrict__ x, const float* __restrict__ gpa,
       float* __restrict__ cat) {
    extern __shared__ float sm[];
    float* Asm = sm;                                       // 2 x 256*36 f32
    __nv_bfloat16* Bsm = (__nv_bfloat16*)(sm + 2 * 256 * 36);  // 2 x 128*40 bf16
    __shared__ float red[256];
    int tid = threadIdx.x, lane = tid & 31, wid = tid >> 5;
    int wm = wid & 3, wn = wid >> 2;
    int b = blockIdx.z, n0 = blockIdx.x * 128;
    const float* Ag = v + (long)b * C_ * N_;
    const __nv_bfloat16* Bg = attn + (long)b * N_ * N_ + (long)n0 * N_;
    uint32_t smu_a = smem_to_u32(Asm), smu_b = smem_to_u32(Bsm);

    float c[4][8][4] = {};
    float part = 0.f;                  // row-sum strip: row=tid>>1, k=(tid&1)*16..+15
    int srow = tid >> 1, skoff = (tid & 1) * 16;

    #pragma unroll
    for (int s = 0; s < 2; s++) {
        int k0 = s * 32;
        #pragma unroll
        for (int j = 0; j < 8; j++) {            // A: 256 rows x 8 quads (f32)
            int f = tid + 256 * j;
            int r = f >> 3, q = (f & 7) * 4;
            cp16(smu_a + (s * 9216 + r * 36 + q) * 4, Ag + (long)r * N_ + k0 + q);
        }
        #pragma unroll
        for (int j = 0; j < 2; j++) {            // B: 128 rows x 4 oct (bf16)
            int f = tid + 256 * j;
            int r = f >> 2, q = (f & 3) * 8;
            cp16(smu_b + (s * PA_BS_ELE + r * 40 + q) * 2, Bg + (long)r * N_ + k0 + q);
        }
        CP_COMMIT();
    }

    for (int ch = 0; ch < 128; ch++) {
        if (ch < 126) { CP_WAIT(1); } else { CP_WAIT(0); }
        __syncthreads();
        const float* As_ = Asm + (ch & 1) * 9216;
        const __nv_bfloat16* Bs_ = Bsm + (ch & 1) * PA_BS_ELE;
        // accumulate row sums l_i from the staged attn tile
        {
            const __nv_bfloat162* bp =
                (const __nv_bfloat162*)(Bs_ + srow * 40 + skoff);
            #pragma unroll
            for (int kk = 0; kk < 8; kk++) {
                float2 f2 = __bfloat1622float2(bp[kk]);
                part += f2.x + f2.y;
            }
        }
        #pragma unroll
        for (int k8 = 0; k8 < 32; k8 += 8) {
            uint32_t a[4][4], bb[8][2];
            #pragma unroll
            for (int mt = 0; mt < 4; mt++) {
                const float* ap = As_ + (wm * 64 + mt * 16 + (lane >> 2)) * 36 + k8 + (lane & 3);
                a[mt][0] = ld_tf32(ap);
                a[mt][1] = ld_tf32(ap + 8 * 36);
                a[mt][2] = ld_tf32(ap + 4);
                a[mt][3] = ld_tf32(ap + 8 * 36 + 4);
            }
            #pragma unroll
            for (int nt = 0; nt < 8; nt++) {
                const __nv_bfloat16* bp = Bs_ + (wn * 64 + nt * 8 + (lane >> 2)) * 40
                                          + k8 + (lane & 3);
                bb[nt][0] = bf_tf32(bp);
                bb[nt][1] = bf_tf32(bp + 4);
            }
            #pragma unroll
            for (int mt = 0; mt < 4; mt++)
                #pragma unroll
                for (int nt = 0; nt < 8; nt++)
                    mma_tf32(c[mt][nt], a[mt][0], a[mt][1], a[mt][2], a[mt][3],
                             bb[nt][0], bb[nt][1]);
        }
        __syncthreads();
        if (ch + 2 < 128) {
            int s = ch & 1;
            int k0 = (ch + 2) * 32;
            #pragma unroll
            for (int j = 0; j < 8; j++) {
                int f = tid + 256 * j;
                int r = f >> 3, q = (f & 7) * 4;
                cp16(smu_a + (s * 9216 + r * 36 + q) * 4, Ag + (long)r * N_ + k0 + q);
            }
            #pragma unroll
            for (int j = 0; j < 2; j++) {
                int f = tid + 256 * j;
                int r = f >> 2, q = (f & 3) * 8;
                cp16(smu_b + (s * PA_BS_ELE + r * 40 + q) * 2, Bg + (long)r * N_ + k0 + q);
            }
            CP_COMMIT();
        }
    }

    red[tid] = part;
    __syncthreads();

    float g = gpa[0];
    #pragma unroll
    for (int nt = 0; nt < 8; nt++) {
        int cl = wn * 64 + nt * 8 + 2 * (lane & 3);
        float inv0 = 1.f / (red[2 * cl] + red[2 * cl + 1]);
        float inv1 = 1.f / (red[2 * cl + 2] + red[2 * cl + 3]);
        #pragma unroll
        for (int mt = 0; mt < 4; mt++) {
            int row = wm * 64 + mt * 16 + (lane >> 2);
            int col = n0 + cl;
            long xo = ((long)b * C_ + row) * N_ + col;
            long co = ((long)b * 2 * C_ + row) * N_ + col;
            *(float2*)(cat + co) = make_float2(
                fmaf(g, c[mt][nt][0] * inv0, x[xo]),
                fmaf(g, c[mt][nt][1] * inv1, x[xo + 1]));
            *(float2*)(cat + co + 8 * N_) = make_float2(
                fmaf(g, c[mt][nt][2] * inv0, x[xo + 8 * N_]),
                fmaf(g, c[mt][nt][3] * inv1, x[xo + 8 * N_ + 1]));
        }
    }
}

// =================================================================
// xxT_mma: split-K channel-logits partials (tf32 mma, NT):
//   part[z][i][j] = sum_{n in ks-slice} x[b,i,n] * x[b,j,n],  z = b*8+ks
// CTA 128x128, K=512 per split, BK=32, double buffer.
// =================================================================
#define XT_SMEM_BYTES ((2 * 128 * 36 * 2) * 4)   // 73728

__global__ void __launch_bounds__(256)
xxT_mma(const float* __restrict__ x, float* __restrict__ part) {
    extern __shared__ float sm[];
    float* Asm = sm;                   // 2 x 128*36
    float* Bsm = sm + 2 * 128 * 36;    // 2 x 128*36
    int tid = threadIdx.x, lane = tid & 31, wid = tid >> 5;
    int wm = wid & 3, wn = wid >> 2;
    int z = blockIdx.z, b = z >> 3, ks = z & 7;
    int m0 = blockIdx.y * 128, n0 = blockIdx.x * 128;
    const float* Ag = x + (long)b * C_ * N_ + (long)m0 * N_ + ks * 512;
    const float* Bg = x + (long)b * C_ * N_ + (long)n0 * N_ + ks * 512;
    uint32_t smu_a = smem_to_u32(Asm), smu_b = smem_to_u32(Bsm);
    float c[2][8][4] = {};

    #pragma unroll
    for (int s = 0; s < 2; s++) {
        int k0 = s * 32;
        #pragma unroll
        for (int j = 0; j < 4; j++) {
            int f = tid + 256 * j;
            int r = f >> 3, q = (f & 7) * 4;
            cp16(smu_a + (s * 4608 + r * 36 + q) * 4, Ag + (long)r * N_ + k0 + q);
            cp16(smu_b + (s * 4608 + r * 36 + q) * 4, Bg + (long)r * N_ + k0 + q);
        }
        CP_COMMIT();
    }

    for (int ch = 0; ch < 16; ch++) {
        if (ch < 14) { CP_WAIT(1); } else { CP_WAIT(0); }
        __syncthreads();
        const float* As_ = Asm + (ch & 1) * 4608;
        const float* Bs_ = Bsm + (ch & 1) * 4608;
        #pragma unroll
        for (int k8 = 0; k8 < 32; k8 += 8) {
            uint32_t a[2][4], bb[8][2];
            #pragma unroll
            for (int mt = 0; mt < 2; mt++) {
                const float* ap = As_ + (wm * 32 + mt * 16 + (lane >> 2)) * 36 + k8 + (lane & 3);
                a[mt][0] = ld_tf32(ap);
                a[mt][1] = ld_tf32(ap + 8 * 36);
                a[mt][2] = ld_tf32(ap + 4);
                a[mt][3] = ld_tf32(ap + 8 * 36 + 4);
            }
            #pragma unroll
            for (int nt = 0; nt < 8; nt++) {
                const float* bp = Bs_ + (wn * 64 + nt * 8 + (lane >> 2)) * 36 + k8 + (lane & 3);
                bb[nt][0] = ld_tf32(bp);
                bb[nt][1] = ld_tf32(bp + 4);
            }
            #pragma unroll
            for (int mt = 0; mt < 2; mt++)
                #pragma unroll
                for (int nt = 0; nt < 8; nt++)
                    mma_tf32(c[mt][nt], a[mt][0], a[mt][1], a[mt][2], a[mt][3],
                             bb[nt][0], bb[nt][1]);
        }
        __syncthreads();
        if (ch + 2 < 16) {
            int s = ch & 1;
            int k0 = (ch + 2) * 32;
            #pragma unroll
            for (int j = 0; j < 4; j++) {
                int f = tid + 256 * j;
                int r = f >> 3, q = (f & 7) * 4;
                cp16(smu_a + (s * 4608 + r * 36 + q) * 4, Ag + (long)r * N_ + k0 + q);
                cp16(smu_b + (s * 4608 + r * 36 + q) * 4, Bg + (long)r * N_ + k0 + q);
            }
            CP_COMMIT();
        }
    }

    float* Ob = part + (long)z * C_ * C_;
    #pragma unroll
    for (int mt = 0; mt < 2; mt++) {
        int row = m0 + wm * 32 + mt * 16 + (lane >> 2);
        #pragma unroll
        for (int nt = 0; nt < 8; nt++) {
            int col = n0 + wn * 64 + nt * 8 + 2 * (lane & 3);
            long o = (long)row * C_ + col;
            *(float2*)(Ob + o) = make_float2(c[mt][nt][0], c[mt][nt][1]);
            *(float2*)(Ob + o + 8 * C_) = make_float2(c[mt][nt][2], c[mt][nt][3]);
        }
    }
}

// =================================================================
// NN-GEMM (tf32 mma): Out[m][n] = sum_k A[m][k] * B[k][n]
// =================================================================
#define NN_SMEM_BYTES ((2 * 128 * 36 + 2 * 32 * 132) * 4)   // 70656

__global__ void __launch_bounds__(256)
gemm_nn_mma(const float* __restrict__ A, const float* __restrict__ B,
            float* __restrict__ Out, int K, int epi,
            const float* __restrict__ bias, const float* __restrict__ gsc,
            const float* __restrict__ res,
            long sA, long sB, long sO, long sR) {
    extern __shared__ float sm[];
    float* As = sm;                      // 2 x [128][36]
    float* Bs = sm + 2 * 128 * 36;       // 2 x [32][132]
    int tid = threadIdx.x, lane = tid & 31, w = tid >> 5;
    int wm = w & 3, wn = w >> 2;
    int b = blockIdx.z, m0 = blockIdx.y * 128, n0 = blockIdx.x * 128;
    const float* Ag = A + sA * b + (long)m0 * K;
    const float* Bg = B + sB * b + n0;
    uint32_t smu_a = smem_to_u32(As), smu_b = smem_to_u32(Bs);
    float acc[2][8][4] = {};
    int nchunks = K / 32;

    #pragma unroll
    for (int s = 0; s < 2; s++) {
        #pragma unroll
        for (int jj = 0; jj < 4; jj++) {
            int idx = tid + 256 * jj;
            int r = idx >> 3, kq = (idx & 7) * 4;
            cp16(smu_a + (s * 4608 + r * 36 + kq) * 4, Ag + (long)r * K + s * 32 + kq);
            int kk = idx >> 5, nq = (idx & 31) * 4;
            cp16(smu_b + (s * 4224 + kk * 132 + nq) * 4, Bg + (long)(s * 32 + kk) * N_ + nq);
        }
        CP_COMMIT();
    }

    for (int ch = 0; ch < nchunks; ch++) {
        if (ch < nchunks - 2) { CP_WAIT(1); } else { CP_WAIT(0); }
        __syncthreads();
        const float* As_ = As + (ch & 1) * 4608;
        const float* Bs_ = Bs + (ch & 1) * 4224;
        #pragma unroll
        for (int k8 = 0; k8 < 32; k8 += 8) {
            uint32_t a[2][4], bb[8][2];
            #pragma unroll
            for (int mt = 0; mt < 2; mt++) {
                const float* ap = As_ + (wm * 32 + mt * 16 + (lane >> 2)) * 36 + k8 + (lane & 3);
                a[mt][0] = ld_tf32(ap);
                a[mt][1] = ld_tf32(ap + 8 * 36);
                a[mt][2] = ld_tf32(ap + 4);
                a[mt][3] = ld_tf32(ap + 8 * 36 + 4);
            }
            #pragma unroll
            for (int nt = 0; nt < 8; nt++) {
                const float* bp = Bs_ + (k8 + (lane & 3)) * 132 + wn * 64 + nt * 8 + (lane >> 2);
                bb[nt][0] = ld_tf32(bp);
                bb[nt][1] = ld_tf32(bp + 4 * 132);
            }
            #pragma unroll
            for (int mt = 0; mt < 2; mt++)
                #pragma unroll
                for (int nt = 0; nt < 8; nt++)
                    mma_tf32(acc[mt][nt], a[mt][0], a[mt][1], a[mt][2], a[mt][3],
                             bb[nt][0], bb[nt][1]);
        }
        __syncthreads();
        if (ch + 2 < nchunks) {
            int s = ch & 1;
            #pragma unroll
            for (int jj = 0; jj < 4; jj++) {
                int idx = tid + 256 * jj;
                int r = idx >> 3, kq = (idx & 7) * 4;
                cp16(smu_a + (s * 4608 + r * 36 + kq) * 4,
                     Ag + (long)r * K + (ch + 2) * 32 + kq);
                int kk = idx >> 5, nq = (idx & 31) * 4;
                cp16(smu_b + (s * 4224 + kk * 132 + nq) * 4,
                     Bg + (long)((ch + 2) * 32 + kk) * N_ + nq);
            }
            CP_COMMIT();
        }
    }

    float g = gsc ? *gsc : 0.f;
    const float* resb = res ? res + sR * b : nullptr;
    float* Ob = Out + sO * b;
    #pragma unroll
    for (int mt = 0; mt < 2; mt++) {
        int row = m0 + wm * 32 + mt * 16 + (lane >> 2);
        #pragma unroll
        for (int nt = 0; nt < 8; nt++) {
            int col = n0 + wn * 64 + nt * 8 + 2 * (lane & 3);
            long o = (long)row * N_ + col;
            if (epi == 0) {
                float bv = bias[row], bv8 = bias[row + 8];
                *(float2*)(Ob + o) = make_float2(acc[mt][nt][0] + bv, acc[mt][nt][1] + bv);
                *(float2*)(Ob + o + 8 * N_) =
                    make_float2(acc[mt][nt][2] + bv8, acc[mt][nt][3] + bv8);
            } else {
                *(float2*)(Ob + o) = make_float2(
                    fmaf(g, acc[mt][nt][0], resb[o]), fmaf(g, acc[mt][nt][1], resb[o + 1]));
                *(float2*)(Ob + o + 8 * N_) = make_float2(
                    fmaf(g, acc[mt][nt][2], resb[o + 8 * N_]),
                    fmaf(g, acc[mt][nt][3], resb[o + 8 * N_ + 1]));
            }
        }
    }
}

// =================================================================
// 3x3 conv 512 -> 256, implicit GEMM v2 (tf32 mma)
// =================================================================
#define CV_AS_FLOATS  (128 * 76)         // 9728 per buffer
#define CV_PT_FLOATS  (8 * 296)          // 2368 per buffer
#define CV_SMEM_BYTES ((2 * CV_AS_FLOATS + 2 * CV_PT_FLOATS) * 4)   // 96768

__global__ void __launch_bounds__(256)
conv_mma(const float* __restrict__ cat, const float* __restrict__ wf,
         float* __restrict__ y) {
    extern __shared__ float sm[];
    float* Asm = sm;                         // 2 x [128][76]
    float* Pt = sm + 2 * CV_AS_FLOATS;       // 2 x [8][296]
    int tid = threadIdx.x, lane = tid & 31, wid = tid >> 5;
    int wm = wid & 3, wn = wid >> 2;
    int b = blockIdx.z, o0 = blockIdx.y * 128, p0 = blockIdx.x * 128;
    int h0 = blockIdx.x * 2;
    uint32_t smu_a = smem_to_u32(Asm), smu_p = smem_to_u32(Pt);

    for (int i = tid; i < 2 * CV_PT_FLOATS; i += 256) Pt[i] = 0.f;
    __syncthreads();

    float c[2][8][4] = {};

    #pragma unroll
    for (int s = 0; s < 2; s++) {
        #pragma unroll
        for (int j = 0; j < 9; j++) {
            int f = tid + 256 * j;
            int r = f / 18, q = (f % 18) * 4;
            cp16(smu_a + (s * CV_AS_FLOATS + r * 76 + q) * 4,
                 wf + (long)(o0 + r) * 4608 + s * 72 + q);
        }
        #pragma unroll
        for (int j = 0; j < 2; j++) {
            int f = tid + 256 * j;
            int ci = f >> 6, rq = (f >> 4) & 3, q = (f & 15) * 4;
            int h = h0 - 1 + rq;
            if (h >= 0 && h < 64)
                cp16(smu_p + (s * CV_PT_FLOATS + ci * 296 + rq * 72 + 4 + q) * 4,
                     cat + ((long)b * 512 + s * 8 + ci) * 4096 + h * 64 + q);
        }
        CP_COMMIT();
    }

    for (int chunk = 0; chunk < 64; chunk++) {
        if (chunk < 62) { CP_WAIT(1); } else { CP_WAIT(0); }
        __syncthreads();
        const float* As_ = Asm + (chunk & 1) * CV_AS_FLOATS;
        const float* Pt_ = Pt + (chunk & 1) * CV_PT_FLOATS;

        #pragma unroll
        for (int pos = 0; pos < 9; pos++) {
            const int kh = pos / 3, kw = pos % 3;
            uint32_t a[2][4], bb[8][2];
            #pragma unroll
            for (int mt = 0; mt < 2; mt++) {
                const float* ap = As_ + (wm * 32 + mt * 16 + (lane >> 2)) * 76
                                  + (lane & 3) * 9 + pos;
                a[mt][0] = ld_tf32(ap);
                a[mt][1] = ld_tf32(ap + 8 * 76);
                a[mt][2] = ld_tf32(ap + 36);          // ci + 4
                a[mt][3] = ld_tf32(ap + 8 * 76 + 36);
            }
            {
                int nbase = wn * 64 + (lane >> 2);
                int hh = nbase >> 6;
                const float* pb = Pt_ + (lane & 3) * 296 + (hh + kh) * 72;
                #pragma unroll
                for (int nt = 0; nt < 8; nt++) {
                    int wpos = ((nbase + nt * 8) & 63) + kw + 3;
                    bb[nt][0] = ld_tf32(pb + wpos);
                    bb[nt][1] = ld_tf32(pb + 4 * 296 + wpos);
                }
            }
            #pragma unroll
            for (int mt = 0; mt < 2; mt++)
                #pragma unroll
                for (int nt = 0; nt < 8; nt++)
                    mma_tf32(c[mt][nt], a[mt][0], a[mt][1], a[mt][2], a[mt][3],
                             bb[nt][0], bb[nt][1]);
        }
        __syncthreads();
        if (chunk + 2 < 64) {
            int s = chunk & 1;
            #pragma unroll
            for (int j = 0; j < 9; j++) {
                int f = tid + 256 * j;
                int r = f / 18, q = (f % 18) * 4;
                cp16(smu_a + (s * CV_AS_FLOATS + r * 76 + q) * 4,
                     wf + (long)(o0 + r) * 4608 + (chunk + 2) * 72 + q);
            }
            #pragma unroll
            for (int j = 0; j < 2; j++) {
                int f = tid + 256 * j;
                int ci = f >> 6, rq = (f >> 4) & 3, q = (f & 15) * 4;
                int h = h0 - 1 + rq;
                if (h >= 0 && h < 64)
                    cp16(smu_p + (s * CV_PT_FLOATS + ci * 296 + rq * 72 + 4 + q) * 4,
                         cat + ((long)b * 512 + (chunk + 2) * 8 + ci) * 4096 + h * 64 + q);
            }
            CP_COMMIT();
        }
    }

    #pragma unroll
    for (int mt = 0; mt < 2; mt++) {
        #pragma unroll
        for (int nt = 0; nt < 8; nt++) {
            int row = o0 + wm * 32 + mt * 16 + (lane >> 2);
            int col = p0 + wn * 64 + nt * 8 + 2 * (lane & 3);
            long yo = ((long)b * 256 + row) * 4096 + col;
            *(float2*)(y + yo) = make_float2(c[mt][nt][0], c[mt][nt][1]);
            *(float2*)(y + yo + 8 * 4096) = make_float2(c[mt][nt][2], c[mt][nt][3]);
        }
    }
}

// ---------------- helpers ----------------
__device__ __forceinline__ float warpMax(float v) {
    #pragma unroll
    for (int o = 16; o; o >>= 1) v = fmaxf(v, __shfl_xor_sync(0xffffffffu, v, o));
    return v;
}
__device__ __forceinline__ float warpSum(float v) {
    #pragma unroll
    for (int o = 16; o; o >>= 1) v += __shfl_xor_sync(0xffffffffu, v, o);
    return v;
}

__device__ __forceinline__ void mma_tile(const float (*As)[64], const float (*Bs)[64],
                                         float acc[4][4], int ty, int tx) {
    #pragma unroll
    for (int k = 0; k < 16; k++) {
        float4 a = *(const float4*)&As[k][ty * 4];
        float4 b = *(const float4*)&Bs[k][tx * 4];
        float ar[4] = {a.x, a.y, a.z, a.w};
        float br[4] = {b.x, b.y, b.z, b.w};
        #pragma unroll
        for (int i = 0; i < 4; i++)
            #pragma unroll
            for (int j = 0; j < 4; j++)
                acc[i][j] = fmaf(ar[i], br[j], acc[i][j]);
    }
}

__device__ __forceinline__ void epilogue(float* Out, int M, int N, int m0, int n0,
                                         int ty, int tx, float acc[4][4], int epi,
                                         const float* bias, const float* gsc,
                                         const float* res) {
    float g = gsc ? *gsc : 0.f;
    #pragma unroll
    for (int i = 0; i < 4; i++) {
        int m = m0 + ty * 4 + i;
        if (m < M) {
            long off = (long)m * N + n0 + tx * 4;
            float4 o;
            if (epi == 0) {
                float bv = bias[m];
                o = make_float4(acc[i][0] + bv, acc[i][1] + bv, acc[i][2] + bv, acc[i][3] + bv);
            } else if (epi == 1) {
                float4 r = *(const float4*)(res + off);
                o = make_float4(fmaf(g, acc[i][0], r.x), fmaf(g, acc[i][1], r.y),
                                fmaf(g, acc[i][2], r.z), fmaf(g, acc[i][3], r.w));
            } else {
                o = make_float4(acc[i][0], acc[i][1], acc[i][2], acc[i][3]);
            }
            *(float4*)(Out + off) = o;
        }
    }
}

// ---------------- fp32 SIMT GEMM (q/k projections) ----------------
__global__ void gemm_nn_k(const float* __restrict__ A, const float* __restrict__ Bm,
                          float* __restrict__ Out, int M, int N, int K, int epi,
                          const float* __restrict__ bias, const float* __restrict__ gsc,
                          const float* __restrict__ res,
                          long sA, long sB, long sO, long sR) {
    int b = blockIdx.z;
    A += sA * b; Bm += sB * b; Out += sO * b;
    const float* resb = res ? res + sR * b : nullptr;
    __shared__ float As[16][64];
    __shared__ float Bs[16][64];
    int tid = threadIdx.x;
    int tx = tid & 15, ty = tid >> 4;
    int m0 = blockIdx.y * 64, n0 = blockIdx.x * 64;
    int arow = tid >> 2, ak = (tid & 3) * 4;
    int brow = tid >> 4, bn = (tid & 15) * 4;
    float acc[4][4] = {};
    for (int k0 = 0; k0 < K; k0 += 16) {
        float4 av = make_float4(0.f, 0.f, 0.f, 0.f);
        if (m0 + arow < M) av = *(const float4*)(A + (long)(m0 + arow) * K + k0 + ak);
        As[ak + 0][arow] = av.x; As[ak + 1][arow] = av.y;
        As[ak + 2][arow] = av.z; As[ak + 3][arow] = av.w;
        *(float4*)&Bs[brow][bn] = *(const float4*)(Bm + (long)(k0 + brow) * N + n0 + bn);
        __syncthreads();
        mma_tile(As, Bs, acc, ty, tx);
        __syncthreads();
    }
    epilogue(Out, M, N, m0, n0, ty, tx, acc, epi, bias, gsc, resb);
}

// ---------------- softmax over 256 with split-K reduction ----------------
__global__ void softmax256(const float* __restrict__ part, float* __restrict__ out) {
    __shared__ float sh[8];
    int tid = threadIdx.x;
    int row = blockIdx.x;                 // b*256 + i
    int b = row >> 8, i = row & 255;
    float v = 0.f;
    #pragma unroll
    for (int ks = 0; ks < 8; ks++)
        v += part[((long)(b * 8 + ks) * C_ + i) * C_ + tid];
    float m = warpMax(v);
    if ((tid & 31) == 0) sh[tid >> 5] = m;
    __syncthreads();
    m = sh[tid & 7];
    #pragma unroll
    for (int o = 4; o; o >>= 1) m = fmaxf(m, __shfl_xor_sync(0xffffffffu, m, o));
    __syncthreads();
    float e = __expf(v - m);
    float s = warpSum(e);
    if ((tid & 31) == 0) sh[tid >> 5] = s;
    __syncthreads();
    s = sh[tid & 7];
    #pragma unroll
    for (int o = 4; o; o >>= 1) s += __shfl_xor_sync(0xffffffffu, s, o);
    out[(long)row * 256 + tid] = e / s;
}

// ---------------- BN (train-mode batch stats) + ReLU ----------------
__global__ void bnstats(const float* __restrict__ y, float* __restrict__ meanp,
                        float* __restrict__ rstdp) {
    __shared__ float sh[16];
    int o = blockIdx.x, tid = threadIdx.x;
    float s = 0.f, sq = 0.f;
    for (int b = 0; b < 4; b++) {
        const float4* p = (const float4*)(y + ((size_t)b * 256 + o) * 4096);
        for (int i = tid; i < 1024; i += 256) {
            float4 v = p[i];
            s += v.x + v.y + v.z + v.w;
            sq += v.x * v.x + v.y * v.y + v.z * v.z + v.w * v.w;
        }
    }
    s = warpSum(s); sq = warpSum(sq);
    if ((tid & 31) == 0) { sh[tid >> 5] = s; sh[8 + (tid >> 5)] = sq; }
    __syncthreads();
    if (tid == 0) {
        float S = 0.f, SQ = 0.f;
        for (int i = 0; i < 8; i++) { S += sh[i]; SQ += sh[8 + i]; }
        float mean = S / 16384.f;
        float var = SQ / 16384.f - mean * mean;
        meanp[o] = mean;
        rstdp[o] = rsqrtf(var + 1e-5f);
    }
}

__global__ void bnapply(const float* __restrict__ y, const float* __restrict__ gam,
                        const float* __restrict__ bet, const float* __restrict__ meanp,
                        const float* __restrict__ rstdp, float* __restrict__ out) {
    size_t i = (size_t)blockIdx.x * 256 + threadIdx.x;  // float4 index
    int o = (int)((i >> 10) & 255);
    float mu = meanp[o], rs = rstdp[o], g = gam[o], be = bet[o];
    float4 v = ((const float4*)y)[i];
    float4 r;
    r.x = fmaxf(0.f, fmaf((v.x - mu) * rs, g, be));
    r.y = fmaxf(0.f, fmaf((v.y - mu) * rs, g, be));
    r.z = fmaxf(0.f, fmaf((v.z - mu) * rs, g, be));
    r.w = fmaxf(0.f, fmaf((v.w - mu) * rs, g, be));
    ((float4*)out)[i] = r;
}

// ---------------- launcher ----------------
extern "C" void kernel_launch(void* const* d_in, const int* in_sizes, int n_in,
                              void* d_out, int out_size) {
    const float* x   = (const float*)d_in[0];
    const float* wq  = (const float*)d_in[1];
    const float* bq  = (const float*)d_in[2];
    const float* wk  = (const float*)d_in[3];
    const float* bk  = (const float*)d_in[4];
    const float* wv  = (const float*)d_in[5];
    const float* bv  = (const float*)d_in[6];
    const float* gpa = (const float*)d_in[7];
    const float* gca = (const float*)d_in[8];
    const float* wf  = (const float*)d_in[9];
    const float* bng = (const float*)d_in[10];
    const float* bnb = (const float*)d_in[11];
    float* out = (float*)d_out;

    float *q, *k, *v, *cat, *cattn, *cattn_part, *y, *mean, *rstd;
    __nv_bfloat16* attn;
    cudaGetSymbolAddress((void**)&q, g_q);
    cudaGetSymbolAddress((void**)&k, g_k);
    cudaGetSymbolAddress((void**)&v, g_v);
    cudaGetSymbolAddress((void**)&attn, g_attn);
    cudaGetSymbolAddress((void**)&cat, g_cat);
    cudaGetSymbolAddress((void**)&cattn, g_cattn);
    cudaGetSymbolAddress((void**)&cattn_part, g_cattn_part);
    cudaGetSymbolAddress((void**)&y, g_y);
    cudaGetSymbolAddress((void**)&mean, g_mean);
    cudaGetSymbolAddress((void**)&rstd, g_rstd);

    cudaFuncSetAttribute(pa_mma, cudaFuncAttributeMaxDynamicSharedMemorySize,
                         PA_SMEM_BYTES);
    cudaFuncSetAttribute(gemm_nn_mma, cudaFuncAttributeMaxDynamicSharedMemorySize,
                         NN_SMEM_BYTES);
    cudaFuncSetAttribute(xxT_mma, cudaFuncAttributeMaxDynamicSharedMemorySize,
                         XT_SMEM_BYTES);
    cudaFuncSetAttribute(conv_mma, cudaFuncAttributeMaxDynamicSharedMemorySize,
                         CV_SMEM_BYTES);

    dim3 blk(256);
    long sx = (long)C_ * N_;
    long sqk = (long)CQ_ * N_;
    long scat = (long)2 * C_ * N_;

    // q, k projections (small; fp32 SIMT)
    gemm_nn_k<<<dim3(64, 1, 4), blk>>>(wq, x, q, CQ_, N_, C_, 0, bq, nullptr, nullptr,
                                       0, sx, sqk, 0);
    gemm_nn_k<<<dim3(64, 1, 4), blk>>>(wk, x, k, CQ_, N_, C_, 0, bk, nullptr, nullptr,
                                       0, sx, sqk, 0);
    // v projection on tensor cores
    gemm_nn_mma<<<dim3(32, 2, 4), blk, NN_SMEM_BYTES>>>(
        wv, x, v, C_, 0, bv, nullptr, nullptr, 0, sx, sx, 0);
    // logits + exp -> bf16 attn (no separate softmax pass)
    qk_exp<<<dim3(32, 32, 4), blk>>>(q, k, attn);
    // PA (M=256, bf16 attn read once) with fused 1/l normalization -> cat[:,0:256]
    pa_mma<<<dim3(32, 1, 4), blk, PA_SMEM_BYTES>>>(v, attn, x, gpa, cat);
    // channel attention: split-K x.xT partials, fused-reduce softmax, apply
    xxT_mma<<<dim3(2, 2, 32), blk, XT_SMEM_BYTES>>>(x, cattn_part);
    softmax256<<<B_ * C_, 256>>>(cattn_part, cattn);
    gemm_nn_mma<<<dim3(32, 2, 4), blk, NN_SMEM_BYTES>>>(
        cattn, x, cat + (size_t)C_ * N_, C_, 1, nullptr, gca, x,
        (long)C_ * C_, sx, scat, sx);
    // 3x3 conv 512->256 (implicit GEMM v2, tensor cores)
    conv_mma<<<dim3(32, 2, 4), blk, CV_SMEM_BYTES>>>(cat, wf, y);
    // BN train-mode + ReLU
    bnstats<<<256, 256>>>(y, mean, rstd);
    bnapply<<<4096, 256>>>(y, bng, bnb, mean, rstd, out);
}

// round 11
// speedup vs baseline: 2.6784x; 1.1826x over previous
#include <cuda_runtime.h>
#include <cstdint>

#define B_  4
#define C_  256
#define CQ_ 32
#define N_  4096
#define HW_ 64

// ---------------- scratch (device globals; no allocation) ----------------
__device__ float g_q[B_ * CQ_ * N_];
__device__ float g_k[B_ * CQ_ * N_];
__device__ float g_v[B_ * C_ * N_];
__device__ float g_cat[(size_t)B_ * 2 * C_ * N_];        // [b][512][4096]
__device__ float g_cattn_part[32 * C_ * C_];             // split-K partials
__device__ float g_cattn[B_ * C_ * C_];
__device__ float g_y[(size_t)B_ * C_ * N_];
__device__ float g_mean[C_];
__device__ float g_rstd[C_];

// ---------------- PTX helpers (sm_80+ mma.sync / cp.async) ----------------
__device__ __forceinline__ uint32_t smem_to_u32(const void* p) {
    uint32_t a;
    asm("{ .reg .u64 t; cvta.to.shared.u64 t, %1; cvt.u32.u64 %0, t; }" : "=r"(a) : "l"(p));
    return a;
}
__device__ __forceinline__ void cp16(uint32_t dst, const void* src) {
    asm volatile("cp.async.cg.shared.global [%0], [%1], 16;" :: "r"(dst), "l"(src));
}
#define CP_COMMIT() asm volatile("cp.async.commit_group;" ::: "memory")
#define CP_WAIT(n)  asm volatile("cp.async.wait_group %0;" :: "n"(n) : "memory")

__device__ __forceinline__ uint32_t ld_tf32(const float* p) {
    uint32_t r;
    float f = *p;
    asm("cvt.rna.tf32.f32 %0, %1;" : "=r"(r) : "f"(f));
    return r;
}
__device__ __forceinline__ void mma_tf32(float c[4], uint32_t a0, uint32_t a1,
                                         uint32_t a2, uint32_t a3,
                                         uint32_t b0, uint32_t b1) {
    asm volatile(
        "mma.sync.aligned.m16n8k8.row.col.f32.tf32.tf32.f32 "
        "{%0,%1,%2,%3}, {%4,%5,%6,%7}, {%8,%9}, {%0,%1,%2,%3};"
        : "+f"(c[0]), "+f"(c[1]), "+f"(c[2]), "+f"(c[3])
        : "r"(a0), "r"(a1), "r"(a2), "r"(a3), "r"(b0), "r"(b1));
}

// =================================================================
// pa_flash: fused attention (logits + exp + PV + 1/l normalization).
//   cat[b,c,i] = gamma_pa*(1/l_i)*sum_j v[b,c,j]*exp(q_i.k_j) + x[b,c,i]
// CTA: i-tile 128 (grid.x), all 256 channels, batch (grid.z).
// Per 32-j chunk: QK mma (q frags in regs, k tile staged 32x36),
// exp -> Ps[128][36] smem + reg row-sums, PV mma (v staged 2x[256][36]).
// No max-subtraction: |s| <= ~40, exp and l fit fp32 (validated R6-R10).
// =================================================================
#define PF_AS  (256 * 36)          // v tile floats per stage
#define PF_KS  (32 * 36)           // k tile floats per stage
#define PF_PS  (128 * 36)          // P tile floats
#define PF_SMEM_BYTES ((2 * PF_AS + 2 * PF_KS + PF_PS) * 4)   // 101376

__global__ void __launch_bounds__(256, 1)
pa_flash(const float* __restrict__ qg, const float* __restrict__ kg,
         const float* __restrict__ v, const float* __restrict__ x,
         const float* __restrict__ gpa, float* __restrict__ cat) {
    extern __shared__ float sm[];
    float* Asm = sm;                       // 2 x [256][36]  (v)
    float* Ksm = sm + 2 * PF_AS;           // 2 x [32][36]   (k)
    float* Ps  = sm + 2 * PF_AS + 2 * PF_KS;   // [128][36]  (exp(s))
    __shared__ float red[128];
    int tid = threadIdx.x, lane = tid & 31, w = tid >> 5;
    int wm = w & 3, wn = w >> 2;
    int b = blockIdx.z, I0 = blockIdx.x * 128;
    const float* Qg = qg + (long)b * CQ_ * N_;
    const float* Kg = kg + (long)b * CQ_ * N_;
    const float* Ag = v + (long)b * C_ * N_;
    uint32_t smu_a = smem_to_u32(Asm), smu_k = smem_to_u32(Ksm);

    // loop-invariant q fragments: A[m=i][k=d], warp w owns i rows w*16..+16
    uint32_t aq[4][4];
    {
        int i0 = I0 + w * 16 + (lane >> 2);
        #pragma unroll
        for (int k8 = 0; k8 < 4; k8++) {
            int d0 = k8 * 8 + (lane & 3);
            const float* qp = Qg + (long)d0 * N_ + i0;
            aq[k8][0] = ld_tf32(qp);
            aq[k8][1] = ld_tf32(qp + 8);
            aq[k8][2] = ld_tf32(qp + 4 * N_);
            aq[k8][3] = ld_tf32(qp + 4 * N_ + 8);
        }
    }

    float c[4][8][4] = {};
    float lsum0 = 0.f, lsum1 = 0.f;

    // prologue: stage chunks 0,1 (v rows + k tile)
    #pragma unroll
    for (int s = 0; s < 2; s++) {
        int j0 = s * 32;
        #pragma unroll
        for (int j = 0; j < 8; j++) {
            int f = tid + 256 * j;
            int r = f >> 3, q = (f & 7) * 4;
            cp16(smu_a + (s * PF_AS + r * 36 + q) * 4, Ag + (long)r * N_ + j0 + q);
        }
        cp16(smu_k + (s * PF_KS + (tid >> 3) * 36 + (tid & 7) * 4) * 4,
             Kg + (long)(tid >> 3) * N_ + j0 + (tid & 7) * 4);
        CP_COMMIT();
    }

    for (int ch = 0; ch < 128; ch++) {
        if (ch < 126) { CP_WAIT(1); } else { CP_WAIT(0); }
        __syncthreads();
        const float* As_ = Asm + (ch & 1) * PF_AS;
        const float* Ks_ = Ksm + (ch & 1) * PF_KS;

        // ---- QK: s[i, j] tile, warp w -> i rows w*16..+16, all 32 j ----
        float s4[4][4] = {};
        #pragma unroll
        for (int k8 = 0; k8 < 4; k8++) {
            int d0 = k8 * 8 + (lane & 3);
            #pragma unroll
            for (int nt = 0; nt < 4; nt++) {
                uint32_t b0 = ld_tf32(&Ks_[d0 * 36 + nt * 8 + (lane >> 2)]);
                uint32_t b1 = ld_tf32(&Ks_[(d0 + 4) * 36 + nt * 8 + (lane >> 2)]);
                mma_tf32(s4[nt], aq[k8][0], aq[k8][1], aq[k8][2], aq[k8][3], b0, b1);
            }
        }
        // ---- exp + row sums + store P ----
        {
            int r0 = (w * 16 + (lane >> 2)) * 36 + 2 * (lane & 3);
            #pragma unroll
            for (int nt = 0; nt < 4; nt++) {
                float p0 = __expf(s4[nt][0]), p1 = __expf(s4[nt][1]);
                float p2 = __expf(s4[nt][2]), p3 = __expf(s4[nt][3]);
                lsum0 += p0 + p1;
                lsum1 += p2 + p3;
                *(float2*)&Ps[r0 + nt * 8] = make_float2(p0, p1);
                *(float2*)&Ps[r0 + 8 * 36 + nt * 8] = make_float2(p2, p3);
            }
        }
        __syncthreads();
        // ---- PV: c[c, i] += v[c, j] * P[i, j]  (warps 4m x 2n) ----
        #pragma unroll
        for (int k8 = 0; k8 < 32; k8 += 8) {
            uint32_t a[4][4], bb[8][2];
            #pragma unroll
            for (int mt = 0; mt < 4; mt++) {
                const float* ap = As_ + (wm * 64 + mt * 16 + (lane >> 2)) * 36 + k8 + (lane & 3);
                a[mt][0] = ld_tf32(ap);
                a[mt][1] = ld_tf32(ap + 8 * 36);
                a[mt][2] = ld_tf32(ap + 4);
                a[mt][3] = ld_tf32(ap + 8 * 36 + 4);
            }
            #pragma unroll
            for (int nt = 0; nt < 8; nt++) {
                const float* bp = &Ps[(wn * 64 + nt * 8 + (lane >> 2)) * 36 + k8 + (lane & 3)];
                bb[nt][0] = ld_tf32(bp);
                bb[nt][1] = ld_tf32(bp + 4);
            }
            #pragma unroll
            for (int mt = 0; mt < 4; mt++)
                #pragma unroll
                for (int nt = 0; nt < 8; nt++)
                    mma_tf32(c[mt][nt], a[mt][0], a[mt][1], a[mt][2], a[mt][3],
                             bb[nt][0], bb[nt][1]);
        }
        __syncthreads();
        // ---- prefetch chunk+2 ----
        if (ch + 2 < 128) {
            int s = ch & 1;
            int j0 = (ch + 2) * 32;
            #pragma unroll
            for (int j = 0; j < 8; j++) {
                int f = tid + 256 * j;
                int r = f >> 3, q = (f & 7) * 4;
                cp16(smu_a + (s * PF_AS + r * 36 + q) * 4, Ag + (long)r * N_ + j0 + q);
            }
            cp16(smu_k + (s * PF_KS + (tid >> 3) * 36 + (tid & 7) * 4) * 4,
                 Kg + (long)(tid >> 3) * N_ + j0 + (tid & 7) * 4);
            CP_COMMIT();
        }
    }

    // finalize row sums: reduce over lane&3 quads (cols partitioned by lane&3)
    lsum0 += __shfl_xor_sync(0xffffffffu, lsum0, 1);
    lsum0 += __shfl_xor_sync(0xffffffffu, lsum0, 2);
    lsum1 += __shfl_xor_sync(0xffffffffu, lsum1, 1);
    lsum1 += __shfl_xor_sync(0xffffffffu, lsum1, 2);
    if ((lane & 3) == 0) {
        red[w * 16 + (lane >> 2)] = lsum0;
        red[w * 16 + 8 + (lane >> 2)] = lsum1;
    }
    __syncthreads();

    float g = gpa[0];
    #pragma unroll
    for (int nt = 0; nt < 8; nt++) {
        int cl = wn * 64 + nt * 8 + 2 * (lane & 3);
        float inv0 = 1.f / red[cl];
        float inv1 = 1.f / red[cl + 1];
        #pragma unroll
        for (int mt = 0; mt < 4; mt++) {
            int row = wm * 64 + mt * 16 + (lane >> 2);
            int col = I0 + cl;
            long xo = ((long)b * C_ + row) * N_ + col;
            long co = ((long)b * 2 * C_ + row) * N_ + col;
            *(float2*)(cat + co) = make_float2(
                fmaf(g, c[mt][nt][0] * inv0, x[xo]),
                fmaf(g, c[mt][nt][1] * inv1, x[xo + 1]));
            *(float2*)(cat + co + 8 * N_) = make_float2(
                fmaf(g, c[mt][nt][2] * inv0, x[xo + 8 * N_]),
                fmaf(g, c[mt][nt][3] * inv1, x[xo + 8 * N_ + 1]));
        }
    }
}

// =================================================================
// xxT_mma: split-K channel-logits partials (tf32 mma, NT)
// =================================================================
#define XT_SMEM_BYTES ((2 * 128 * 36 * 2) * 4)   // 73728

__global__ void __launch_bounds__(256)
xxT_mma(const float* __restrict__ x, float* __restrict__ part) {
    extern __shared__ float sm[];
    float* Asm = sm;
    float* Bsm = sm + 2 * 128 * 36;
    int tid = threadIdx.x, lane = tid & 31, wid = tid >> 5;
    int wm = wid & 3, wn = wid >> 2;
    int z = blockIdx.z, b = z >> 3, ks = z & 7;
    int m0 = blockIdx.y * 128, n0 = blockIdx.x * 128;
    const float* Ag = x + (long)b * C_ * N_ + (long)m0 * N_ + ks * 512;
    const float* Bg = x + (long)b * C_ * N_ + (long)n0 * N_ + ks * 512;
    uint32_t smu_a = smem_to_u32(Asm), smu_b = smem_to_u32(Bsm);
    float c[2][8][4] = {};

    #pragma unroll
    for (int s = 0; s < 2; s++) {
        int k0 = s * 32;
        #pragma unroll
        for (int j = 0; j < 4; j++) {
            int f = tid + 256 * j;
            int r = f >> 3, q = (f & 7) * 4;
            cp16(smu_a + (s * 4608 + r * 36 + q) * 4, Ag + (long)r * N_ + k0 + q);
            cp16(smu_b + (s * 4608 + r * 36 + q) * 4, Bg + (long)r * N_ + k0 + q);
        }
        CP_COMMIT();
    }

    for (int ch = 0; ch < 16; ch++) {
        if (ch < 14) { CP_WAIT(1); } else { CP_WAIT(0); }
        __syncthreads();
        const float* As_ = Asm + (ch & 1) * 4608;
        const float* Bs_ = Bsm + (ch & 1) * 4608;
        #pragma unroll
        for (int k8 = 0; k8 < 32; k8 += 8) {
            uint32_t a[2][4], bb[8][2];
            #pragma unroll
            for (int mt = 0; mt < 2; mt++) {
                const float* ap = As_ + (wm * 32 + mt * 16 + (lane >> 2)) * 36 + k8 + (lane & 3);
                a[mt][0] = ld_tf32(ap);
                a[mt][1] = ld_tf32(ap + 8 * 36);
                a[mt][2] = ld_tf32(ap + 4);
                a[mt][3] = ld_tf32(ap + 8 * 36 + 4);
            }
            #pragma unroll
            for (int nt = 0; nt < 8; nt++) {
                const float* bp = Bs_ + (wn * 64 + nt * 8 + (lane >> 2)) * 36 + k8 + (lane & 3);
                bb[nt][0] = ld_tf32(bp);
                bb[nt][1] = ld_tf32(bp + 4);
            }
            #pragma unroll
            for (int mt = 0; mt < 2; mt++)
                #pragma unroll
                for (int nt = 0; nt < 8; nt++)
                    mma_tf32(c[mt][nt], a[mt][0], a[mt][1], a[mt][2], a[mt][3],
                             bb[nt][0], bb[nt][1]);
        }
        __syncthreads();
        if (ch + 2 < 16) {
            int s = ch & 1;
            int k0 = (ch + 2) * 32;
            #pragma unroll
            for (int j = 0; j < 4; j++) {
                int f = tid + 256 * j;
                int r = f >> 3, q = (f & 7) * 4;
                cp16(smu_a + (s * 4608 + r * 36 + q) * 4, Ag + (long)r * N_ + k0 + q);
                cp16(smu_b + (s * 4608 + r * 36 + q) * 4, Bg + (long)r * N_ + k0 + q);
            }
            CP_COMMIT();
        }
    }

    float* Ob = part + (long)z * C_ * C_;
    #pragma unroll
    for (int mt = 0; mt < 2; mt++) {
        int row = m0 + wm * 32 + mt * 16 + (lane >> 2);
        #pragma unroll
        for (int nt = 0; nt < 8; nt++) {
            int col = n0 + wn * 64 + nt * 8 + 2 * (lane & 3);
            long o = (long)row * C_ + col;
            *(float2*)(Ob + o) = make_float2(c[mt][nt][0], c[mt][nt][1]);
            *(float2*)(Ob + o + 8 * C_) = make_float2(c[mt][nt][2], c[mt][nt][3]);
        }
    }
}

// =================================================================
// NN-GEMM (tf32 mma): Out[m][n] = sum_k A[m][k] * B[k][n]
// =================================================================
#define NN_SMEM_BYTES ((2 * 128 * 36 + 2 * 32 * 132) * 4)   // 70656

__global__ void __launch_bounds__(256)
gemm_nn_mma(const float* __restrict__ A, const float* __restrict__ B,
            float* __restrict__ Out, int K, int epi,
            const float* __restrict__ bias, const float* __restrict__ gsc,
            const float* __restrict__ res,
            long sA, long sB, long sO, long sR) {
    extern __shared__ float sm[];
    float* As = sm;
    float* Bs = sm + 2 * 128 * 36;
    int tid = threadIdx.x, lane = tid & 31, w = tid >> 5;
    int wm = w & 3, wn = w >> 2;
    int b = blockIdx.z, m0 = blockIdx.y * 128, n0 = blockIdx.x * 128;
    const float* Ag = A + sA * b + (long)m0 * K;
    const float* Bg = B + sB * b + n0;
    uint32_t smu_a = smem_to_u32(As), smu_b = smem_to_u32(Bs);
    float acc[2][8][4] = {};
    int nchunks = K / 32;

    #pragma unroll
    for (int s = 0; s < 2; s++) {
        #pragma unroll
        for (int jj = 0; jj < 4; jj++) {
            int idx = tid + 256 * jj;
            int r = idx >> 3, kq = (idx & 7) * 4;
            cp16(smu_a + (s * 4608 + r * 36 + kq) * 4, Ag + (long)r * K + s * 32 + kq);
            int kk = idx >> 5, nq = (idx & 31) * 4;
            cp16(smu_b + (s * 4224 + kk * 132 + nq) * 4, Bg + (long)(s * 32 + kk) * N_ + nq);
        }
        CP_COMMIT();
    }

    for (int ch = 0; ch < nchunks; ch++) {
        if (ch < nchunks - 2) { CP_WAIT(1); } else { CP_WAIT(0); }
        __syncthreads();
        const float* As_ = As + (ch & 1) * 4608;
        const float* Bs_ = Bs + (ch & 1) * 4224;
        #pragma unroll
        for (int k8 = 0; k8 < 32; k8 += 8) {
            uint32_t a[2][4], bb[8][2];
            #pragma unroll
            for (int mt = 0; mt < 2; mt++) {
                const float* ap = As_ + (wm * 32 + mt * 16 + (lane >> 2)) * 36 + k8 + (lane & 3);
                a[mt][0] = ld_tf32(ap);
                a[mt][1] = ld_tf32(ap + 8 * 36);
                a[mt][2] = ld_tf32(ap + 4);
                a[mt][3] = ld_tf32(ap + 8 * 36 + 4);
            }
            #pragma unroll
            for (int nt = 0; nt < 8; nt++) {
                const float* bp = Bs_ + (k8 + (lane & 3)) * 132 + wn * 64 + nt * 8 + (lane >> 2);
                bb[nt][0] = ld_tf32(bp);
                bb[nt][1] = ld_tf32(bp + 4 * 132);
            }
            #pragma unroll
            for (int mt = 0; mt < 2; mt++)
                #pragma unroll
                for (int nt = 0; nt < 8; nt++)
                    mma_tf32(acc[mt][nt], a[mt][0], a[mt][1], a[mt][2], a[mt][3],
                             bb[nt][0], bb[nt][1]);
        }
        __syncthreads();
        if (ch + 2 < nchunks) {
            int s = ch & 1;
            #pragma unroll
            for (int jj = 0; jj < 4; jj++) {
                int idx = tid + 256 * jj;
                int r = idx >> 3, kq = (idx & 7) * 4;
                cp16(smu_a + (s * 4608 + r * 36 + kq) * 4,
                     Ag + (long)r * K + (ch + 2) * 32 + kq);
                int kk = idx >> 5, nq = (idx & 31) * 4;
                cp16(smu_b + (s * 4224 + kk * 132 + nq) * 4,
                     Bg + (long)((ch + 2) * 32 + kk) * N_ + nq);
            }
            CP_COMMIT();
        }
    }

    float g = gsc ? *gsc : 0.f;
    const float* resb = res ? res + sR * b : nullptr;
    float* Ob = Out + sO * b;
    #pragma unroll
    for (int mt = 0; mt < 2; mt++) {
        int row = m0 + wm * 32 + mt * 16 + (lane >> 2);
        #pragma unroll
        for (int nt = 0; nt < 8; nt++) {
            int col = n0 + wn * 64 + nt * 8 + 2 * (lane & 3);
            long o = (long)row * N_ + col;
            if (epi == 0) {
                float bv = bias[row], bv8 = bias[row + 8];
                *(float2*)(Ob + o) = make_float2(acc[mt][nt][0] + bv, acc[mt][nt][1] + bv);
                *(float2*)(Ob + o + 8 * N_) =
                    make_float2(acc[mt][nt][2] + bv8, acc[mt][nt][3] + bv8);
            } else {
                *(float2*)(Ob + o) = make_float2(
                    fmaf(g, acc[mt][nt][0], resb[o]), fmaf(g, acc[mt][nt][1], resb[o + 1]));
                *(float2*)(Ob + o + 8 * N_) = make_float2(
                    fmaf(g, acc[mt][nt][2], resb[o + 8 * N_]),
                    fmaf(g, acc[mt][nt][3], resb[o + 8 * N_ + 1]));
            }
        }
    }
}

// =================================================================
// 3x3 conv 512 -> 256, implicit GEMM v3 (tf32 mma): M=256 (all o-channels
// per CTA -> cat patch loaded once), spatial 128 (2 h-rows), 64 ci-chunks.
// =================================================================
#define CV_AS_FLOATS  (256 * 76)         // 19456 per buffer
#define CV_PT_FLOATS  (8 * 296)          // 2368 per buffer
#define CV_SMEM_BYTES ((2 * CV_AS_FLOATS + 2 * CV_PT_FLOATS) * 4)   // 174592

__global__ void __launch_bounds__(256, 1)
conv_mma(const float* __restrict__ cat, const float* __restrict__ wf,
         float* __restrict__ y) {
    extern __shared__ float sm[];
    float* Asm = sm;                         // 2 x [256][76]
    float* Pt = sm + 2 * CV_AS_FLOATS;       // 2 x [8][296]
    int tid = threadIdx.x, lane = tid & 31, wid = tid >> 5;
    int wm = wid & 3, wn = wid >> 2;
    int b = blockIdx.z, p0 = blockIdx.x * 128;
    int h0 = blockIdx.x * 2;
    uint32_t smu_a = smem_to_u32(Asm), smu_p = smem_to_u32(Pt);

    for (int i = tid; i < 2 * CV_PT_FLOATS; i += 256) Pt[i] = 0.f;
    __syncthreads();

    float c[4][8][4] = {};

    #pragma unroll
    for (int s = 0; s < 2; s++) {
        #pragma unroll
        for (int j = 0; j < 18; j++) {       // weights: 256 rows x 18 cp16
            int f = tid + 256 * j;
            int r = f / 18, q = (f % 18) * 4;
            cp16(smu_a + (s * CV_AS_FLOATS + r * 76 + q) * 4,
                 wf + (long)r * 4608 + s * 72 + q);
        }
        #pragma unroll
        for (int j = 0; j < 2; j++) {
            int f = tid + 256 * j;
            int ci = f >> 6, rq = (f >> 4) & 3, q = (f & 15) * 4;
            int h = h0 - 1 + rq;
            if (h >= 0 && h < 64)
                cp16(smu_p + (s * CV_PT_FLOATS + ci * 296 + rq * 72 + 4 + q) * 4,
                     cat + ((long)b * 512 + s * 8 + ci) * 4096 + h * 64 + q);
        }
        CP_COMMIT();
    }

    for (int chunk = 0; chunk < 64; chunk++) {
        if (chunk < 62) { CP_WAIT(1); } else { CP_WAIT(0); }
        __syncthreads();
        const float* As_ = Asm + (chunk & 1) * CV_AS_FLOATS;
        const float* Pt_ = Pt + (chunk & 1) * CV_PT_FLOATS;

        #pragma unroll
        for (int pos = 0; pos < 9; pos++) {
            const int kh = pos / 3, kw = pos % 3;
            uint32_t a[4][4], bb[8][2];
            #pragma unroll
            for (int mt = 0; mt < 4; mt++) {
                const float* ap = As_ + (wm * 64 + mt * 16 + (lane >> 2)) * 76
                                  + (lane & 3) * 9 + pos;
                a[mt][0] = ld_tf32(ap);
                a[mt][1] = ld_tf32(ap + 8 * 76);
                a[mt][2] = ld_tf32(ap + 36);          // ci + 4
                a[mt][3] = ld_tf32(ap + 8 * 76 + 36);
            }
            {
                int nbase = wn * 64 + (lane >> 2);
                int hh = nbase >> 6;
                const float* pb = Pt_ + (lane & 3) * 296 + (hh + kh) * 72;
                #pragma unroll
                for (int nt = 0; nt < 8; nt++) {
                    int wpos = ((nbase + nt * 8) & 63) + kw + 3;
                    bb[nt][0] = ld_tf32(pb + wpos);
                    bb[nt][1] = ld_tf32(pb + 4 * 296 + wpos);
                }
            }
            #pragma unroll
            for (int mt = 0; mt < 4; mt++)
                #pragma unroll
                for (int nt = 0; nt < 8; nt++)
                    mma_tf32(c[mt][nt], a[mt][0], a[mt][1], a[mt][2], a[mt][3],
                             bb[nt][0], bb[nt][1]);
        }
        __syncthreads();
        if (chunk + 2 < 64) {
            int s = chunk & 1;
            #pragma unroll
            for (int j = 0; j < 18; j++) {
                int f = tid + 256 * j;
                int r = f / 18, q = (f % 18) * 4;
                cp16(smu_a + (s * CV_AS_FLOATS + r * 76 + q) * 4,
                     wf + (long)r * 4608 + (chunk + 2) * 72 + q);
            }
            #pragma unroll
            for (int j = 0; j < 2; j++) {
                int f = tid + 256 * j;
                int ci = f >> 6, rq = (f >> 4) & 3, q = (f & 15) * 4;
                int h = h0 - 1 + rq;
                if (h >= 0 && h < 64)
                    cp16(smu_p + (s * CV_PT_FLOATS + ci * 296 + rq * 72 + 4 + q) * 4,
                         cat + ((long)b * 512 + (chunk + 2) * 8 + ci) * 4096 + h * 64 + q);
            }
            CP_COMMIT();
        }
    }

    #pragma unroll
    for (int mt = 0; mt < 4; mt++) {
        #pragma unroll
        for (int nt = 0; nt < 8; nt++) {
            int row = wm * 64 + mt * 16 + (lane >> 2);
            int col = p0 + wn * 64 + nt * 8 + 2 * (lane & 3);
            long yo = ((long)b * 256 + row) * 4096 + col;
            *(float2*)(y + yo) = make_float2(c[mt][nt][0], c[mt][nt][1]);
            *(float2*)(y + yo + 8 * 4096) = make_float2(c[mt][nt][2], c[mt][nt][3]);
        }
    }
}

// ---------------- helpers ----------------
__device__ __forceinline__ float warpMax(float v) {
    #pragma unroll
    for (int o = 16; o; o >>= 1) v = fmaxf(v, __shfl_xor_sync(0xffffffffu, v, o));
    return v;
}
__device__ __forceinline__ float warpSum(float v) {
    #pragma unroll
    for (int o = 16; o; o >>= 1) v += __shfl_xor_sync(0xffffffffu, v, o);
    return v;
}

// ---------------- merged q+k projection (fp32 SIMT, M=64) ----------------
__global__ void qk_proj(const float* __restrict__ wq, const float* __restrict__ bq,
                        const float* __restrict__ wk, const float* __restrict__ bk,
                        const float* __restrict__ x, float* __restrict__ q,
                        float* __restrict__ k) {
    __shared__ float As[16][64];
    __shared__ float Bs[16][64];
    int b = blockIdx.z;
    const float* Bm = x + (long)b * C_ * N_;
    int tid = threadIdx.x;
    int tx = tid & 15, ty = tid >> 4;
    int n0 = blockIdx.x * 64;
    int arow = tid >> 2, ak = (tid & 3) * 4;
    int brow = tid >> 4, bn = (tid & 15) * 4;
    const float* Arow = (arow < 32) ? (wq + (long)arow * C_)
                                    : (wk + (long)(arow - 32) * C_);
    float acc[4][4] = {};
    for (int k0 = 0; k0 < C_; k0 += 16) {
        float4 av = *(const float4*)(Arow + k0 + ak);
        As[ak + 0][arow] = av.x; As[ak + 1][arow] = av.y;
        As[ak + 2][arow] = av.z; As[ak + 3][arow] = av.w;
        *(float4*)&Bs[brow][bn] = *(const float4*)(Bm + (long)(k0 + brow) * N_ + n0 + bn);
        __syncthreads();
        #pragma unroll
        for (int kk = 0; kk < 16; kk++) {
            float4 a = *(const float4*)&As[kk][ty * 4];
            float4 bv = *(const float4*)&Bs[kk][tx * 4];
            float ar[4] = {a.x, a.y, a.z, a.w};
            float br[4] = {bv.x, bv.y, bv.z, bv.w};
            #pragma unroll
            for (int i = 0; i < 4; i++)
                #pragma unroll
                for (int j = 0; j < 4; j++)
                    acc[i][j] = fmaf(ar[i], br[j], acc[i][j]);
        }
        __syncthreads();
    }
    #pragma unroll
    for (int i = 0; i < 4; i++) {
        int m = ty * 4 + i;
        float bv = (m < 32) ? bq[m] : bk[m - 32];
        float* Out = (m < 32) ? (q + ((long)b * CQ_ + m) * N_)
                              : (k + ((long)b * CQ_ + m - 32) * N_);
        *(float4*)(Out + n0 + tx * 4) = make_float4(
            acc[i][0] + bv, acc[i][1] + bv, acc[i][2] + bv, acc[i][3] + bv);
    }
}

// ---------------- softmax over 256 with split-K reduction ----------------
__global__ void softmax256(const float* __restrict__ part, float* __restrict__ out) {
    __shared__ float sh[8];
    int tid = threadIdx.x;
    int row = blockIdx.x;                 // b*256 + i
    int b = row >> 8, i = row & 255;
    float v = 0.f;
    #pragma unroll
    for (int ks = 0; ks < 8; ks++)
        v += part[((long)(b * 8 + ks) * C_ + i) * C_ + tid];
    float m = warpMax(v);
    if ((tid & 31) == 0) sh[tid >> 5] = m;
    __syncthreads();
    m = sh[tid & 7];
    #pragma unroll
    for (int o = 4; o; o >>= 1) m = fmaxf(m, __shfl_xor_sync(0xffffffffu, m, o));
    __syncthreads();
    float e = __expf(v - m);
    float s = warpSum(e);
    if ((tid & 31) == 0) sh[tid >> 5] = s;
    __syncthreads();
    s = sh[tid & 7];
    #pragma unroll
    for (int o = 4; o; o >>= 1) s += __shfl_xor_sync(0xffffffffu, s, o);
    out[(long)row * 256 + tid] = e / s;
}

// ---------------- BN (train-mode batch stats) + ReLU ----------------
__global__ void bnstats(const float* __restrict__ y, float* __restrict__ meanp,
                        float* __restrict__ rstdp) {
    __shared__ float sh[16];
    int o = blockIdx.x, tid = threadIdx.x;
    float s = 0.f, sq = 0.f;
    for (int b = 0; b < 4; b++) {
        const float4* p = (const float4*)(y + ((size_t)b * 256 + o) * 4096);
        for (int i = tid; i < 1024; i += 256) {
            float4 v = p[i];
            s += v.x + v.y + v.z + v.w;
            sq += v.x * v.x + v.y * v.y + v.z * v.z + v.w * v.w;
        }
    }
    s = warpSum(s); sq = warpSum(sq);
    if ((tid & 31) == 0) { sh[tid >> 5] = s; sh[8 + (tid >> 5)] = sq; }
    __syncthreads();
    if (tid == 0) {
        float S = 0.f, SQ = 0.f;
        for (int i = 0; i < 8; i++) { S += sh[i]; SQ += sh[8 + i]; }
        float mean = S / 16384.f;
        float var = SQ / 16384.f - mean * mean;
        meanp[o] = mean;
        rstdp[o] = rsqrtf(var + 1e-5f);
    }
}

__global__ void bnapply(const float* __restrict__ y, const float* __restrict__ gam,
                        const float* __restrict__ bet, const float* __restrict__ meanp,
                        const float* __restrict__ rstdp, float* __restrict__ out) {
    size_t i = (size_t)blockIdx.x * 256 + threadIdx.x;  // float4 index
    int o = (int)((i >> 10) & 255);
    float mu = meanp[o], rs = rstdp[o], g = gam[o], be = bet[o];
    float4 v = ((const float4*)y)[i];
    float4 r;
    r.x = fmaxf(0.f, fmaf((v.x - mu) * rs, g, be));
    r.y = fmaxf(0.f, fmaf((v.y - mu) * rs, g, be));
    r.z = fmaxf(0.f, fmaf((v.z - mu) * rs, g, be));
    r.w = fmaxf(0.f, fmaf((v.w - mu) * rs, g, be));
    ((float4*)out)[i] = r;
}

// ---------------- launcher ----------------
extern "C" void kernel_launch(void* const* d_in, const int* in_sizes, int n_in,
                              void* d_out, int out_size) {
    const float* x   = (const float*)d_in[0];
    const float* wq  = (const float*)d_in[1];
    const float* bq  = (const float*)d_in[2];
    const float* wk  = (const float*)d_in[3];
    const float* bk  = (const float*)d_in[4];
    const float* wv  = (const float*)d_in[5];
    const float* bv  = (const float*)d_in[6];
    const float* gpa = (const float*)d_in[7];
    const float* gca = (const float*)d_in[8];
    const float* wf  = (const float*)d_in[9];
    const float* bng = (const float*)d_in[10];
    const float* bnb = (const float*)d_in[11];
    float* out = (float*)d_out;

    float *q, *k, *v, *cat, *cattn, *cattn_part, *y, *mean, *rstd;
    cudaGetSymbolAddress((void**)&q, g_q);
    cudaGetSymbolAddress((void**)&k, g_k);
    cudaGetSymbolAddress((void**)&v, g_v);
    cudaGetSymbolAddress((void**)&cat, g_cat);
    cudaGetSymbolAddress((void**)&cattn, g_cattn);
    cudaGetSymbolAddress((void**)&cattn_part, g_cattn_part);
    cudaGetSymbolAddress((void**)&y, g_y);
    cudaGetSymbolAddress((void**)&mean, g_mean);
    cudaGetSymbolAddress((void**)&rstd, g_rstd);

    cudaFuncSetAttribute(pa_flash, cudaFuncAttributeMaxDynamicSharedMemorySize,
                         PF_SMEM_BYTES);
    cudaFuncSetAttribute(gemm_nn_mma, cudaFuncAttributeMaxDynamicSharedMemorySize,
                         NN_SMEM_BYTES);
    cudaFuncSetAttribute(xxT_mma, cudaFuncAttributeMaxDynamicSharedMemorySize,
                         XT_SMEM_BYTES);
    cudaFuncSetAttribute(conv_mma, cudaFuncAttributeMaxDynamicSharedMemorySize,
                         CV_SMEM_BYTES);

    dim3 blk(256);
    long sx = (long)C_ * N_;
    long scat = (long)2 * C_ * N_;

    // q + k projections in one kernel
    qk_proj<<<dim3(64, 1, 4), blk>>>(wq, bq, wk, bk, x, q, k);
    // v projection on tensor cores
    gemm_nn_mma<<<dim3(32, 2, 4), blk, NN_SMEM_BYTES>>>(
        wv, x, v, C_, 0, bv, nullptr, nullptr, 0, sx, sx, 0);
    // fused flash position-attention -> cat[:, 0:256]
    pa_flash<<<dim3(32, 1, 4), blk, PF_SMEM_BYTES>>>(q, k, v, x, gpa, cat);
    // channel attention: split-K x.xT partials, fused-reduce softmax, apply
    xxT_mma<<<dim3(2, 2, 32), blk, XT_SMEM_BYTES>>>(x, cattn_part);
    softmax256<<<B_ * C_, 256>>>(cattn_part, cattn);
    gemm_nn_mma<<<dim3(32, 2, 4), blk, NN_SMEM_BYTES>>>(
        cattn, x, cat + (size_t)C_ * N_, C_, 1, nullptr, gca, x,
        (long)C_ * C_, sx, scat, sx);
    // 3x3 conv 512->256 (implicit GEMM v3, M=256)
    conv_mma<<<dim3(32, 1, 4), blk, CV_SMEM_BYTES>>>(cat, wf, y);
    // BN train-mode + ReLU
    bnstats<<<256, 256>>>(y, mean, rstd);
    bnapply<<<4096, 256>>>(y, bng, bnb, mean, rstd, out);
}

// round 12
// speedup vs baseline: 3.1864x; 1.1897x over previous
#include <cuda_runtime.h>
#include <cuda_bf16.h>
#include <cstdint>

#define B_  4
#define C_  256
#define CQ_ 32
#define N_  4096
#define HW_ 64

// ---------------- scratch (device globals; no allocation) ----------------
__device__ float g_q[B_ * CQ_ * N_];
__device__ float g_k[B_ * CQ_ * N_];
__device__ __nv_bfloat16 g_v[B_ * C_ * N_];              // bf16 v
__device__ float g_cat[(size_t)B_ * 2 * C_ * N_];        // [b][512][4096]
__device__ float g_cattn_part[32 * C_ * C_];             // split-K partials
__device__ float g_cattn[B_ * C_ * C_];
__device__ float g_y[(size_t)B_ * C_ * N_];
__device__ float g_mean[C_];
__device__ float g_rstd[C_];

// ---------------- PTX helpers (sm_80+ mma.sync / cp.async) ----------------
__device__ __forceinline__ uint32_t smem_to_u32(const void* p) {
    uint32_t a;
    asm("{ .reg .u64 t; cvta.to.shared.u64 t, %1; cvt.u32.u64 %0, t; }" : "=r"(a) : "l"(p));
    return a;
}
__device__ __forceinline__ void cp16(uint32_t dst, const void* src) {
    asm volatile("cp.async.cg.shared.global [%0], [%1], 16;" :: "r"(dst), "l"(src));
}
#define CP_COMMIT() asm volatile("cp.async.commit_group;" ::: "memory")
#define CP_WAIT(n)  asm volatile("cp.async.wait_group %0;" :: "n"(n) : "memory")

__device__ __forceinline__ uint32_t ld_tf32(const float* p) {
    uint32_t r;
    float f = *p;
    asm("cvt.rna.tf32.f32 %0, %1;" : "=r"(r) : "f"(f));
    return r;
}
__device__ __forceinline__ void mma_tf32(float c[4], uint32_t a0, uint32_t a1,
                                         uint32_t a2, uint32_t a3,
                                         uint32_t b0, uint32_t b1) {
    asm volatile(
        "mma.sync.aligned.m16n8k8.row.col.f32.tf32.tf32.f32 "
        "{%0,%1,%2,%3}, {%4,%5,%6,%7}, {%8,%9}, {%0,%1,%2,%3};"
        : "+f"(c[0]), "+f"(c[1]), "+f"(c[2]), "+f"(c[3])
        : "r"(a0), "r"(a1), "r"(a2), "r"(a3), "r"(b0), "r"(b1));
}
// bf16 mma, K=16 per instruction (2x tf32 throughput per issue slot)
__device__ __forceinline__ void mma_bf16(float c[4], uint32_t a0, uint32_t a1,
                                         uint32_t a2, uint32_t a3,
                                         uint32_t b0, uint32_t b1) {
    asm volatile(
        "mma.sync.aligned.m16n8k16.row.col.f32.bf16.bf16.f32 "
        "{%0,%1,%2,%3}, {%4,%5,%6,%7}, {%8,%9}, {%0,%1,%2,%3};"
        : "+f"(c[0]), "+f"(c[1]), "+f"(c[2]), "+f"(c[3])
        : "r"(a0), "r"(a1), "r"(a2), "r"(a3), "r"(b0), "r"(b1));
}

// =================================================================
// pa_flash v2: fused attention, PV on bf16 m16n8k16.
//   cat[b,c,i] = gamma_pa*(1/l_i)*sum_j v[b,c,j]*exp(q_i.k_j) + x[b,c,i]
// CTA: i-tile 128, all 256 channels, batch. Per 32-j chunk:
//   QK tf32 mma (q frags in regs, k staged fp32 32x36),
//   exp -> Ps[128][40] bf16 + fp32 reg row-sums,
//   PV bf16 mma (v staged bf16 2x[256][40]).
// smem: v 40960B + k 9216B + Ps 10240B = 60416B.
// =================================================================
#define PF_AS  (256 * 40)          // bf16 units per v stage
#define PF_KS  (32 * 36)           // floats per k stage
#define PF_SMEM_BYTES (2 * PF_AS * 2 + 2 * PF_KS * 4 + 128 * 40 * 2)  // 60416

__global__ void __launch_bounds__(256, 1)
pa_flash(const float* __restrict__ qg, const float* __restrict__ kg,
         const __nv_bfloat16* __restrict__ v, const float* __restrict__ x,
         const float* __restrict__ gpa, float* __restrict__ cat) {
    extern __shared__ char smc[];
    __nv_bfloat16* Avs = (__nv_bfloat16*)smc;             // 2 x [256][40] bf16
    float* Ksm = (float*)(smc + 2 * PF_AS * 2);           // 2 x [32][36] f32
    __nv_bfloat16* Ps = (__nv_bfloat16*)(smc + 2 * PF_AS * 2 + 2 * PF_KS * 4);
    __shared__ float red[128];
    int tid = threadIdx.x, lane = tid & 31, w = tid >> 5;
    int wm = w & 3, wn = w >> 2;
    int b = blockIdx.z, I0 = blockIdx.x * 128;
    const float* Qg = qg + (long)b * CQ_ * N_;
    const float* Kg = kg + (long)b * CQ_ * N_;
    const __nv_bfloat16* Ag = v + (long)b * C_ * N_;
    uint32_t smu_a = smem_to_u32(Avs), smu_k = smem_to_u32(Ksm);

    // loop-invariant q fragments: A[m=i][k=d], warp w owns i rows w*16..+16
    uint32_t aq[4][4];
    {
        int i0 = I0 + w * 16 + (lane >> 2);
        #pragma unroll
        for (int k8 = 0; k8 < 4; k8++) {
            int d0 = k8 * 8 + (lane & 3);
            const float* qp = Qg + (long)d0 * N_ + i0;
            aq[k8][0] = ld_tf32(qp);
            aq[k8][1] = ld_tf32(qp + 8);
            aq[k8][2] = ld_tf32(qp + 4 * N_);
            aq[k8][3] = ld_tf32(qp + 4 * N_ + 8);
        }
    }

    float c[4][8][4] = {};
    float lsum0 = 0.f, lsum1 = 0.f;

    // prologue: stage chunks 0,1 (v rows bf16 + k tile f32)
    #pragma unroll
    for (int s = 0; s < 2; s++) {
        int j0 = s * 32;
        #pragma unroll
        for (int j = 0; j < 4; j++) {        // v: 256 rows x 4 cp16 (8 bf16 each)
            int f = tid + 256 * j;
            int r = f >> 2, q = (f & 3) * 8;
            cp16(smu_a + (s * PF_AS + r * 40 + q) * 2, Ag + (long)r * N_ + j0 + q);
        }
        cp16(smu_k + (s * PF_KS + (tid >> 3) * 36 + (tid & 7) * 4) * 4,
             Kg + (long)(tid >> 3) * N_ + j0 + (tid & 7) * 4);
        CP_COMMIT();
    }

    for (int ch = 0; ch < 128; ch++) {
        if (ch < 126) { CP_WAIT(1); } else { CP_WAIT(0); }
        __syncthreads();
        const __nv_bfloat16* As_ = Avs + (ch & 1) * PF_AS;
        const float* Ks_ = Ksm + (ch & 1) * PF_KS;

        // ---- QK (tf32): s[i, j] tile, warp w -> i rows w*16..+16 ----
        float s4[4][4] = {};
        #pragma unroll
        for (int k8 = 0; k8 < 4; k8++) {
            int d0 = k8 * 8 + (lane & 3);
            #pragma unroll
            for (int nt = 0; nt < 4; nt++) {
                uint32_t b0 = ld_tf32(&Ks_[d0 * 36 + nt * 8 + (lane >> 2)]);
                uint32_t b1 = ld_tf32(&Ks_[(d0 + 4) * 36 + nt * 8 + (lane >> 2)]);
                mma_tf32(s4[nt], aq[k8][0], aq[k8][1], aq[k8][2], aq[k8][3], b0, b1);
            }
        }
        // ---- exp + fp32 row sums + pack P -> bf16 smem ----
        {
            int r0 = (w * 16 + (lane >> 2)) * 40 + 2 * (lane & 3);
            #pragma unroll
            for (int nt = 0; nt < 4; nt++) {
                float p0 = __expf(s4[nt][0]), p1 = __expf(s4[nt][1]);
                float p2 = __expf(s4[nt][2]), p3 = __expf(s4[nt][3]);
                lsum0 += p0 + p1;
                lsum1 += p2 + p3;
                __nv_bfloat162 h0 = __floats2bfloat162_rn(p0, p1);
                __nv_bfloat162 h1 = __floats2bfloat162_rn(p2, p3);
                *(__nv_bfloat162*)&Ps[r0 + nt * 8] = h0;
                *(__nv_bfloat162*)&Ps[r0 + 8 * 40 + nt * 8] = h1;
            }
        }
        __syncthreads();
        // ---- PV (bf16 k16): c[c, i] += v[c, j] * P[i, j] ----
        #pragma unroll
        for (int ks = 0; ks < 2; ks++) {
            int k0 = ks * 16;
            uint32_t a[4][4], bb[8][2];
            #pragma unroll
            for (int mt = 0; mt < 4; mt++) {
                const __nv_bfloat16* ap = As_ + (wm * 64 + mt * 16 + (lane >> 2)) * 40
                                          + k0 + 2 * (lane & 3);
                a[mt][0] = *(const uint32_t*)ap;
                a[mt][1] = *(const uint32_t*)(ap + 8 * 40);
                a[mt][2] = *(const uint32_t*)(ap + 8);
                a[mt][3] = *(const uint32_t*)(ap + 8 * 40 + 8);
            }
            #pragma unroll
            for (int nt = 0; nt < 8; nt++) {
                const __nv_bfloat16* bp = Ps + (wn * 64 + nt * 8 + (lane >> 2)) * 40
                                          + k0 + 2 * (lane & 3);
                bb[nt][0] = *(const uint32_t*)bp;
                bb[nt][1] = *(const uint32_t*)(bp + 8);
            }
            #pragma unroll
            for (int mt = 0; mt < 4; mt++)
                #pragma unroll
                for (int nt = 0; nt < 8; nt++)
                    mma_bf16(c[mt][nt], a[mt][0], a[mt][1], a[mt][2], a[mt][3],
                             bb[nt][0], bb[nt][1]);
        }
        __syncthreads();
        // ---- prefetch chunk+2 ----
        if (ch + 2 < 128) {
            int s = ch & 1;
            int j0 = (ch + 2) * 32;
            #pragma unroll
            for (int j = 0; j < 4; j++) {
                int f = tid + 256 * j;
                int r = f >> 2, q = (f & 3) * 8;
                cp16(smu_a + (s * PF_AS + r * 40 + q) * 2, Ag + (long)r * N_ + j0 + q);
            }
            cp16(smu_k + (s * PF_KS + (tid >> 3) * 36 + (tid & 7) * 4) * 4,
                 Kg + (long)(tid >> 3) * N_ + j0 + (tid & 7) * 4);
            CP_COMMIT();
        }
    }

    // finalize row sums (cols partitioned by lane&3 quads)
    lsum0 += __shfl_xor_sync(0xffffffffu, lsum0, 1);
    lsum0 += __shfl_xor_sync(0xffffffffu, lsum0, 2);
    lsum1 += __shfl_xor_sync(0xffffffffu, lsum1, 1);
    lsum1 += __shfl_xor_sync(0xffffffffu, lsum1, 2);
    if ((lane & 3) == 0) {
        red[w * 16 + (lane >> 2)] = lsum0;
        red[w * 16 + 8 + (lane >> 2)] = lsum1;
    }
    __syncthreads();

    float g = gpa[0];
    #pragma unroll
    for (int nt = 0; nt < 8; nt++) {
        int cl = wn * 64 + nt * 8 + 2 * (lane & 3);
        float inv0 = 1.f / red[cl];
        float inv1 = 1.f / red[cl + 1];
        #pragma unroll
        for (int mt = 0; mt < 4; mt++) {
            int row = wm * 64 + mt * 16 + (lane >> 2);
            int col = I0 + cl;
            long xo = ((long)b * C_ + row) * N_ + col;
            long co = ((long)b * 2 * C_ + row) * N_ + col;
            *(float2*)(cat + co) = make_float2(
                fmaf(g, c[mt][nt][0] * inv0, x[xo]),
                fmaf(g, c[mt][nt][1] * inv1, x[xo + 1]));
            *(float2*)(cat + co + 8 * N_) = make_float2(
                fmaf(g, c[mt][nt][2] * inv0, x[xo + 8 * N_]),
                fmaf(g, c[mt][nt][3] * inv1, x[xo + 8 * N_ + 1]));
        }
    }
}

// =================================================================
// v_proj: NN-GEMM (tf32 mma) -> bf16 output.  v = wv @ x + bv
// =================================================================
#define NN_SMEM_BYTES ((2 * 128 * 36 + 2 * 32 * 132) * 4)   // 70656

__global__ void __launch_bounds__(256)
v_proj(const float* __restrict__ A, const float* __restrict__ B,
       __nv_bfloat16* __restrict__ Out, const float* __restrict__ bias,
       long sB, long sO) {
    extern __shared__ float sm[];
    float* As = sm;
    float* Bs = sm + 2 * 128 * 36;
    int tid = threadIdx.x, lane = tid & 31, w = tid >> 5;
    int wm = w & 3, wn = w >> 2;
    int b = blockIdx.z, m0 = blockIdx.y * 128, n0 = blockIdx.x * 128;
    const float* Ag = A + (long)m0 * C_;
    const float* Bg = B + sB * b + n0;
    uint32_t smu_a = smem_to_u32(As), smu_b = smem_to_u32(Bs);
    float acc[2][8][4] = {};

    #pragma unroll
    for (int s = 0; s < 2; s++) {
        #pragma unroll
        for (int jj = 0; jj < 4; jj++) {
            int idx = tid + 256 * jj;
            int r = idx >> 3, kq = (idx & 7) * 4;
            cp16(smu_a + (s * 4608 + r * 36 + kq) * 4, Ag + (long)r * C_ + s * 32 + kq);
            int kk = idx >> 5, nq = (idx & 31) * 4;
            cp16(smu_b + (s * 4224 + kk * 132 + nq) * 4, Bg + (long)(s * 32 + kk) * N_ + nq);
        }
        CP_COMMIT();
    }

    for (int ch = 0; ch < 8; ch++) {
        if (ch < 6) { CP_WAIT(1); } else { CP_WAIT(0); }
        __syncthreads();
        const float* As_ = As + (ch & 1) * 4608;
        const float* Bs_ = Bs + (ch & 1) * 4224;
        #pragma unroll
        for (int k8 = 0; k8 < 32; k8 += 8) {
            uint32_t a[2][4], bb[8][2];
            #pragma unroll
            for (int mt = 0; mt < 2; mt++) {
                const float* ap = As_ + (wm * 32 + mt * 16 + (lane >> 2)) * 36 + k8 + (lane & 3);
                a[mt][0] = ld_tf32(ap);
                a[mt][1] = ld_tf32(ap + 8 * 36);
                a[mt][2] = ld_tf32(ap + 4);
                a[mt][3] = ld_tf32(ap + 8 * 36 + 4);
            }
            #pragma unroll
            for (int nt = 0; nt < 8; nt++) {
                const float* bp = Bs_ + (k8 + (lane & 3)) * 132 + wn * 64 + nt * 8 + (lane >> 2);
                bb[nt][0] = ld_tf32(bp);
                bb[nt][1] = ld_tf32(bp + 4 * 132);
            }
            #pragma unroll
            for (int mt = 0; mt < 2; mt++)
                #pragma unroll
                for (int nt = 0; nt < 8; nt++)
                    mma_tf32(acc[mt][nt], a[mt][0], a[mt][1], a[mt][2], a[mt][3],
                             bb[nt][0], bb[nt][1]);
        }
        __syncthreads();
        if (ch + 2 < 8) {
            int s = ch & 1;
            #pragma unroll
            for (int jj = 0; jj < 4; jj++) {
                int idx = tid + 256 * jj;
                int r = idx >> 3, kq = (idx & 7) * 4;
                cp16(smu_a + (s * 4608 + r * 36 + kq) * 4,
                     Ag + (long)r * C_ + (ch + 2) * 32 + kq);
                int kk = idx >> 5, nq = (idx & 31) * 4;
                cp16(smu_b + (s * 4224 + kk * 132 + nq) * 4,
                     Bg + (long)((ch + 2) * 32 + kk) * N_ + nq);
            }
            CP_COMMIT();
        }
    }

    __nv_bfloat16* Ob = Out + sO * b;
    #pragma unroll
    for (int mt = 0; mt < 2; mt++) {
        int row = m0 + wm * 32 + mt * 16 + (lane >> 2);
        float bv = bias[row], bv8 = bias[row + 8];
        #pragma unroll
        for (int nt = 0; nt < 8; nt++) {
            int col = n0 + wn * 64 + nt * 8 + 2 * (lane & 3);
            long o = (long)row * N_ + col;
            *(__nv_bfloat162*)(Ob + o) =
                __floats2bfloat162_rn(acc[mt][nt][0] + bv, acc[mt][nt][1] + bv);
            *(__nv_bfloat162*)(Ob + o + 8 * N_) =
                __floats2bfloat162_rn(acc[mt][nt][2] + bv8, acc[mt][nt][3] + bv8);
        }
    }
}

// =================================================================
// xxT_mma: split-K channel-logits partials (tf32 mma, NT)
// =================================================================
#define XT_SMEM_BYTES ((2 * 128 * 36 * 2) * 4)   // 73728

__global__ void __launch_bounds__(256)
xxT_mma(const float* __restrict__ x, float* __restrict__ part) {
    extern __shared__ float sm[];
    float* Asm = sm;
    float* Bsm = sm + 2 * 128 * 36;
    int tid = threadIdx.x, lane = tid & 31, wid = tid >> 5;
    int wm = wid & 3, wn = wid >> 2;
    int z = blockIdx.z, b = z >> 3, ks = z & 7;
    int m0 = blockIdx.y * 128, n0 = blockIdx.x * 128;
    const float* Ag = x + (long)b * C_ * N_ + (long)m0 * N_ + ks * 512;
    const float* Bg = x + (long)b * C_ * N_ + (long)n0 * N_ + ks * 512;
    uint32_t smu_a = smem_to_u32(Asm), smu_b = smem_to_u32(Bsm);
    float c[2][8][4] = {};

    #pragma unroll
    for (int s = 0; s < 2; s++) {
        int k0 = s * 32;
        #pragma unroll
        for (int j = 0; j < 4; j++) {
            int f = tid + 256 * j;
            int r = f >> 3, q = (f & 7) * 4;
            cp16(smu_a + (s * 4608 + r * 36 + q) * 4, Ag + (long)r * N_ + k0 + q);
            cp16(smu_b + (s * 4608 + r * 36 + q) * 4, Bg + (long)r * N_ + k0 + q);
        }
        CP_COMMIT();
    }

    for (int ch = 0; ch < 16; ch++) {
        if (ch < 14) { CP_WAIT(1); } else { CP_WAIT(0); }
        __syncthreads();
        const float* As_ = Asm + (ch & 1) * 4608;
        const float* Bs_ = Bsm + (ch & 1) * 4608;
        #pragma unroll
        for (int k8 = 0; k8 < 32; k8 += 8) {
            uint32_t a[2][4], bb[8][2];
            #pragma unroll
            for (int mt = 0; mt < 2; mt++) {
                const float* ap = As_ + (wm * 32 + mt * 16 + (lane >> 2)) * 36 + k8 + (lane & 3);
                a[mt][0] = ld_tf32(ap);
                a[mt][1] = ld_tf32(ap + 8 * 36);
                a[mt][2] = ld_tf32(ap + 4);
                a[mt][3] = ld_tf32(ap + 8 * 36 + 4);
            }
            #pragma unroll
            for (int nt = 0; nt < 8; nt++) {
                const float* bp = Bs_ + (wn * 64 + nt * 8 + (lane >> 2)) * 36 + k8 + (lane & 3);
                bb[nt][0] = ld_tf32(bp);
                bb[nt][1] = ld_tf32(bp + 4);
            }
            #pragma unroll
            for (int mt = 0; mt < 2; mt++)
                #pragma unroll
                for (int nt = 0; nt < 8; nt++)
                    mma_tf32(c[mt][nt], a[mt][0], a[mt][1], a[mt][2], a[mt][3],
                             bb[nt][0], bb[nt][1]);
        }
        __syncthreads();
        if (ch + 2 < 16) {
            int s = ch & 1;
            int k0 = (ch + 2) * 32;
            #pragma unroll
            for (int j = 0; j < 4; j++) {
                int f = tid + 256 * j;
                int r = f >> 3, q = (f & 7) * 4;
                cp16(smu_a + (s * 4608 + r * 36 + q) * 4, Ag + (long)r * N_ + k0 + q);
                cp16(smu_b + (s * 4608 + r * 36 + q) * 4, Bg + (long)r * N_ + k0 + q);
            }
            CP_COMMIT();
        }
    }

    float* Ob = part + (long)z * C_ * C_;
    #pragma unroll
    for (int mt = 0; mt < 2; mt++) {
        int row = m0 + wm * 32 + mt * 16 + (lane >> 2);
        #pragma unroll
        for (int nt = 0; nt < 8; nt++) {
            int col = n0 + wn * 64 + nt * 8 + 2 * (lane & 3);
            long o = (long)row * C_ + col;
            *(float2*)(Ob + o) = make_float2(c[mt][nt][0], c[mt][nt][1]);
            *(float2*)(Ob + o + 8 * C_) = make_float2(c[mt][nt][2], c[mt][nt][3]);
        }
    }
}

// =================================================================
// NN-GEMM (tf32 mma): Out[m][n] = sum_k A[m][k] * B[k][n]  (ca apply)
// =================================================================
__global__ void __launch_bounds__(256)
gemm_nn_mma(const float* __restrict__ A, const float* __restrict__ B,
            float* __restrict__ Out, int K, int epi,
            const float* __restrict__ bias, const float* __restrict__ gsc,
            const float* __restrict__ res,
            long sA, long sB, long sO, long sR) {
    extern __shared__ float sm[];
    float* As = sm;
    float* Bs = sm + 2 * 128 * 36;
    int tid = threadIdx.x, lane = tid & 31, w = tid >> 5;
    int wm = w & 3, wn = w >> 2;
    int b = blockIdx.z, m0 = blockIdx.y * 128, n0 = blockIdx.x * 128;
    const float* Ag = A + sA * b + (long)m0 * K;
    const float* Bg = B + sB * b + n0;
    uint32_t smu_a = smem_to_u32(As), smu_b = smem_to_u32(Bs);
    float acc[2][8][4] = {};
    int nchunks = K / 32;

    #pragma unroll
    for (int s = 0; s < 2; s++) {
        #pragma unroll
        for (int jj = 0; jj < 4; jj++) {
            int idx = tid + 256 * jj;
            int r = idx >> 3, kq = (idx & 7) * 4;
            cp16(smu_a + (s * 4608 + r * 36 + kq) * 4, Ag + (long)r * K + s * 32 + kq);
            int kk = idx >> 5, nq = (idx & 31) * 4;
            cp16(smu_b + (s * 4224 + kk * 132 + nq) * 4, Bg + (long)(s * 32 + kk) * N_ + nq);
        }
        CP_COMMIT();
    }

    for (int ch = 0; ch < nchunks; ch++) {
        if (ch < nchunks - 2) { CP_WAIT(1); } else { CP_WAIT(0); }
        __syncthreads();
        const float* As_ = As + (ch & 1) * 4608;
        const float* Bs_ = Bs + (ch & 1) * 4224;
        #pragma unroll
        for (int k8 = 0; k8 < 32; k8 += 8) {
            uint32_t a[2][4], bb[8][2];
            #pragma unroll
            for (int mt = 0; mt < 2; mt++) {
                const float* ap = As_ + (wm * 32 + mt * 16 + (lane >> 2)) * 36 + k8 + (lane & 3);
                a[mt][0] = ld_tf32(ap);
                a[mt][1] = ld_tf32(ap + 8 * 36);
                a[mt][2] = ld_tf32(ap + 4);
                a[mt][3] = ld_tf32(ap + 8 * 36 + 4);
            }
            #pragma unroll
            for (int nt = 0; nt < 8; nt++) {
                const float* bp = Bs_ + (k8 + (lane & 3)) * 132 + wn * 64 + nt * 8 + (lane >> 2);
                bb[nt][0] = ld_tf32(bp);
                bb[nt][1] = ld_tf32(bp + 4 * 132);
            }
            #pragma unroll
            for (int mt = 0; mt < 2; mt++)
                #pragma unroll
                for (int nt = 0; nt < 8; nt++)
                    mma_tf32(acc[mt][nt], a[mt][0], a[mt][1], a[mt][2], a[mt][3],
                             bb[nt][0], bb[nt][1]);
        }
        __syncthreads();
        if (ch + 2 < nchunks) {
            int s = ch & 1;
            #pragma unroll
            for (int jj = 0; jj < 4; jj++) {
                int idx = tid + 256 * jj;
                int r = idx >> 3, kq = (idx & 7) * 4;
                cp16(smu_a + (s * 4608 + r * 36 + kq) * 4,
                     Ag + (long)r * K + (ch + 2) * 32 + kq);
                int kk = idx >> 5, nq = (idx & 31) * 4;
                cp16(smu_b + (s * 4224 + kk * 132 + nq) * 4,
                     Bg + (long)((ch + 2) * 32 + kk) * N_ + nq);
            }
            CP_COMMIT();
        }
    }

    float g = gsc ? *gsc : 0.f;
    const float* resb = res ? res + sR * b : nullptr;
    float* Ob = Out + sO * b;
    #pragma unroll
    for (int mt = 0; mt < 2; mt++) {
        int row = m0 + wm * 32 + mt * 16 + (lane >> 2);
        #pragma unroll
        for (int nt = 0; nt < 8; nt++) {
            int col = n0 + wn * 64 + nt * 8 + 2 * (lane & 3);
            long o = (long)row * N_ + col;
            if (epi == 0) {
                float bv = bias[row], bv8 = bias[row + 8];
                *(float2*)(Ob + o) = make_float2(acc[mt][nt][0] + bv, acc[mt][nt][1] + bv);
                *(float2*)(Ob + o + 8 * N_) =
                    make_float2(acc[mt][nt][2] + bv8, acc[mt][nt][3] + bv8);
            } else {
                *(float2*)(Ob + o) = make_float2(
                    fmaf(g, acc[mt][nt][0], resb[o]), fmaf(g, acc[mt][nt][1], resb[o + 1]));
                *(float2*)(Ob + o + 8 * N_) = make_float2(
                    fmaf(g, acc[mt][nt][2], resb[o + 8 * N_]),
                    fmaf(g, acc[mt][nt][3], resb[o + 8 * N_ + 1]));
            }
        }
    }
}

// =================================================================
// 3x3 conv 512 -> 256, implicit GEMM v3 (tf32 mma), M=256
// =================================================================
#define CV_AS_FLOATS  (256 * 76)
#define CV_PT_FLOATS  (8 * 296)
#define CV_SMEM_BYTES ((2 * CV_AS_FLOATS + 2 * CV_PT_FLOATS) * 4)   // 174592

__global__ void __launch_bounds__(256, 1)
conv_mma(const float* __restrict__ cat, const float* __restrict__ wf,
         float* __restrict__ y) {
    extern __shared__ float sm[];
    float* Asm = sm;
    float* Pt = sm + 2 * CV_AS_FLOATS;
    int tid = threadIdx.x, lane = tid & 31, wid = tid >> 5;
    int wm = wid & 3, wn = wid >> 2;
    int b = blockIdx.z, p0 = blockIdx.x * 128;
    int h0 = blockIdx.x * 2;
    uint32_t smu_a = smem_to_u32(Asm), smu_p = smem_to_u32(Pt);

    for (int i = tid; i < 2 * CV_PT_FLOATS; i += 256) Pt[i] = 0.f;
    __syncthreads();

    float c[4][8][4] = {};

    #pragma unroll
    for (int s = 0; s < 2; s++) {
        #pragma unroll
        for (int j = 0; j < 18; j++) {
            int f = tid + 256 * j;
            int r = f / 18, q = (f % 18) * 4;
            cp16(smu_a + (s * CV_AS_FLOATS + r * 76 + q) * 4,
                 wf + (long)r * 4608 + s * 72 + q);
        }
        #pragma unroll
        for (int j = 0; j < 2; j++) {
            int f = tid + 256 * j;
            int ci = f >> 6, rq = (f >> 4) & 3, q = (f & 15) * 4;
            int h = h0 - 1 + rq;
            if (h >= 0 && h < 64)
                cp16(smu_p + (s * CV_PT_FLOATS + ci * 296 + rq * 72 + 4 + q) * 4,
                     cat + ((long)b * 512 + s * 8 + ci) * 4096 + h * 64 + q);
        }
        CP_COMMIT();
    }

    for (int chunk = 0; chunk < 64; chunk++) {
        if (chunk < 62) { CP_WAIT(1); } else { CP_WAIT(0); }
        __syncthreads();
        const float* As_ = Asm + (chunk & 1) * CV_AS_FLOATS;
        const float* Pt_ = Pt + (chunk & 1) * CV_PT_FLOATS;

        #pragma unroll
        for (int pos = 0; pos < 9; pos++) {
            const int kh = pos / 3, kw = pos % 3;
            uint32_t a[4][4], bb[8][2];
            #pragma unroll
            for (int mt = 0; mt < 4; mt++) {
                const float* ap = As_ + (wm * 64 + mt * 16 + (lane >> 2)) * 76
                                  + (lane & 3) * 9 + pos;
                a[mt][0] = ld_tf32(ap);
                a[mt][1] = ld_tf32(ap + 8 * 76);
                a[mt][2] = ld_tf32(ap + 36);
                a[mt][3] = ld_tf32(ap + 8 * 76 + 36);
            }
            {
                int nbase = wn * 64 + (lane >> 2);
                int hh = nbase >> 6;
                const float* pb = Pt_ + (lane & 3) * 296 + (hh + kh) * 72;
                #pragma unroll
                for (int nt = 0; nt < 8; nt++) {
                    int wpos = ((nbase + nt * 8) & 63) + kw + 3;
                    bb[nt][0] = ld_tf32(pb + wpos);
                    bb[nt][1] = ld_tf32(pb + 4 * 296 + wpos);
                }
            }
            #pragma unroll
            for (int mt = 0; mt < 4; mt++)
                #pragma unroll
                for (int nt = 0; nt < 8; nt++)
                    mma_tf32(c[mt][nt], a[mt][0], a[mt][1], a[mt][2], a[mt][3],
                             bb[nt][0], bb[nt][1]);
        }
        __syncthreads();
        if (chunk + 2 < 64) {
            int s = chunk & 1;
            #pragma unroll
            for (int j = 0; j < 18; j++) {
                int f = tid + 256 * j;
                int r = f / 18, q = (f % 18) * 4;
                cp16(smu_a + (s * CV_AS_FLOATS + r * 76 + q) * 4,
                     wf + (long)r * 4608 + (chunk + 2) * 72 + q);
            }
            #pragma unroll
            for (int j = 0; j < 2; j++) {
                int f = tid + 256 * j;
                int ci = f >> 6, rq = (f >> 4) & 3, q = (f & 15) * 4;
                int h = h0 - 1 + rq;
                if (h >= 0 && h < 64)
                    cp16(smu_p + (s * CV_PT_FLOATS + ci * 296 + rq * 72 + 4 + q) * 4,
                         cat + ((long)b * 512 + (chunk + 2) * 8 + ci) * 4096 + h * 64 + q);
            }
            CP_COMMIT();
        }
    }

    #pragma unroll
    for (int mt = 0; mt < 4; mt++) {
        #pragma unroll
        for (int nt = 0; nt < 8; nt++) {
            int row = wm * 64 + mt * 16 + (lane >> 2);
            int col = p0 + wn * 64 + nt * 8 + 2 * (lane & 3);
            long yo = ((long)b * 256 + row) * 4096 + col;
            *(float2*)(y + yo) = make_float2(c[mt][nt][0], c[mt][nt][1]);
            *(float2*)(y + yo + 8 * 4096) = make_float2(c[mt][nt][2], c[mt][nt][3]);
        }
    }
}

// ---------------- helpers ----------------
__device__ __forceinline__ float warpMax(float v) {
    #pragma unroll
    for (int o = 16; o; o >>= 1) v = fmaxf(v, __shfl_xor_sync(0xffffffffu, v, o));
    return v;
}
__device__ __forceinline__ float warpSum(float v) {
    #pragma unroll
    for (int o = 16; o; o >>= 1) v += __shfl_xor_sync(0xffffffffu, v, o);
    return v;
}

// ---------------- merged q+k projection (fp32 SIMT, M=64) ----------------
__global__ void qk_proj(const float* __restrict__ wq, const float* __restrict__ bq,
                        const float* __restrict__ wk, const float* __restrict__ bk,
                        const float* __restrict__ x, float* __restrict__ q,
                        float* __restrict__ k) {
    __shared__ float As[16][64];
    __shared__ float Bs[16][64];
    int b = blockIdx.z;
    const float* Bm = x + (long)b * C_ * N_;
    int tid = threadIdx.x;
    int tx = tid & 15, ty = tid >> 4;
    int n0 = blockIdx.x * 64;
    int arow = tid >> 2, ak = (tid & 3) * 4;
    int brow = tid >> 4, bn = (tid & 15) * 4;
    const float* Arow = (arow < 32) ? (wq + (long)arow * C_)
                                    : (wk + (long)(arow - 32) * C_);
    float acc[4][4] = {};
    for (int k0 = 0; k0 < C_; k0 += 16) {
        float4 av = *(const float4*)(Arow + k0 + ak);
        As[ak + 0][arow] = av.x; As[ak + 1][arow] = av.y;
        As[ak + 2][arow] = av.z; As[ak + 3][arow] = av.w;
        *(float4*)&Bs[brow][bn] = *(const float4*)(Bm + (long)(k0 + brow) * N_ + n0 + bn);
        __syncthreads();
        #pragma unroll
        for (int kk = 0; kk < 16; kk++) {
            float4 a = *(const float4*)&As[kk][ty * 4];
            float4 bv = *(const float4*)&Bs[kk][tx * 4];
            float ar[4] = {a.x, a.y, a.z, a.w};
            float br[4] = {bv.x, bv.y, bv.z, bv.w};
            #pragma unroll
            for (int i = 0; i < 4; i++)
                #pragma unroll
                for (int j = 0; j < 4; j++)
                    acc[i][j] = fmaf(ar[i], br[j], acc[i][j]);
        }
        __syncthreads();
    }
    #pragma unroll
    for (int i = 0; i < 4; i++) {
        int m = ty * 4 + i;
        float bv = (m < 32) ? bq[m] : bk[m - 32];
        float* Out = (m < 32) ? (q + ((long)b * CQ_ + m) * N_)
                              : (k + ((long)b * CQ_ + m - 32) * N_);
        *(float4*)(Out + n0 + tx * 4) = make_float4(
            acc[i][0] + bv, acc[i][1] + bv, acc[i][2] + bv, acc[i][3] + bv);
    }
}

// ---------------- softmax over 256 with split-K reduction ----------------
__global__ void softmax256(const float* __restrict__ part, float* __restrict__ out) {
    __shared__ float sh[8];
    int tid = threadIdx.x;
    int row = blockIdx.x;
    int b = row >> 8, i = row & 255;
    float v = 0.f;
    #pragma unroll
    for (int ks = 0; ks < 8; ks++)
        v += part[((long)(b * 8 + ks) * C_ + i) * C_ + tid];
    float m = warpMax(v);
    if ((tid & 31) == 0) sh[tid >> 5] = m;
    __syncthreads();
    m = sh[tid & 7];
    #pragma unroll
    for (int o = 4; o; o >>= 1) m = fmaxf(m, __shfl_xor_sync(0xffffffffu, m, o));
    __syncthreads();
    float e = __expf(v - m);
    float s = warpSum(e);
    if ((tid & 31) == 0) sh[tid >> 5] = s;
    __syncthreads();
    s = sh[tid & 7];
    #pragma unroll
    for (int o = 4; o; o >>= 1) s += __shfl_xor_sync(0xffffffffu, s, o);
    out[(long)row * 256 + tid] = e / s;
}

// ---------------- BN (train-mode batch stats) + ReLU ----------------
__global__ void bnstats(const float* __restrict__ y, float* __restrict__ meanp,
                        float* __restrict__ rstdp) {
    __shared__ float sh[16];
    int o = blockIdx.x, tid = threadIdx.x;
    float s = 0.f, sq = 0.f;
    for (int b = 0; b < 4; b++) {
        const float4* p = (const float4*)(y + ((size_t)b * 256 + o) * 4096);
        for (int i = tid; i < 1024; i += 256) {
            float4 v = p[i];
            s += v.x + v.y + v.z + v.w;
            sq += v.x * v.x + v.y * v.y + v.z * v.z + v.w * v.w;
        }
    }
    s = warpSum(s); sq = warpSum(sq);
    if ((tid & 31) == 0) { sh[tid >> 5] = s; sh[8 + (tid >> 5)] = sq; }
    __syncthreads();
    if (tid == 0) {
        float S = 0.f, SQ = 0.f;
        for (int i = 0; i < 8; i++) { S += sh[i]; SQ += sh[8 + i]; }
        float mean = S / 16384.f;
        float var = SQ / 16384.f - mean * mean;
        meanp[o] = mean;
        rstdp[o] = rsqrtf(var + 1e-5f);
    }
}

__global__ void bnapply(const float* __restrict__ y, const float* __restrict__ gam,
                        const float* __restrict__ bet, const float* __restrict__ meanp,
                        const float* __restrict__ rstdp, float* __restrict__ out) {
    size_t i = (size_t)blockIdx.x * 256 + threadIdx.x;
    int o = (int)((i >> 10) & 255);
    float mu = meanp[o], rs = rstdp[o], g = gam[o], be = bet[o];
    float4 v = ((const float4*)y)[i];
    float4 r;
    r.x = fmaxf(0.f, fmaf((v.x - mu) * rs, g, be));
    r.y = fmaxf(0.f, fmaf((v.y - mu) * rs, g, be));
    r.z = fmaxf(0.f, fmaf((v.z - mu) * rs, g, be));
    r.w = fmaxf(0.f, fmaf((v.w - mu) * rs, g, be));
    ((float4*)out)[i] = r;
}

// ---------------- launcher ----------------
extern "C" void kernel_launch(void* const* d_in, const int* in_sizes, int n_in,
                              void* d_out, int out_size) {
    const float* x   = (const float*)d_in[0];
    const float* wq  = (const float*)d_in[1];
    const float* bq  = (const float*)d_in[2];
    const float* wk  = (const float*)d_in[3];
    const float* bk  = (const float*)d_in[4];
    const float* wv  = (const float*)d_in[5];
    const float* bv  = (const float*)d_in[6];
    const float* gpa = (const float*)d_in[7];
    const float* gca = (const float*)d_in[8];
    const float* wf  = (const float*)d_in[9];
    const float* bng = (const float*)d_in[10];
    const float* bnb = (const float*)d_in[11];
    float* out = (float*)d_out;

    float *q, *k, *cat, *cattn, *cattn_part, *y, *mean, *rstd;
    __nv_bfloat16* v;
    cudaGetSymbolAddress((void**)&q, g_q);
    cudaGetSymbolAddress((void**)&k, g_k);
    cudaGetSymbolAddress((void**)&v, g_v);
    cudaGetSymbolAddress((void**)&cat, g_cat);
    cudaGetSymbolAddress((void**)&cattn, g_cattn);
    cudaGetSymbolAddress((void**)&cattn_part, g_cattn_part);
    cudaGetSymbolAddress((void**)&y, g_y);
    cudaGetSymbolAddress((void**)&mean, g_mean);
    cudaGetSymbolAddress((void**)&rstd, g_rstd);

    cudaFuncSetAttribute(pa_flash, cudaFuncAttributeMaxDynamicSharedMemorySize,
                         PF_SMEM_BYTES);
    cudaFuncSetAttribute(v_proj, cudaFuncAttributeMaxDynamicSharedMemorySize,
                         NN_SMEM_BYTES);
    cudaFuncSetAttribute(gemm_nn_mma, cudaFuncAttributeMaxDynamicSharedMemorySize,
                         NN_SMEM_BYTES);
    cudaFuncSetAttribute(xxT_mma, cudaFuncAttributeMaxDynamicSharedMemorySize,
                         XT_SMEM_BYTES);
    cudaFuncSetAttribute(conv_mma, cudaFuncAttributeMaxDynamicSharedMemorySize,
                         CV_SMEM_BYTES);

    dim3 blk(256);
    long sx = (long)C_ * N_;
    long scat = (long)2 * C_ * N_;

    // q + k projections in one kernel
    qk_proj<<<dim3(64, 1, 4), blk>>>(wq, bq, wk, bk, x, q, k);
    // v projection on tensor cores, bf16 output
    v_proj<<<dim3(32, 2, 4), blk, NN_SMEM_BYTES>>>(wv, x, v, bv, sx, sx);
    // fused flash position-attention (PV in bf16) -> cat[:, 0:256]
    pa_flash<<<dim3(32, 1, 4), blk, PF_SMEM_BYTES>>>(q, k, v, x, gpa, cat);
    // channel attention: split-K x.xT partials, fused-reduce softmax, apply
    xxT_mma<<<dim3(2, 2, 32), blk, XT_SMEM_BYTES>>>(x, cattn_part);
    softmax256<<<B_ * C_, 256>>>(cattn_part, cattn);
    gemm_nn_mma<<<dim3(32, 2, 4), blk, NN_SMEM_BYTES>>>(
        cattn, x, cat + (size_t)C_ * N_, C_, 1, nullptr, gca, x,
        (long)C_ * C_, sx, scat, sx);
    // 3x3 conv 512->256 (implicit GEMM v3, M=256, tf32)
    conv_mma<<<dim3(32, 1, 4), blk, CV_SMEM_BYTES>>>(cat, wf, y);
    // BN train-mode + ReLU
    bnstats<<<256, 256>>>(y, mean, rstd);
    bnapply<<<4096, 256>>>(y, bng, bnb, mean, rstd, out);
}

// round 13
// speedup vs baseline: 3.9556x; 1.2414x over previous
#include <cuda_runtime.h>
#include <cuda_bf16.h>
#include <cuda_fp16.h>
#include <cstdint>

#define B_  4
#define C_  256
#define CQ_ 32
#define N_  4096
#define HW_ 64

// ---------------- scratch (device globals; no allocation) ----------------
__device__ float g_q[B_ * CQ_ * N_];
__device__ float g_k[B_ * CQ_ * N_];
__device__ __nv_bfloat16 g_v[B_ * C_ * N_];              // bf16 v
__device__ float g_cat[(size_t)B_ * 2 * C_ * N_];        // [b][512][4096] fp32
__device__ __half g_catsh[(size_t)B_ * N_ * 2 * C_];     // [b][4096][512] fp16 NHWC
__device__ __half g_wfh[C_ * 2 * C_ * 9];                // reordered fp16 weights
__device__ float g_cattn_part[32 * C_ * C_];             // split-K partials
__device__ float g_cattn[B_ * C_ * C_];
__device__ float g_y[(size_t)B_ * C_ * N_];
__device__ float g_mean[C_];
__device__ float g_rstd[C_];

// ---------------- PTX helpers (sm_80+ mma.sync / cp.async) ----------------
__device__ __forceinline__ uint32_t smem_to_u32(const void* p) {
    uint32_t a;
    asm("{ .reg .u64 t; cvta.to.shared.u64 t, %1; cvt.u32.u64 %0, t; }" : "=r"(a) : "l"(p));
    return a;
}
__device__ __forceinline__ void cp16(uint32_t dst, const void* src) {
    asm volatile("cp.async.cg.shared.global [%0], [%1], 16;" :: "r"(dst), "l"(src));
}
#define CP_COMMIT() asm volatile("cp.async.commit_group;" ::: "memory")
#define CP_WAIT(n)  asm volatile("cp.async.wait_group %0;" :: "n"(n) : "memory")

__device__ __forceinline__ uint32_t ld_tf32(const float* p) {
    uint32_t r;
    float f = *p;
    asm("cvt.rna.tf32.f32 %0, %1;" : "=r"(r) : "f"(f));
    return r;
}
__device__ __forceinline__ void mma_tf32(float c[4], uint32_t a0, uint32_t a1,
                                         uint32_t a2, uint32_t a3,
                                         uint32_t b0, uint32_t b1) {
    asm volatile(
        "mma.sync.aligned.m16n8k8.row.col.f32.tf32.tf32.f32 "
        "{%0,%1,%2,%3}, {%4,%5,%6,%7}, {%8,%9}, {%0,%1,%2,%3};"
        : "+f"(c[0]), "+f"(c[1]), "+f"(c[2]), "+f"(c[3])
        : "r"(a0), "r"(a1), "r"(a2), "r"(a3), "r"(b0), "r"(b1));
}
__device__ __forceinline__ void mma_bf16(float c[4], uint32_t a0, uint32_t a1,
                                         uint32_t a2, uint32_t a3,
                                         uint32_t b0, uint32_t b1) {
    asm volatile(
        "mma.sync.aligned.m16n8k16.row.col.f32.bf16.bf16.f32 "
        "{%0,%1,%2,%3}, {%4,%5,%6,%7}, {%8,%9}, {%0,%1,%2,%3};"
        : "+f"(c[0]), "+f"(c[1]), "+f"(c[2]), "+f"(c[3])
        : "r"(a0), "r"(a1), "r"(a2), "r"(a3), "r"(b0), "r"(b1));
}
__device__ __forceinline__ void mma_f16(float c[4], uint32_t a0, uint32_t a1,
                                        uint32_t a2, uint32_t a3,
                                        uint32_t b0, uint32_t b1) {
    asm volatile(
        "mma.sync.aligned.m16n8k16.row.col.f32.f16.f16.f32 "
        "{%0,%1,%2,%3}, {%4,%5,%6,%7}, {%8,%9}, {%0,%1,%2,%3};"
        : "+f"(c[0]), "+f"(c[1]), "+f"(c[2]), "+f"(c[3])
        : "r"(a0), "r"(a1), "r"(a2), "r"(a3), "r"(b0), "r"(b1));
}

// =================================================================
// pa_flash v2: fused attention, PV on bf16 m16n8k16.  (unchanged R12)
// =================================================================
#define PF_AS  (256 * 40)
#define PF_KS  (32 * 36)
#define PF_SMEM_BYTES (2 * PF_AS * 2 + 2 * PF_KS * 4 + 128 * 40 * 2)  // 60416

__global__ void __launch_bounds__(256, 1)
pa_flash(const float* __restrict__ qg, const float* __restrict__ kg,
         const __nv_bfloat16* __restrict__ v, const float* __restrict__ x,
         const float* __restrict__ gpa, float* __restrict__ cat) {
    extern __shared__ char smc[];
    __nv_bfloat16* Avs = (__nv_bfloat16*)smc;
    float* Ksm = (float*)(smc + 2 * PF_AS * 2);
    __nv_bfloat16* Ps = (__nv_bfloat16*)(smc + 2 * PF_AS * 2 + 2 * PF_KS * 4);
    __shared__ float red[128];
    int tid = threadIdx.x, lane = tid & 31, w = tid >> 5;
    int wm = w & 3, wn = w >> 2;
    int b = blockIdx.z, I0 = blockIdx.x * 128;
    const float* Qg = qg + (long)b * CQ_ * N_;
    const float* Kg = kg + (long)b * CQ_ * N_;
    const __nv_bfloat16* Ag = v + (long)b * C_ * N_;
    uint32_t smu_a = smem_to_u32(Avs), smu_k = smem_to_u32(Ksm);

    uint32_t aq[4][4];
    {
        int i0 = I0 + w * 16 + (lane >> 2);
        #pragma unroll
        for (int k8 = 0; k8 < 4; k8++) {
            int d0 = k8 * 8 + (lane & 3);
            const float* qp = Qg + (long)d0 * N_ + i0;
            aq[k8][0] = ld_tf32(qp);
            aq[k8][1] = ld_tf32(qp + 8);
            aq[k8][2] = ld_tf32(qp + 4 * N_);
            aq[k8][3] = ld_tf32(qp + 4 * N_ + 8);
        }
    }

    float c[4][8][4] = {};
    float lsum0 = 0.f, lsum1 = 0.f;

    #pragma unroll
    for (int s = 0; s < 2; s++) {
        int j0 = s * 32;
        #pragma unroll
        for (int j = 0; j < 4; j++) {
            int f = tid + 256 * j;
            int r = f >> 2, q = (f & 3) * 8;
            cp16(smu_a + (s * PF_AS + r * 40 + q) * 2, Ag + (long)r * N_ + j0 + q);
        }
        cp16(smu_k + (s * PF_KS + (tid >> 3) * 36 + (tid & 7) * 4) * 4,
             Kg + (long)(tid >> 3) * N_ + j0 + (tid & 7) * 4);
        CP_COMMIT();
    }

    for (int ch = 0; ch < 128; ch++) {
        if (ch < 126) { CP_WAIT(1); } else { CP_WAIT(0); }
        __syncthreads();
        const __nv_bfloat16* As_ = Avs + (ch & 1) * PF_AS;
        const float* Ks_ = Ksm + (ch & 1) * PF_KS;

        float s4[4][4] = {};
        #pragma unroll
        for (int k8 = 0; k8 < 4; k8++) {
            int d0 = k8 * 8 + (lane & 3);
            #pragma unroll
            for (int nt = 0; nt < 4; nt++) {
                uint32_t b0 = ld_tf32(&Ks_[d0 * 36 + nt * 8 + (lane >> 2)]);
                uint32_t b1 = ld_tf32(&Ks_[(d0 + 4) * 36 + nt * 8 + (lane >> 2)]);
                mma_tf32(s4[nt], aq[k8][0], aq[k8][1], aq[k8][2], aq[k8][3], b0, b1);
            }
        }
        {
            int r0 = (w * 16 + (lane >> 2)) * 40 + 2 * (lane & 3);
            #pragma unroll
            for (int nt = 0; nt < 4; nt++) {
                float p0 = __expf(s4[nt][0]), p1 = __expf(s4[nt][1]);
                float p2 = __expf(s4[nt][2]), p3 = __expf(s4[nt][3]);
                lsum0 += p0 + p1;
                lsum1 += p2 + p3;
                *(__nv_bfloat162*)&Ps[r0 + nt * 8] = __floats2bfloat162_rn(p0, p1);
                *(__nv_bfloat162*)&Ps[r0 + 8 * 40 + nt * 8] = __floats2bfloat162_rn(p2, p3);
            }
        }
        __syncthreads();
        #pragma unroll
        for (int ks = 0; ks < 2; ks++) {
            int k0 = ks * 16;
            uint32_t a[4][4], bb[8][2];
            #pragma unroll
            for (int mt = 0; mt < 4; mt++) {
                const __nv_bfloat16* ap = As_ + (wm * 64 + mt * 16 + (lane >> 2)) * 40
                                          + k0 + 2 * (lane & 3);
                a[mt][0] = *(const uint32_t*)ap;
                a[mt][1] = *(const uint32_t*)(ap + 8 * 40);
                a[mt][2] = *(const uint32_t*)(ap + 8);
                a[mt][3] = *(const uint32_t*)(ap + 8 * 40 + 8);
            }
            #pragma unroll
            for (int nt = 0; nt < 8; nt++) {
                const __nv_bfloat16* bp = Ps + (wn * 64 + nt * 8 + (lane >> 2)) * 40
                                          + k0 + 2 * (lane & 3);
                bb[nt][0] = *(const uint32_t*)bp;
                bb[nt][1] = *(const uint32_t*)(bp + 8);
            }
            #pragma unroll
            for (int mt = 0; mt < 4; mt++)
                #pragma unroll
                for (int nt = 0; nt < 8; nt++)
                    mma_bf16(c[mt][nt], a[mt][0], a[mt][1], a[mt][2], a[mt][3],
                             bb[nt][0], bb[nt][1]);
        }
        __syncthreads();
        if (ch + 2 < 128) {
            int s = ch & 1;
            int j0 = (ch + 2) * 32;
            #pragma unroll
            for (int j = 0; j < 4; j++) {
                int f = tid + 256 * j;
                int r = f >> 2, q = (f & 3) * 8;
                cp16(smu_a + (s * PF_AS + r * 40 + q) * 2, Ag + (long)r * N_ + j0 + q);
            }
            cp16(smu_k + (s * PF_KS + (tid >> 3) * 36 + (tid & 7) * 4) * 4,
                 Kg + (long)(tid >> 3) * N_ + j0 + (tid & 7) * 4);
            CP_COMMIT();
        }
    }

    lsum0 += __shfl_xor_sync(0xffffffffu, lsum0, 1);
    lsum0 += __shfl_xor_sync(0xffffffffu, lsum0, 2);
    lsum1 += __shfl_xor_sync(0xffffffffu, lsum1, 1);
    lsum1 += __shfl_xor_sync(0xffffffffu, lsum1, 2);
    if ((lane & 3) == 0) {
        red[w * 16 + (lane >> 2)] = lsum0;
        red[w * 16 + 8 + (lane >> 2)] = lsum1;
    }
    __syncthreads();

    float g = gpa[0];
    #pragma unroll
    for (int nt = 0; nt < 8; nt++) {
        int cl = wn * 64 + nt * 8 + 2 * (lane & 3);
        float inv0 = 1.f / red[cl];
        float inv1 = 1.f / red[cl + 1];
        #pragma unroll
        for (int mt = 0; mt < 4; mt++) {
            int row = wm * 64 + mt * 16 + (lane >> 2);
            int col = I0 + cl;
            long xo = ((long)b * C_ + row) * N_ + col;
            long co = ((long)b * 2 * C_ + row) * N_ + col;
            *(float2*)(cat + co) = make_float2(
                fmaf(g, c[mt][nt][0] * inv0, x[xo]),
                fmaf(g, c[mt][nt][1] * inv1, x[xo + 1]));
            *(float2*)(cat + co + 8 * N_) = make_float2(
                fmaf(g, c[mt][nt][2] * inv0, x[xo + 8 * N_]),
                fmaf(g, c[mt][nt][3] * inv1, x[xo + 8 * N_ + 1]));
        }
    }
}

// =================================================================
// v_proj: NN-GEMM (tf32 mma) -> bf16 output.  (unchanged R12)
// =================================================================
#define NN_SMEM_BYTES ((2 * 128 * 36 + 2 * 32 * 132) * 4)   // 70656

__global__ void __launch_bounds__(256)
v_proj(const float* __restrict__ A, const float* __restrict__ B,
       __nv_bfloat16* __restrict__ Out, const float* __restrict__ bias,
       long sB, long sO) {
    extern __shared__ float sm[];
    float* As = sm;
    float* Bs = sm + 2 * 128 * 36;
    int tid = threadIdx.x, lane = tid & 31, w = tid >> 5;
    int wm = w & 3, wn = w >> 2;
    int b = blockIdx.z, m0 = blockIdx.y * 128, n0 = blockIdx.x * 128;
    const float* Ag = A + (long)m0 * C_;
    const float* Bg = B + sB * b + n0;
    uint32_t smu_a = smem_to_u32(As), smu_b = smem_to_u32(Bs);
    float acc[2][8][4] = {};

    #pragma unroll
    for (int s = 0; s < 2; s++) {
        #pragma unroll
        for (int jj = 0; jj < 4; jj++) {
            int idx = tid + 256 * jj;
            int r = idx >> 3, kq = (idx & 7) * 4;
            cp16(smu_a + (s * 4608 + r * 36 + kq) * 4, Ag + (long)r * C_ + s * 32 + kq);
            int kk = idx >> 5, nq = (idx & 31) * 4;
            cp16(smu_b + (s * 4224 + kk * 132 + nq) * 4, Bg + (long)(s * 32 + kk) * N_ + nq);
        }
        CP_COMMIT();
    }

    for (int ch = 0; ch < 8; ch++) {
        if (ch < 6) { CP_WAIT(1); } else { CP_WAIT(0); }
        __syncthreads();
        const float* As_ = As + (ch & 1) * 4608;
        const float* Bs_ = Bs + (ch & 1) * 4224;
        #pragma unroll
        for (int k8 = 0; k8 < 32; k8 += 8) {
            uint32_t a[2][4], bb[8][2];
            #pragma unroll
            for (int mt = 0; mt < 2; mt++) {
                const float* ap = As_ + (wm * 32 + mt * 16 + (lane >> 2)) * 36 + k8 + (lane & 3);
                a[mt][0] = ld_tf32(ap);
                a[mt][1] = ld_tf32(ap + 8 * 36);
                a[mt][2] = ld_tf32(ap + 4);
                a[mt][3] = ld_tf32(ap + 8 * 36 + 4);
            }
            #pragma unroll
            for (int nt = 0; nt < 8; nt++) {
                const float* bp = Bs_ + (k8 + (lane & 3)) * 132 + wn * 64 + nt * 8 + (lane >> 2);
                bb[nt][0] = ld_tf32(bp);
                bb[nt][1] = ld_tf32(bp + 4 * 132);
            }
            #pragma unroll
            for (int mt = 0; mt < 2; mt++)
                #pragma unroll
                for (int nt = 0; nt < 8; nt++)
                    mma_tf32(acc[mt][nt], a[mt][0], a[mt][1], a[mt][2], a[mt][3],
                             bb[nt][0], bb[nt][1]);
        }
        __syncthreads();
        if (ch + 2 < 8) {
            int s = ch & 1;
            #pragma unroll
            for (int jj = 0; jj < 4; jj++) {
                int idx = tid + 256 * jj;
                int r = idx >> 3, kq = (idx & 7) * 4;
                cp16(smu_a + (s * 4608 + r * 36 + kq) * 4,
                     Ag + (long)r * C_ + (ch + 2) * 32 + kq);
                int kk = idx >> 5, nq = (idx & 31) * 4;
                cp16(smu_b + (s * 4224 + kk * 132 + nq) * 4,
                     Bg + (long)((ch + 2) * 32 + kk) * N_ + nq);
            }
            CP_COMMIT();
        }
    }

    __nv_bfloat16* Ob = Out + sO * b;
    #pragma unroll
    for (int mt = 0; mt < 2; mt++) {
        int row = m0 + wm * 32 + mt * 16 + (lane >> 2);
        float bv = bias[row], bv8 = bias[row + 8];
        #pragma unroll
        for (int nt = 0; nt < 8; nt++) {
            int col = n0 + wn * 64 + nt * 8 + 2 * (lane & 3);
            long o = (long)row * N_ + col;
            *(__nv_bfloat162*)(Ob + o) =
                __floats2bfloat162_rn(acc[mt][nt][0] + bv, acc[mt][nt][1] + bv);
            *(__nv_bfloat162*)(Ob + o + 8 * N_) =
                __floats2bfloat162_rn(acc[mt][nt][2] + bv8, acc[mt][nt][3] + bv8);
        }
    }
}

// =================================================================
// xxT_mma: split-K channel-logits partials (tf32 mma, NT)  (unchanged)
// =================================================================
#define XT_SMEM_BYTES ((2 * 128 * 36 * 2) * 4)   // 73728

__global__ void __launch_bounds__(256)
xxT_mma(const float* __restrict__ x, float* __restrict__ part) {
    extern __shared__ float sm[];
    float* Asm = sm;
    float* Bsm = sm + 2 * 128 * 36;
    int tid = threadIdx.x, lane = tid & 31, wid = tid >> 5;
    int wm = wid & 3, wn = wid >> 2;
    int z = blockIdx.z, b = z >> 3, ks = z & 7;
    int m0 = blockIdx.y * 128, n0 = blockIdx.x * 128;
    const float* Ag = x + (long)b * C_ * N_ + (long)m0 * N_ + ks * 512;
    const float* Bg = x + (long)b * C_ * N_ + (long)n0 * N_ + ks * 512;
    uint32_t smu_a = smem_to_u32(Asm), smu_b = smem_to_u32(Bsm);
    float c[2][8][4] = {};

    #pragma unroll
    for (int s = 0; s < 2; s++) {
        int k0 = s * 32;
        #pragma unroll
        for (int j = 0; j < 4; j++) {
            int f = tid + 256 * j;
            int r = f >> 3, q = (f & 7) * 4;
            cp16(smu_a + (s * 4608 + r * 36 + q) * 4, Ag + (long)r * N_ + k0 + q);
            cp16(smu_b + (s * 4608 + r * 36 + q) * 4, Bg + (long)r * N_ + k0 + q);
        }
        CP_COMMIT();
    }

    for (int ch = 0; ch < 16; ch++) {
        if (ch < 14) { CP_WAIT(1); } else { CP_WAIT(0); }
        __syncthreads();
        const float* As_ = Asm + (ch & 1) * 4608;
        const float* Bs_ = Bsm + (ch & 1) * 4608;
        #pragma unroll
        for (int k8 = 0; k8 < 32; k8 += 8) {
            uint32_t a[2][4], bb[8][2];
            #pragma unroll
            for (int mt = 0; mt < 2; mt++) {
                const float* ap = As_ + (wm * 32 + mt * 16 + (lane >> 2)) * 36 + k8 + (lane & 3);
                a[mt][0] = ld_tf32(ap);
                a[mt][1] = ld_tf32(ap + 8 * 36);
                a[mt][2] = ld_tf32(ap + 4);
                a[mt][3] = ld_tf32(ap + 8 * 36 + 4);
            }
            #pragma unroll
            for (int nt = 0; nt < 8; nt++) {
                const float* bp = Bs_ + (wn * 64 + nt * 8 + (lane >> 2)) * 36 + k8 + (lane & 3);
                bb[nt][0] = ld_tf32(bp);
                bb[nt][1] = ld_tf32(bp + 4);
            }
            #pragma unroll
            for (int mt = 0; mt < 2; mt++)
                #pragma unroll
                for (int nt = 0; nt < 8; nt++)
                    mma_tf32(c[mt][nt], a[mt][0], a[mt][1], a[mt][2], a[mt][3],
                             bb[nt][0], bb[nt][1]);
        }
        __syncthreads();
        if (ch + 2 < 16) {
            int s = ch & 1;
            int k0 = (ch + 2) * 32;
            #pragma unroll
            for (int j = 0; j < 4; j++) {
                int f = tid + 256 * j;
                int r = f >> 3, q = (f & 7) * 4;
                cp16(smu_a + (s * 4608 + r * 36 + q) * 4, Ag + (long)r * N_ + k0 + q);
                cp16(smu_b + (s * 4608 + r * 36 + q) * 4, Bg + (long)r * N_ + k0 + q);
            }
            CP_COMMIT();
        }
    }

    float* Ob = part + (long)z * C_ * C_;
    #pragma unroll
    for (int mt = 0; mt < 2; mt++) {
        int row = m0 + wm * 32 + mt * 16 + (lane >> 2);
        #pragma unroll
        for (int nt = 0; nt < 8; nt++) {
            int col = n0 + wn * 64 + nt * 8 + 2 * (lane & 3);
            long o = (long)row * C_ + col;
            *(float2*)(Ob + o) = make_float2(c[mt][nt][0], c[mt][nt][1]);
            *(float2*)(Ob + o + 8 * C_) = make_float2(c[mt][nt][2], c[mt][nt][3]);
        }
    }
}

// =================================================================
// NN-GEMM (tf32 mma): ca apply  (unchanged R12)
// =================================================================
__global__ void __launch_bounds__(256)
gemm_nn_mma(const float* __restrict__ A, const float* __restrict__ B,
            float* __restrict__ Out, int K, int epi,
            const float* __restrict__ bias, const float* __restrict__ gsc,
            const float* __restrict__ res,
            long sA, long sB, long sO, long sR) {
    extern __shared__ float sm[];
    float* As = sm;
    float* Bs = sm + 2 * 128 * 36;
    int tid = threadIdx.x, lane = tid & 31, w = tid >> 5;
    int wm = w & 3, wn = w >> 2;
    int b = blockIdx.z, m0 = blockIdx.y * 128, n0 = blockIdx.x * 128;
    const float* Ag = A + sA * b + (long)m0 * K;
    const float* Bg = B + sB * b + n0;
    uint32_t smu_a = smem_to_u32(As), smu_b = smem_to_u32(Bs);
    float acc[2][8][4] = {};
    int nchunks = K / 32;

    #pragma unroll
    for (int s = 0; s < 2; s++) {
        #pragma unroll
        for (int jj = 0; jj < 4; jj++) {
            int idx = tid + 256 * jj;
            int r = idx >> 3, kq = (idx & 7) * 4;
            cp16(smu_a + (s * 4608 + r * 36 + kq) * 4, Ag + (long)r * K + s * 32 + kq);
            int kk = idx >> 5, nq = (idx & 31) * 4;
            cp16(smu_b + (s * 4224 + kk * 132 + nq) * 4, Bg + (long)(s * 32 + kk) * N_ + nq);
        }
        CP_COMMIT();
    }

    for (int ch = 0; ch < nchunks; ch++) {
        if (ch < nchunks - 2) { CP_WAIT(1); } else { CP_WAIT(0); }
        __syncthreads();
        const float* As_ = As + (ch & 1) * 4608;
        const float* Bs_ = Bs + (ch & 1) * 4224;
        #pragma unroll
        for (int k8 = 0; k8 < 32; k8 += 8) {
            uint32_t a[2][4], bb[8][2];
            #pragma unroll
            for (int mt = 0; mt < 2; mt++) {
                const float* ap = As_ + (wm * 32 + mt * 16 + (lane >> 2)) * 36 + k8 + (lane & 3);
                a[mt][0] = ld_tf32(ap);
                a[mt][1] = ld_tf32(ap + 8 * 36);
                a[mt][2] = ld_tf32(ap + 4);
                a[mt][3] = ld_tf32(ap + 8 * 36 + 4);
            }
            #pragma unroll
            for (int nt = 0; nt < 8; nt++) {
                const float* bp = Bs_ + (k8 + (lane & 3)) * 132 + wn * 64 + nt * 8 + (lane >> 2);
                bb[nt][0] = ld_tf32(bp);
                bb[nt][1] = ld_tf32(bp + 4 * 132);
            }
            #pragma unroll
            for (int mt = 0; mt < 2; mt++)
                #pragma unroll
                for (int nt = 0; nt < 8; nt++)
                    mma_tf32(acc[mt][nt], a[mt][0], a[mt][1], a[mt][2], a[mt][3],
                             bb[nt][0], bb[nt][1]);
        }
        __syncthreads();
        if (ch + 2 < nchunks) {
            int s = ch & 1;
            #pragma unroll
            for (int jj = 0; jj < 4; jj++) {
                int idx = tid + 256 * jj;
                int r = idx >> 3, kq = (idx & 7) * 4;
                cp16(smu_a + (s * 4608 + r * 36 + kq) * 4,
                     Ag + (long)r * K + (ch + 2) * 32 + kq);
                int kk = idx >> 5, nq = (idx & 31) * 4;
                cp16(smu_b + (s * 4224 + kk * 132 + nq) * 4,
                     Bg + (long)((ch + 2) * 32 + kk) * N_ + nq);
            }
            CP_COMMIT();
        }
    }

    float g = gsc ? *gsc : 0.f;
    const float* resb = res ? res + sR * b : nullptr;
    float* Ob = Out + sO * b;
    #pragma unroll
    for (int mt = 0; mt < 2; mt++) {
        int row = m0 + wm * 32 + mt * 16 + (lane >> 2);
        #pragma unroll
        for (int nt = 0; nt < 8; nt++) {
            int col = n0 + wn * 64 + nt * 8 + 2 * (lane & 3);
            long o = (long)row * N_ + col;
            if (epi == 0) {
                float bv = bias[row], bv8 = bias[row + 8];
                *(float2*)(Ob + o) = make_float2(acc[mt][nt][0] + bv, acc[mt][nt][1] + bv);
                *(float2*)(Ob + o + 8 * N_) =
                    make_float2(acc[mt][nt][2] + bv8, acc[mt][nt][3] + bv8);
            } else {
                *(float2*)(Ob + o) = make_float2(
                    fmaf(g, acc[mt][nt][0], resb[o]), fmaf(g, acc[mt][nt][1], resb[o + 1]));
                *(float2*)(Ob + o + 8 * N_) = make_float2(
                    fmaf(g, acc[mt][nt][2], resb[o + 8 * N_]),
                    fmaf(g, acc[mt][nt][3], resb[o + 8 * N_ + 1]));
            }
        }
    }
}

// =================================================================
// wf2h: reorder + convert weights to fp16: wfh[o][chunk32][pos9][ci16]
// =================================================================
__global__ void wf2h_k(const float* __restrict__ wf, __half* __restrict__ wfh) {
    __shared__ float row[4608];
    int o = blockIdx.x, tid = threadIdx.x;
    const float* src = wf + (long)o * 4608;
    for (int i = tid; i < 4608; i += 256) row[i] = src[i];
    __syncthreads();
    __half* dst = wfh + (long)o * 4608;
    for (int i = tid; i < 4608; i += 256) {
        int chunk = i / 144, r = i % 144, pos = r >> 4, cil = r & 15;
        dst[i] = __float2half(row[(chunk * 16 + cil) * 9 + pos]);
    }
}

// =================================================================
// cat2h: transpose+convert cat fp32 NCHW -> fp16 NHWC ([b][4096][512])
// =================================================================
__global__ void cat2h_k(const float* __restrict__ cat, __half* __restrict__ catsh) {
    __shared__ float t[32][33];
    int b = blockIdx.z;
    int ci0 = blockIdx.y * 32, p0 = blockIdx.x * 32;
    int tx = threadIdx.x, ty = threadIdx.y;   // (32, 8)
    #pragma unroll
    for (int i = 0; i < 4; i++)
        t[ty + 8 * i][tx] = cat[((long)b * 512 + ci0 + ty + 8 * i) * 4096 + p0 + tx];
    __syncthreads();
    #pragma unroll
    for (int i = 0; i < 4; i++)
        catsh[((long)b * 4096 + p0 + ty + 8 * i) * 512 + ci0 + tx] =
            __float2half(t[tx][ty + 8 * i]);
}

// =================================================================
// 3x3 conv 512 -> 256, implicit GEMM v4 (fp16 m16n8k16), M=256.
// k order = chunk(32 of 16ci) * (pos*16 + ci). A = wfh (pre-reordered),
// B read directly from NHWC fp16 patch. 2-stage cp.async.
// smem: A 2x[256][152] half (pad 152 -> conflict-free),
//       patch 2x[4row][68w][24ci-pad] half (48B w-stride, conflict-free).
// =================================================================
#define CV_A_STRIDE 152
#define CV_AS_H  (256 * CV_A_STRIDE)     // 38912 halves per stage
#define CV_PT_H  (4 * 68 * 24)           // 6528 halves per stage
#define CV_SMEM_BYTES ((2 * CV_AS_H + 2 * CV_PT_H) * 2)   // 181760

__global__ void __launch_bounds__(256, 1)
conv_mma(const __half* __restrict__ catsh, const __half* __restrict__ wfh,
         float* __restrict__ y) {
    extern __shared__ char smc[];
    __half* Asm = (__half*)smc;                    // 2 x [256][152]
    __half* Pt = Asm + 2 * CV_AS_H;                // 2 x [4][68][24]
    int tid = threadIdx.x, lane = tid & 31, wid = tid >> 5;
    int wm = wid & 3, wn = wid >> 2;
    int b = blockIdx.z, p0 = blockIdx.x * 128;
    int h0 = blockIdx.x * 2;
    uint32_t smu_a = smem_to_u32(Asm), smu_p = smem_to_u32(Pt);
    const __half* Cb = catsh + (long)b * 4096 * 512;

    for (int i = tid; i < 2 * CV_PT_H; i += 256) Pt[i] = __float2half(0.f);
    __syncthreads();

    float c[4][8][4] = {};

    // prologue: chunks 0,1
    #pragma unroll
    for (int s = 0; s < 2; s++) {
        #pragma unroll
        for (int j = 0; j < 18; j++) {       // weights: 256 rows x 18 cp16 (144 halves)
            int f = tid + 256 * j;
            int r = f / 18, q = (f % 18) * 8;
            cp16(smu_a + (s * CV_AS_H + r * CV_A_STRIDE + q) * 2,
                 wfh + (long)r * 4608 + s * 144 + q);
        }
        #pragma unroll
        for (int j = 0; j < 2; j++) {        // patch: 4row x 64w x 2 half-groups
            int f = tid + 256 * j;           // 0..511
            int ww = f & 63, rq = (f >> 6) & 3, hf = (f >> 8) & 1;
            int h = h0 - 1 + rq;
            if (h >= 0 && h < 64)
                cp16(smu_p + (s * CV_PT_H + (rq * 68 + ww + 2) * 24 + hf * 8) * 2,
                     Cb + ((long)h * 64 + ww) * 512 + s * 16 + hf * 8);
        }
        CP_COMMIT();
    }

    for (int chunk = 0; chunk < 32; chunk++) {
        if (chunk < 30) { CP_WAIT(1); } else { CP_WAIT(0); }
        __syncthreads();
        const __half* As_ = Asm + (chunk & 1) * CV_AS_H;
        const __half* Pt_ = Pt + (chunk & 1) * CV_PT_H;

        #pragma unroll
        for (int pos = 0; pos < 9; pos++) {
            const int kh = pos / 3, kw = pos % 3;
            uint32_t a[4][4], bb[8][2];
            #pragma unroll
            for (int mt = 0; mt < 4; mt++) {
                const __half* ap = As_ + (wm * 64 + mt * 16 + (lane >> 2)) * CV_A_STRIDE
                                   + pos * 16 + 2 * (lane & 3);
                a[mt][0] = *(const uint32_t*)ap;
                a[mt][1] = *(const uint32_t*)(ap + 8 * CV_A_STRIDE);
                a[mt][2] = *(const uint32_t*)(ap + 8);
                a[mt][3] = *(const uint32_t*)(ap + 8 * CV_A_STRIDE + 8);
            }
            {
                int nbase = wn * 64 + (lane >> 2);
                const __half* pb = Pt_ + (wn + kh) * 68 * 24 + 2 * (lane & 3);
                #pragma unroll
                for (int nt = 0; nt < 8; nt++) {
                    int wpos = ((nbase + nt * 8) & 63) + kw + 1;
                    bb[nt][0] = *(const uint32_t*)(pb + wpos * 24);
                    bb[nt][1] = *(const uint32_t*)(pb + wpos * 24 + 8);
                }
            }
            #pragma unroll
            for (int mt = 0; mt < 4; mt++)
                #pragma unroll
                for (int nt = 0; nt < 8; nt++)
                    mma_f16(c[mt][nt], a[mt][0], a[mt][1], a[mt][2], a[mt][3],
                            bb[nt][0], bb[nt][1]);
        }
        __syncthreads();
        if (chunk + 2 < 32) {
            int s = chunk & 1;
            #pragma unroll
            for (int j = 0; j < 18; j++) {
                int f = tid + 256 * j;
                int r = f / 18, q = (f % 18) * 8;
                cp16(smu_a + (s * CV_AS_H + r * CV_A_STRIDE + q) * 2,
                     wfh + (long)r * 4608 + (chunk + 2) * 144 + q);
            }
            #pragma unroll
            for (int j = 0; j < 2; j++) {
                int f = tid + 256 * j;
                int ww = f & 63, rq = (f >> 6) & 3, hf = (f >> 8) & 1;
                int h = h0 - 1 + rq;
                if (h >= 0 && h < 64)
                    cp16(smu_p + (s * CV_PT_H + (rq * 68 + ww + 2) * 24 + hf * 8) * 2,
                         Cb + ((long)h * 64 + ww) * 512 + (chunk + 2) * 16 + hf * 8);
            }
            CP_COMMIT();
        }
    }

    #pragma unroll
    for (int mt = 0; mt < 4; mt++) {
        #pragma unroll
        for (int nt = 0; nt < 8; nt++) {
            int row = wm * 64 + mt * 16 + (lane >> 2);
            int col = p0 + wn * 64 + nt * 8 + 2 * (lane & 3);
            long yo = ((long)b * 256 + row) * 4096 + col;
            *(float2*)(y + yo) = make_float2(c[mt][nt][0], c[mt][nt][1]);
            *(float2*)(y + yo + 8 * 4096) = make_float2(c[mt][nt][2], c[mt][nt][3]);
        }
    }
}

// ---------------- helpers ----------------
__device__ __forceinline__ float warpMax(float v) {
    #pragma unroll
    for (int o = 16; o; o >>= 1) v = fmaxf(v, __shfl_xor_sync(0xffffffffu, v, o));
    return v;
}
__device__ __forceinline__ float warpSum(float v) {
    #pragma unroll
    for (int o = 16; o; o >>= 1) v += __shfl_xor_sync(0xffffffffu, v, o);
    return v;
}

// ---------------- merged q+k projection (fp32 SIMT, M=64) ----------------
__global__ void qk_proj(const float* __restrict__ wq, const float* __restrict__ bq,
                        const float* __restrict__ wk, const float* __restrict__ bk,
                        const float* __restrict__ x, float* __restrict__ q,
                        float* __restrict__ k) {
    __shared__ float As[16][64];
    __shared__ float Bs[16][64];
    int b = blockIdx.z;
    const float* Bm = x + (long)b * C_ * N_;
    int tid = threadIdx.x;
    int tx = tid & 15, ty = tid >> 4;
    int n0 = blockIdx.x * 64;
    int arow = tid >> 2, ak = (tid & 3) * 4;
    int brow = tid >> 4, bn = (tid & 15) * 4;
    const float* Arow = (arow < 32) ? (wq + (long)arow * C_)
                                    : (wk + (long)(arow - 32) * C_);
    float acc[4][4] = {};
    for (int k0 = 0; k0 < C_; k0 += 16) {
        float4 av = *(const float4*)(Arow + k0 + ak);
        As[ak + 0][arow] = av.x; As[ak + 1][arow] = av.y;
        As[ak + 2][arow] = av.z; As[ak + 3][arow] = av.w;
        *(float4*)&Bs[brow][bn] = *(const float4*)(Bm + (long)(k0 + brow) * N_ + n0 + bn);
        __syncthreads();
        #pragma unroll
        for (int kk = 0; kk < 16; kk++) {
            float4 a = *(const float4*)&As[kk][ty * 4];
            float4 bv = *(const float4*)&Bs[kk][tx * 4];
            float ar[4] = {a.x, a.y, a.z, a.w};
            float br[4] = {bv.x, bv.y, bv.z, bv.w};
            #pragma unroll
            for (int i = 0; i < 4; i++)
                #pragma unroll
                for (int j = 0; j < 4; j++)
                    acc[i][j] = fmaf(ar[i], br[j], acc[i][j]);
        }
        __syncthreads();
    }
    #pragma unroll
    for (int i = 0; i < 4; i++) {
        int m = ty * 4 + i;
        float bv = (m < 32) ? bq[m] : bk[m - 32];
        float* Out = (m < 32) ? (q + ((long)b * CQ_ + m) * N_)
                              : (k + ((long)b * CQ_ + m - 32) * N_);
        *(float4*)(Out + n0 + tx * 4) = make_float4(
            acc[i][0] + bv, acc[i][1] + bv, acc[i][2] + bv, acc[i][3] + bv);
    }
}

// ---------------- softmax over 256 with split-K reduction ----------------
__global__ void softmax256(const float* __restrict__ part, float* __restrict__ out) {
    __shared__ float sh[8];
    int tid = threadIdx.x;
    int row = blockIdx.x;
    int b = row >> 8, i = row & 255;
    float v = 0.f;
    #pragma unroll
    for (int ks = 0; ks < 8; ks++)
        v += part[((long)(b * 8 + ks) * C_ + i) * C_ + tid];
    float m = warpMax(v);
    if ((tid & 31) == 0) sh[tid >> 5] = m;
    __syncthreads();
    m = sh[tid & 7];
    #pragma unroll
    for (int o = 4; o; o >>= 1) m = fmaxf(m, __shfl_xor_sync(0xffffffffu, m, o));
    __syncthreads();
    float e = __expf(v - m);
    float s = warpSum(e);
    if ((tid & 31) == 0) sh[tid >> 5] = s;
    __syncthreads();
    s = sh[tid & 7];
    #pragma unroll
    for (int o = 4; o; o >>= 1) s += __shfl_xor_sync(0xffffffffu, s, o);
    out[(long)row * 256 + tid] = e / s;
}

// ---------------- BN (train-mode batch stats) + ReLU ----------------
__global__ void bnstats(const float* __restrict__ y, float* __restrict__ meanp,
                        float* __restrict__ rstdp) {
    __shared__ float sh[16];
    int o = blockIdx.x, tid = threadIdx.x;
    float s = 0.f, sq = 0.f;
    for (int b = 0; b < 4; b++) {
        const float4* p = (const float4*)(y + ((size_t)b * 256 + o) * 4096);
        for (int i = tid; i < 1024; i += 256) {
            float4 v = p[i];
            s += v.x + v.y + v.z + v.w;
            sq += v.x * v.x + v.y * v.y + v.z * v.z + v.w * v.w;
        }
    }
    s = warpSum(s); sq = warpSum(sq);
    if ((tid & 31) == 0) { sh[tid >> 5] = s; sh[8 + (tid >> 5)] = sq; }
    __syncthreads();
    if (tid == 0) {
        float S = 0.f, SQ = 0.f;
        for (int i = 0; i < 8; i++) { S += sh[i]; SQ += sh[8 + i]; }
        float mean = S / 16384.f;
        float var = SQ / 16384.f - mean * mean;
        meanp[o] = mean;
        rstdp[o] = rsqrtf(var + 1e-5f);
    }
}

__global__ void bnapply(const float* __restrict__ y, const float* __restrict__ gam,
                        const float* __restrict__ bet, const float* __restrict__ meanp,
                        const float* __restrict__ rstdp, float* __restrict__ out) {
    size_t i = (size_t)blockIdx.x * 256 + threadIdx.x;
    int o = (int)((i >> 10) & 255);
    float mu = meanp[o], rs = rstdp[o], g = gam[o], be = bet[o];
    float4 v = ((const float4*)y)[i];
    float4 r;
    r.x = fmaxf(0.f, fmaf((v.x - mu) * rs, g, be));
    r.y = fmaxf(0.f, fmaf((v.y - mu) * rs, g, be));
    r.z = fmaxf(0.f, fmaf((v.z - mu) * rs, g, be));
    r.w = fmaxf(0.f, fmaf((v.w - mu) * rs, g, be));
    ((float4*)out)[i] = r;
}

// ---------------- launcher ----------------
extern "C" void kernel_launch(void* const* d_in, const int* in_sizes, int n_in,
                              void* d_out, int out_size) {
    const float* x   = (const float*)d_in[0];
    const float* wq  = (const float*)d_in[1];
    const float* bq  = (const float*)d_in[2];
    const float* wk  = (const float*)d_in[3];
    const float* bk  = (const float*)d_in[4];
    const float* wv  = (const float*)d_in[5];
    const float* bv  = (const float*)d_in[6];
    const float* gpa = (const float*)d_in[7];
    const float* gca = (const float*)d_in[8];
    const float* wf  = (const float*)d_in[9];
    const float* bng = (const float*)d_in[10];
    const float* bnb = (const float*)d_in[11];
    float* out = (float*)d_out;

    float *q, *k, *cat, *cattn, *cattn_part, *y, *mean, *rstd;
    __nv_bfloat16* v;
    __half *catsh, *wfh;
    cudaGetSymbolAddress((void**)&q, g_q);
    cudaGetSymbolAddress((void**)&k, g_k);
    cudaGetSymbolAddress((void**)&v, g_v);
    cudaGetSymbolAddress((void**)&cat, g_cat);
    cudaGetSymbolAddress((void**)&catsh, g_catsh);
    cudaGetSymbolAddress((void**)&wfh, g_wfh);
    cudaGetSymbolAddress((void**)&cattn, g_cattn);
    cudaGetSymbolAddress((void**)&cattn_part, g_cattn_part);
    cudaGetSymbolAddress((void**)&y, g_y);
    cudaGetSymbolAddress((void**)&mean, g_mean);
    cudaGetSymbolAddress((void**)&rstd, g_rstd);

    cudaFuncSetAttribute(pa_flash, cudaFuncAttributeMaxDynamicSharedMemorySize,
                         PF_SMEM_BYTES);
    cudaFuncSetAttribute(v_proj, cudaFuncAttributeMaxDynamicSharedMemorySize,
                         NN_SMEM_BYTES);
    cudaFuncSetAttribute(gemm_nn_mma, cudaFuncAttributeMaxDynamicSharedMemorySize,
                         NN_SMEM_BYTES);
    cudaFuncSetAttribute(xxT_mma, cudaFuncAttributeMaxDynamicSharedMemorySize,
                         XT_SMEM_BYTES);
    cudaFuncSetAttribute(conv_mma, cudaFuncAttributeMaxDynamicSharedMemorySize,
                         CV_SMEM_BYTES);

    dim3 blk(256);
    long sx = (long)C_ * N_;
    long scat = (long)2 * C_ * N_;

    // weight reorder+fp16 (independent; overlaps with projections)
    wf2h_k<<<256, 256>>>(wf, wfh);
    // q + k projections in one kernel
    qk_proj<<<dim3(64, 1, 4), blk>>>(wq, bq, wk, bk, x, q, k);
    // v projection on tensor cores, bf16 output
    v_proj<<<dim3(32, 2, 4), blk, NN_SMEM_BYTES>>>(wv, x, v, bv, sx, sx);
    // fused flash position-attention (PV in bf16) -> cat[:, 0:256]
    pa_flash<<<dim3(32, 1, 4), blk, PF_SMEM_BYTES>>>(q, k, v, x, gpa, cat);
    // channel attention: split-K x.xT partials, fused-reduce softmax, apply
    xxT_mma<<<dim3(2, 2, 32), blk, XT_SMEM_BYTES>>>(x, cattn_part);
    softmax256<<<B_ * C_, 256>>>(cattn_part, cattn);
    gemm_nn_mma<<<dim3(32, 2, 4), blk, NN_SMEM_BYTES>>>(
        cattn, x, cat + (size_t)C_ * N_, C_, 1, nullptr, gca, x,
        (long)C_ * C_, sx, scat, sx);
    // cat -> fp16 NHWC
    cat2h_k<<<dim3(128, 16, 4), dim3(32, 8)>>>(cat, catsh);
    // 3x3 conv 512->256 (implicit GEMM v4, fp16 m16n8k16)
    conv_mma<<<dim3(32, 1, 4), blk, CV_SMEM_BYTES>>>(catsh, wfh, y);
    // BN train-mode + ReLU
    bnstats<<<256, 256>>>(y, mean, rstd);
    bnapply<<<4096, 256>>>(y, bng, bnb, mean, rstd, out);
}

// round 14
// speedup vs baseline: 3.9659x; 1.0026x over previous
#include <cuda_runtime.h>
#include <cuda_bf16.h>
#include <cuda_fp16.h>
#include <cstdint>

#define B_  4
#define C_  256
#define CQ_ 32
#define N_  4096
#define HW_ 64

// ---------------- scratch (device globals; no allocation) ----------------
__device__ float g_q[B_ * CQ_ * N_];
__device__ float g_k[B_ * CQ_ * N_];
__device__ __nv_bfloat16 g_v[B_ * C_ * N_];              // bf16 v
__device__ float g_cat[(size_t)B_ * 2 * C_ * N_];        // [b][512][4096] fp32
__device__ __half g_catsh[(size_t)B_ * N_ * 2 * C_];     // [b][4096][512] fp16 NHWC
__device__ __half g_wfh[C_ * 2 * C_ * 9];                // reordered fp16 weights
__device__ float g_cattn_part[32 * C_ * C_];             // split-K partials
__device__ float g_cattn[B_ * C_ * C_];
__device__ float g_y[(size_t)B_ * C_ * N_];
__device__ float g_mean[C_];
__device__ float g_rstd[C_];

// ---------------- PTX helpers (sm_80+ mma.sync / cp.async) ----------------
__device__ __forceinline__ uint32_t smem_to_u32(const void* p) {
    uint32_t a;
    asm("{ .reg .u64 t; cvta.to.shared.u64 t, %1; cvt.u32.u64 %0, t; }" : "=r"(a) : "l"(p));
    return a;
}
__device__ __forceinline__ void cp16(uint32_t dst, const void* src) {
    asm volatile("cp.async.cg.shared.global [%0], [%1], 16;" :: "r"(dst), "l"(src));
}
#define CP_COMMIT() asm volatile("cp.async.commit_group;" ::: "memory")
#define CP_WAIT(n)  asm volatile("cp.async.wait_group %0;" :: "n"(n) : "memory")

__device__ __forceinline__ uint32_t ld_tf32(const float* p) {
    uint32_t r;
    float f = *p;
    asm("cvt.rna.tf32.f32 %0, %1;" : "=r"(r) : "f"(f));
    return r;
}
__device__ __forceinline__ void mma_tf32(float c[4], uint32_t a0, uint32_t a1,
                                         uint32_t a2, uint32_t a3,
                                         uint32_t b0, uint32_t b1) {
    asm volatile(
        "mma.sync.aligned.m16n8k8.row.col.f32.tf32.tf32.f32 "
        "{%0,%1,%2,%3}, {%4,%5,%6,%7}, {%8,%9}, {%0,%1,%2,%3};"
        : "+f"(c[0]), "+f"(c[1]), "+f"(c[2]), "+f"(c[3])
        : "r"(a0), "r"(a1), "r"(a2), "r"(a3), "r"(b0), "r"(b1));
}
__device__ __forceinline__ void mma_bf16(float c[4], uint32_t a0, uint32_t a1,
                                         uint32_t a2, uint32_t a3,
                                         uint32_t b0, uint32_t b1) {
    asm volatile(
        "mma.sync.aligned.m16n8k16.row.col.f32.bf16.bf16.f32 "
        "{%0,%1,%2,%3}, {%4,%5,%6,%7}, {%8,%9}, {%0,%1,%2,%3};"
        : "+f"(c[0]), "+f"(c[1]), "+f"(c[2]), "+f"(c[3])
        : "r"(a0), "r"(a1), "r"(a2), "r"(a3), "r"(b0), "r"(b1));
}
__device__ __forceinline__ void mma_f16(float c[4], uint32_t a0, uint32_t a1,
                                        uint32_t a2, uint32_t a3,
                                        uint32_t b0, uint32_t b1) {
    asm volatile(
        "mma.sync.aligned.m16n8k16.row.col.f32.f16.f16.f32 "
        "{%0,%1,%2,%3}, {%4,%5,%6,%7}, {%8,%9}, {%0,%1,%2,%3};"
        : "+f"(c[0]), "+f"(c[1]), "+f"(c[2]), "+f"(c[3])
        : "r"(a0), "r"(a1), "r"(a2), "r"(a3), "r"(b0), "r"(b1));
}

// =================================================================
// pa_flash v2: fused attention, PV on bf16 m16n8k16.  (unchanged R12)
// =================================================================
#define PF_AS  (256 * 40)
#define PF_KS  (32 * 36)
#define PF_SMEM_BYTES (2 * PF_AS * 2 + 2 * PF_KS * 4 + 128 * 40 * 2)  // 60416

__global__ void __launch_bounds__(256, 1)
pa_flash(const float* __restrict__ qg, const float* __restrict__ kg,
         const __nv_bfloat16* __restrict__ v, const float* __restrict__ x,
         const float* __restrict__ gpa, float* __restrict__ cat) {
    extern __shared__ char smc[];
    __nv_bfloat16* Avs = (__nv_bfloat16*)smc;
    float* Ksm = (float*)(smc + 2 * PF_AS * 2);
    __nv_bfloat16* Ps = (__nv_bfloat16*)(smc + 2 * PF_AS * 2 + 2 * PF_KS * 4);
    __shared__ float red[128];
    int tid = threadIdx.x, lane = tid & 31, w = tid >> 5;
    int wm = w & 3, wn = w >> 2;
    int b = blockIdx.z, I0 = blockIdx.x * 128;
    const float* Qg = qg + (long)b * CQ_ * N_;
    const float* Kg = kg + (long)b * CQ_ * N_;
    const __nv_bfloat16* Ag = v + (long)b * C_ * N_;
    uint32_t smu_a = smem_to_u32(Avs), smu_k = smem_to_u32(Ksm);

    uint32_t aq[4][4];
    {
        int i0 = I0 + w * 16 + (lane >> 2);
        #pragma unroll
        for (int k8 = 0; k8 < 4; k8++) {
            int d0 = k8 * 8 + (lane & 3);
            const float* qp = Qg + (long)d0 * N_ + i0;
            aq[k8][0] = ld_tf32(qp);
            aq[k8][1] = ld_tf32(qp + 8);
            aq[k8][2] = ld_tf32(qp + 4 * N_);
            aq[k8][3] = ld_tf32(qp + 4 * N_ + 8);
        }
    }

    float c[4][8][4] = {};
    float lsum0 = 0.f, lsum1 = 0.f;

    #pragma unroll
    for (int s = 0; s < 2; s++) {
        int j0 = s * 32;
        #pragma unroll
        for (int j = 0; j < 4; j++) {
            int f = tid + 256 * j;
            int r = f >> 2, q = (f & 3) * 8;
            cp16(smu_a + (s * PF_AS + r * 40 + q) * 2, Ag + (long)r * N_ + j0 + q);
        }
        cp16(smu_k + (s * PF_KS + (tid >> 3) * 36 + (tid & 7) * 4) * 4,
             Kg + (long)(tid >> 3) * N_ + j0 + (tid & 7) * 4);
        CP_COMMIT();
    }

    for (int ch = 0; ch < 128; ch++) {
        if (ch < 126) { CP_WAIT(1); } else { CP_WAIT(0); }
        __syncthreads();
        const __nv_bfloat16* As_ = Avs + (ch & 1) * PF_AS;
        const float* Ks_ = Ksm + (ch & 1) * PF_KS;

        float s4[4][4] = {};
        #pragma unroll
        for (int k8 = 0; k8 < 4; k8++) {
            int d0 = k8 * 8 + (lane & 3);
            #pragma unroll
            for (int nt = 0; nt < 4; nt++) {
                uint32_t b0 = ld_tf32(&Ks_[d0 * 36 + nt * 8 + (lane >> 2)]);
                uint32_t b1 = ld_tf32(&Ks_[(d0 + 4) * 36 + nt * 8 + (lane >> 2)]);
                mma_tf32(s4[nt], aq[k8][0], aq[k8][1], aq[k8][2], aq[k8][3], b0, b1);
            }
        }
        {
            int r0 = (w * 16 + (lane >> 2)) * 40 + 2 * (lane & 3);
            #pragma unroll
            for (int nt = 0; nt < 4; nt++) {
                float p0 = __expf(s4[nt][0]), p1 = __expf(s4[nt][1]);
                float p2 = __expf(s4[nt][2]), p3 = __expf(s4[nt][3]);
                lsum0 += p0 + p1;
                lsum1 += p2 + p3;
                *(__nv_bfloat162*)&Ps[r0 + nt * 8] = __floats2bfloat162_rn(p0, p1);
                *(__nv_bfloat162*)&Ps[r0 + 8 * 40 + nt * 8] = __floats2bfloat162_rn(p2, p3);
            }
        }
        __syncthreads();
        #pragma unroll
        for (int ks = 0; ks < 2; ks++) {
            int k0 = ks * 16;
            uint32_t a[4][4], bb[8][2];
            #pragma unroll
            for (int mt = 0; mt < 4; mt++) {
                const __nv_bfloat16* ap = As_ + (wm * 64 + mt * 16 + (lane >> 2)) * 40
                                          + k0 + 2 * (lane & 3);
                a[mt][0] = *(const uint32_t*)ap;
                a[mt][1] = *(const uint32_t*)(ap + 8 * 40);
                a[mt][2] = *(const uint32_t*)(ap + 8);
                a[mt][3] = *(const uint32_t*)(ap + 8 * 40 + 8);
            }
            #pragma unroll
            for (int nt = 0; nt < 8; nt++) {
                const __nv_bfloat16* bp = Ps + (wn * 64 + nt * 8 + (lane >> 2)) * 40
                                          + k0 + 2 * (lane & 3);
                bb[nt][0] = *(const uint32_t*)bp;
                bb[nt][1] = *(const uint32_t*)(bp + 8);
            }
            #pragma unroll
            for (int mt = 0; mt < 4; mt++)
                #pragma unroll
                for (int nt = 0; nt < 8; nt++)
                    mma_bf16(c[mt][nt], a[mt][0], a[mt][1], a[mt][2], a[mt][3],
                             bb[nt][0], bb[nt][1]);
        }
        __syncthreads();
        if (ch + 2 < 128) {
            int s = ch & 1;
            int j0 = (ch + 2) * 32;
            #pragma unroll
            for (int j = 0; j < 4; j++) {
                int f = tid + 256 * j;
                int r = f >> 2, q = (f & 3) * 8;
                cp16(smu_a + (s * PF_AS + r * 40 + q) * 2, Ag + (long)r * N_ + j0 + q);
            }
            cp16(smu_k + (s * PF_KS + (tid >> 3) * 36 + (tid & 7) * 4) * 4,
                 Kg + (long)(tid >> 3) * N_ + j0 + (tid & 7) * 4);
            CP_COMMIT();
        }
    }

    lsum0 += __shfl_xor_sync(0xffffffffu, lsum0, 1);
    lsum0 += __shfl_xor_sync(0xffffffffu, lsum0, 2);
    lsum1 += __shfl_xor_sync(0xffffffffu, lsum1, 1);
    lsum1 += __shfl_xor_sync(0xffffffffu, lsum1, 2);
    if ((lane & 3) == 0) {
        red[w * 16 + (lane >> 2)] = lsum0;
        red[w * 16 + 8 + (lane >> 2)] = lsum1;
    }
    __syncthreads();

    float g = gpa[0];
    #pragma unroll
    for (int nt = 0; nt < 8; nt++) {
        int cl = wn * 64 + nt * 8 + 2 * (lane & 3);
        float inv0 = 1.f / red[cl];
        float inv1 = 1.f / red[cl + 1];
        #pragma unroll
        for (int mt = 0; mt < 4; mt++) {
            int row = wm * 64 + mt * 16 + (lane >> 2);
            int col = I0 + cl;
            long xo = ((long)b * C_ + row) * N_ + col;
            long co = ((long)b * 2 * C_ + row) * N_ + col;
            *(float2*)(cat + co) = make_float2(
                fmaf(g, c[mt][nt][0] * inv0, x[xo]),
                fmaf(g, c[mt][nt][1] * inv1, x[xo + 1]));
            *(float2*)(cat + co + 8 * N_) = make_float2(
                fmaf(g, c[mt][nt][2] * inv0, x[xo + 8 * N_]),
                fmaf(g, c[mt][nt][3] * inv1, x[xo + 8 * N_ + 1]));
        }
    }
}

// =================================================================
// v_proj: NN-GEMM (tf32 mma) -> bf16 output.  (unchanged R12)
// =================================================================
#define NN_SMEM_BYTES ((2 * 128 * 36 + 2 * 32 * 132) * 4)   // 70656

__global__ void __launch_bounds__(256)
v_proj(const float* __restrict__ A, const float* __restrict__ B,
       __nv_bfloat16* __restrict__ Out, const float* __restrict__ bias,
       long sB, long sO) {
    extern __shared__ float sm[];
    float* As = sm;
    float* Bs = sm + 2 * 128 * 36;
    int tid = threadIdx.x, lane = tid & 31, w = tid >> 5;
    int wm = w & 3, wn = w >> 2;
    int b = blockIdx.z, m0 = blockIdx.y * 128, n0 = blockIdx.x * 128;
    const float* Ag = A + (long)m0 * C_;
    const float* Bg = B + sB * b + n0;
    uint32_t smu_a = smem_to_u32(As), smu_b = smem_to_u32(Bs);
    float acc[2][8][4] = {};

    #pragma unroll
    for (int s = 0; s < 2; s++) {
        #pragma unroll
        for (int jj = 0; jj < 4; jj++) {
            int idx = tid + 256 * jj;
            int r = idx >> 3, kq = (idx & 7) * 4;
            cp16(smu_a + (s * 4608 + r * 36 + kq) * 4, Ag + (long)r * C_ + s * 32 + kq);
            int kk = idx >> 5, nq = (idx & 31) * 4;
            cp16(smu_b + (s * 4224 + kk * 132 + nq) * 4, Bg + (long)(s * 32 + kk) * N_ + nq);
        }
        CP_COMMIT();
    }

    for (int ch = 0; ch < 8; ch++) {
        if (ch < 6) { CP_WAIT(1); } else { CP_WAIT(0); }
        __syncthreads();
        const float* As_ = As + (ch & 1) * 4608;
        const float* Bs_ = Bs + (ch & 1) * 4224;
        #pragma unroll
        for (int k8 = 0; k8 < 32; k8 += 8) {
            uint32_t a[2][4], bb[8][2];
            #pragma unroll
            for (int mt = 0; mt < 2; mt++) {
                const float* ap = As_ + (wm * 32 + mt * 16 + (lane >> 2)) * 36 + k8 + (lane & 3);
                a[mt][0] = ld_tf32(ap);
                a[mt][1] = ld_tf32(ap + 8 * 36);
                a[mt][2] = ld_tf32(ap + 4);
                a[mt][3] = ld_tf32(ap + 8 * 36 + 4);
            }
            #pragma unroll
            for (int nt = 0; nt < 8; nt++) {
                const float* bp = Bs_ + (k8 + (lane & 3)) * 132 + wn * 64 + nt * 8 + (lane >> 2);
                bb[nt][0] = ld_tf32(bp);
                bb[nt][1] = ld_tf32(bp + 4 * 132);
            }
            #pragma unroll
            for (int mt = 0; mt < 2; mt++)
                #pragma unroll
                for (int nt = 0; nt < 8; nt++)
                    mma_tf32(acc[mt][nt], a[mt][0], a[mt][1], a[mt][2], a[mt][3],
                             bb[nt][0], bb[nt][1]);
        }
        __syncthreads();
        if (ch + 2 < 8) {
            int s = ch & 1;
            #pragma unroll
            for (int jj = 0; jj < 4; jj++) {
                int idx = tid + 256 * jj;
                int r = idx >> 3, kq = (idx & 7) * 4;
                cp16(smu_a + (s * 4608 + r * 36 + kq) * 4,
                     Ag + (long)r * C_ + (ch + 2) * 32 + kq);
                int kk = idx >> 5, nq = (idx & 31) * 4;
                cp16(smu_b + (s * 4224 + kk * 132 + nq) * 4,
                     Bg + (long)((ch + 2) * 32 + kk) * N_ + nq);
            }
            CP_COMMIT();
        }
    }

    __nv_bfloat16* Ob = Out + sO * b;
    #pragma unroll
    for (int mt = 0; mt < 2; mt++) {
        int row = m0 + wm * 32 + mt * 16 + (lane >> 2);
        float bv = bias[row], bv8 = bias[row + 8];
        #pragma unroll
        for (int nt = 0; nt < 8; nt++) {
            int col = n0 + wn * 64 + nt * 8 + 2 * (lane & 3);
            long o = (long)row * N_ + col;
            *(__nv_bfloat162*)(Ob + o) =
                __floats2bfloat162_rn(acc[mt][nt][0] + bv, acc[mt][nt][1] + bv);
            *(__nv_bfloat162*)(Ob + o + 8 * N_) =
                __floats2bfloat162_rn(acc[mt][nt][2] + bv8, acc[mt][nt][3] + bv8);
        }
    }
}

// =================================================================
// xxT_mma: split-K channel-logits partials (tf32 mma, NT)  (unchanged)
// =================================================================
#define XT_SMEM_BYTES ((2 * 128 * 36 * 2) * 4)   // 73728

__global__ void __launch_bounds__(256)
xxT_mma(const float* __restrict__ x, float* __restrict__ part) {
    extern __shared__ float sm[];
    float* Asm = sm;
    float* Bsm = sm + 2 * 128 * 36;
    int tid = threadIdx.x, lane = tid & 31, wid = tid >> 5;
    int wm = wid & 3, wn = wid >> 2;
    int z = blockIdx.z, b = z >> 3, ks = z & 7;
    int m0 = blockIdx.y * 128, n0 = blockIdx.x * 128;
    const float* Ag = x + (long)b * C_ * N_ + (long)m0 * N_ + ks * 512;
    const float* Bg = x + (long)b * C_ * N_ + (long)n0 * N_ + ks * 512;
    uint32_t smu_a = smem_to_u32(Asm), smu_b = smem_to_u32(Bsm);
    float c[2][8][4] = {};

    #pragma unroll
    for (int s = 0; s < 2; s++) {
        int k0 = s * 32;
        #pragma unroll
        for (int j = 0; j < 4; j++) {
            int f = tid + 256 * j;
            int r = f >> 3, q = (f & 7) * 4;
            cp16(smu_a + (s * 4608 + r * 36 + q) * 4, Ag + (long)r * N_ + k0 + q);
            cp16(smu_b + (s * 4608 + r * 36 + q) * 4, Bg + (long)r * N_ + k0 + q);
        }
        CP_COMMIT();
    }

    for (int ch = 0; ch < 16; ch++) {
        if (ch < 14) { CP_WAIT(1); } else { CP_WAIT(0); }
        __syncthreads();
        const float* As_ = Asm + (ch & 1) * 4608;
        const float* Bs_ = Bsm + (ch & 1) * 4608;
        #pragma unroll
        for (int k8 = 0; k8 < 32; k8 += 8) {
            uint32_t a[2][4], bb[8][2];
            #pragma unroll
            for (int mt = 0; mt < 2; mt++) {
                const float* ap = As_ + (wm * 32 + mt * 16 + (lane >> 2)) * 36 + k8 + (lane & 3);
                a[mt][0] = ld_tf32(ap);
                a[mt][1] = ld_tf32(ap + 8 * 36);
                a[mt][2] = ld_tf32(ap + 4);
                a[mt][3] = ld_tf32(ap + 8 * 36 + 4);
            }
            #pragma unroll
            for (int nt = 0; nt < 8; nt++) {
                const float* bp = Bs_ + (wn * 64 + nt * 8 + (lane >> 2)) * 36 + k8 + (lane & 3);
                bb[nt][0] = ld_tf32(bp);
                bb[nt][1] = ld_tf32(bp + 4);
            }
            #pragma unroll
            for (int mt = 0; mt < 2; mt++)
                #pragma unroll
                for (int nt = 0; nt < 8; nt++)
                    mma_tf32(c[mt][nt], a[mt][0], a[mt][1], a[mt][2], a[mt][3],
                             bb[nt][0], bb[nt][1]);
        }
        __syncthreads();
        if (ch + 2 < 16) {
            int s = ch & 1;
            int k0 = (ch + 2) * 32;
            #pragma unroll
            for (int j = 0; j < 4; j++) {
                int f = tid + 256 * j;
                int r = f >> 3, q = (f & 7) * 4;
                cp16(smu_a + (s * 4608 + r * 36 + q) * 4, Ag + (long)r * N_ + k0 + q);
                cp16(smu_b + (s * 4608 + r * 36 + q) * 4, Bg + (long)r * N_ + k0 + q);
            }
            CP_COMMIT();
        }
    }

    float* Ob = part + (long)z * C_ * C_;
    #pragma unroll
    for (int mt = 0; mt < 2; mt++) {
        int row = m0 + wm * 32 + mt * 16 + (lane >> 2);
        #pragma unroll
        for (int nt = 0; nt < 8; nt++) {
            int col = n0 + wn * 64 + nt * 8 + 2 * (lane & 3);
            long o = (long)row * C_ + col;
            *(float2*)(Ob + o) = make_float2(c[mt][nt][0], c[mt][nt][1]);
            *(float2*)(Ob + o + 8 * C_) = make_float2(c[mt][nt][2], c[mt][nt][3]);
        }
    }
}

// =================================================================
// NN-GEMM (tf32 mma): ca apply  (unchanged R12)
// =================================================================
__global__ void __launch_bounds__(256)
gemm_nn_mma(const float* __restrict__ A, const float* __restrict__ B,
            float* __restrict__ Out, int K, int epi,
            const float* __restrict__ bias, const float* __restrict__ gsc,
            const float* __restrict__ res,
            long sA, long sB, long sO, long sR) {
    extern __shared__ float sm[];
    float* As = sm;
    float* Bs = sm + 2 * 128 * 36;
    int tid = threadIdx.x, lane = tid & 31, w = tid >> 5;
    int wm = w & 3, wn = w >> 2;
    int b = blockIdx.z, m0 = blockIdx.y * 128, n0 = blockIdx.x * 128;
    const float* Ag = A + sA * b + (long)m0 * K;
    const float* Bg = B + sB * b + n0;
    uint32_t smu_a = smem_to_u32(As), smu_b = smem_to_u32(Bs);
    float acc[2][8][4] = {};
    int nchunks = K / 32;

    #pragma unroll
    for (int s = 0; s < 2; s++) {
        #pragma unroll
        for (int jj = 0; jj < 4; jj++) {
            int idx = tid + 256 * jj;
            int r = idx >> 3, kq = (idx & 7) * 4;
            cp16(smu_a + (s * 4608 + r * 36 + kq) * 4, Ag + (long)r * K + s * 32 + kq);
            int kk = idx >> 5, nq = (idx & 31) * 4;
            cp16(smu_b + (s * 4224 + kk * 132 + nq) * 4, Bg + (long)(s * 32 + kk) * N_ + nq);
        }
        CP_COMMIT();
    }

    for (int ch = 0; ch < nchunks; ch++) {
        if (ch < nchunks - 2) { CP_WAIT(1); } else { CP_WAIT(0); }
        __syncthreads();
        const float* As_ = As + (ch & 1) * 4608;
        const float* Bs_ = Bs + (ch & 1) * 4224;
        #pragma unroll
        for (int k8 = 0; k8 < 32; k8 += 8) {
            uint32_t a[2][4], bb[8][2];
            #pragma unroll
            for (int mt = 0; mt < 2; mt++) {
                const float* ap = As_ + (wm * 32 + mt * 16 + (lane >> 2)) * 36 + k8 + (lane & 3);
                a[mt][0] = ld_tf32(ap);
                a[mt][1] = ld_tf32(ap + 8 * 36);
                a[mt][2] = ld_tf32(ap + 4);
                a[mt][3] = ld_tf32(ap + 8 * 36 + 4);
            }
            #pragma unroll
            for (int nt = 0; nt < 8; nt++) {
                const float* bp = Bs_ + (k8 + (lane & 3)) * 132 + wn * 64 + nt * 8 + (lane >> 2);
                bb[nt][0] = ld_tf32(bp);
                bb[nt][1] = ld_tf32(bp + 4 * 132);
            }
            #pragma unroll
            for (int mt = 0; mt < 2; mt++)
                #pragma unroll
                for (int nt = 0; nt < 8; nt++)
                    mma_tf32(acc[mt][nt], a[mt][0], a[mt][1], a[mt][2], a[mt][3],
                             bb[nt][0], bb[nt][1]);
        }
        __syncthreads();
        if (ch + 2 < nchunks) {
            int s = ch & 1;
            #pragma unroll
            for (int jj = 0; jj < 4; jj++) {
                int idx = tid + 256 * jj;
                int r = idx >> 3, kq = (idx & 7) * 4;
                cp16(smu_a + (s * 4608 + r * 36 + kq) * 4,
                     Ag + (long)r * K + (ch + 2) * 32 + kq);
                int kk = idx >> 5, nq = (idx & 31) * 4;
                cp16(smu_b + (s * 4224 + kk * 132 + nq) * 4,
                     Bg + (long)((ch + 2) * 32 + kk) * N_ + nq);
            }
            CP_COMMIT();
        }
    }

    float g = gsc ? *gsc : 0.f;
    const float* resb = res ? res + sR * b : nullptr;
    float* Ob = Out + sO * b;
    #pragma unroll
    for (int mt = 0; mt < 2; mt++) {
        int row = m0 + wm * 32 + mt * 16 + (lane >> 2);
        #pragma unroll
        for (int nt = 0; nt < 8; nt++) {
            int col = n0 + wn * 64 + nt * 8 + 2 * (lane & 3);
            long o = (long)row * N_ + col;
            if (epi == 0) {
                float bv = bias[row], bv8 = bias[row + 8];
                *(float2*)(Ob + o) = make_float2(acc[mt][nt][0] + bv, acc[mt][nt][1] + bv);
                *(float2*)(Ob + o + 8 * N_) =
                    make_float2(acc[mt][nt][2] + bv8, acc[mt][nt][3] + bv8);
            } else {
                *(float2*)(Ob + o) = make_float2(
                    fmaf(g, acc[mt][nt][0], resb[o]), fmaf(g, acc[mt][nt][1], resb[o + 1]));
                *(float2*)(Ob + o + 8 * N_) = make_float2(
                    fmaf(g, acc[mt][nt][2], resb[o + 8 * N_]),
                    fmaf(g, acc[mt][nt][3], resb[o + 8 * N_ + 1]));
            }
        }
    }
}

// =================================================================
// wf2h: reorder + convert weights to fp16: wfh[o][chunk32][pos9][ci16]
// =================================================================
__global__ void wf2h_k(const float* __restrict__ wf, __half* __restrict__ wfh) {
    __shared__ float row[4608];
    int o = blockIdx.x, tid = threadIdx.x;
    const float* src = wf + (long)o * 4608;
    for (int i = tid; i < 4608; i += 256) row[i] = src[i];
    __syncthreads();
    __half* dst = wfh + (long)o * 4608;
    for (int i = tid; i < 4608; i += 256) {
        int chunk = i / 144, r = i % 144, pos = r >> 4, cil = r & 15;
        dst[i] = __float2half(row[(chunk * 16 + cil) * 9 + pos]);
    }
}

// =================================================================
// cat2h: transpose+convert cat fp32 NCHW -> fp16 NHWC ([b][4096][512])
// =================================================================
__global__ void cat2h_k(const float* __restrict__ cat, __half* __restrict__ catsh) {
    __shared__ float t[32][33];
    int b = blockIdx.z;
    int ci0 = blockIdx.y * 32, p0 = blockIdx.x * 32;
    int tx = threadIdx.x, ty = threadIdx.y;   // (32, 8)
    #pragma unroll
    for (int i = 0; i < 4; i++)
        t[ty + 8 * i][tx] = cat[((long)b * 512 + ci0 + ty + 8 * i) * 4096 + p0 + tx];
    __syncthreads();
    #pragma unroll
    for (int i = 0; i < 4; i++)
        catsh[((long)b * 4096 + p0 + ty + 8 * i) * 512 + ci0 + tx] =
            __float2half(t[tx][ty + 8 * i]);
}

// =================================================================
// 3x3 conv 512 -> 256, implicit GEMM v4 (fp16 m16n8k16), M=256.
// k order = chunk(32 of 16ci) * (pos*16 + ci). A = wfh (pre-reordered),
// B read directly from NHWC fp16 patch. 2-stage cp.async.
// smem: A 2x[256][152] half (pad 152 -> conflict-free),
//       patch 2x[4row][68w][24ci-pad] half (48B w-stride, conflict-free).
// =================================================================
#define CV_A_STRIDE 152
#define CV_AS_H  (256 * CV_A_STRIDE)     // 38912 halves per stage
#define CV_PT_H  (4 * 68 * 24)           // 6528 halves per stage
#define CV_SMEM_BYTES ((2 * CV_AS_H + 2 * CV_PT_H) * 2)   // 181760

__global__ void __launch_bounds__(256, 1)
conv_mma(const __half* __restrict__ catsh, const __half* __restrict__ wfh,
         float* __restrict__ y) {
    extern __shared__ char smc[];
    __half* Asm = (__half*)smc;                    // 2 x [256][152]
    __half* Pt = Asm + 2 * CV_AS_H;                // 2 x [4][68][24]
    int tid = threadIdx.x, lane = tid & 31, wid = tid >> 5;
    int wm = wid & 3, wn = wid >> 2;
    int b = blockIdx.z, p0 = blockIdx.x * 128;
    int h0 = blockIdx.x * 2;
    uint32_t smu_a = smem_to_u32(Asm), smu_p = smem_to_u32(Pt);
    const __half* Cb = catsh + (long)b * 4096 * 512;

    for (int i = tid; i < 2 * CV_PT_H; i += 256) Pt[i] = __float2half(0.f);
    __syncthreads();

    float c[4][8][4] = {};

    // prologue: chunks 0,1
    #pragma unroll
    for (int s = 0; s < 2; s++) {
        #pragma unroll
        for (int j = 0; j < 18; j++) {       // weights: 256 rows x 18 cp16 (144 halves)
            int f = tid + 256 * j;
            int r = f / 18, q = (f % 18) * 8;
            cp16(smu_a + (s * CV_AS_H + r * CV_A_STRIDE + q) * 2,
                 wfh + (long)r * 4608 + s * 144 + q);
        }
        #pragma unroll
        for (int j = 0; j < 2; j++) {        // patch: 4row x 64w x 2 half-groups
            int f = tid + 256 * j;           // 0..511
            int ww = f & 63, rq = (f >> 6) & 3, hf = (f >> 8) & 1;
            int h = h0 - 1 + rq;
            if (h >= 0 && h < 64)
                cp16(smu_p + (s * CV_PT_H + (rq * 68 + ww + 2) * 24 + hf * 8) * 2,
                     Cb + ((long)h * 64 + ww) * 512 + s * 16 + hf * 8);
        }
        CP_COMMIT();
    }

    for (int chunk = 0; chunk < 32; chunk++) {
        if (chunk < 30) { CP_WAIT(1); } else { CP_WAIT(0); }
        __syncthreads();
        const __half* As_ = Asm + (chunk & 1) * CV_AS_H;
        const __half* Pt_ = Pt + (chunk & 1) * CV_PT_H;

        #pragma unroll
        for (int pos = 0; pos < 9; pos++) {
            const int kh = pos / 3, kw = pos % 3;
            uint32_t a[4][4], bb[8][2];
            #pragma unroll
            for (int mt = 0; mt < 4; mt++) {
                const __half* ap = As_ + (wm * 64 + mt * 16 + (lane >> 2)) * CV_A_STRIDE
                                   + pos * 16 + 2 * (lane & 3);
                a[mt][0] = *(const uint32_t*)ap;
                a[mt][1] = *(const uint32_t*)(ap + 8 * CV_A_STRIDE);
                a[mt][2] = *(const uint32_t*)(ap + 8);
                a[mt][3] = *(const uint32_t*)(ap + 8 * CV_A_STRIDE + 8);
            }
            {
                int nbase = wn * 64 + (lane >> 2);
                const __half* pb = Pt_ + (wn + kh) * 68 * 24 + 2 * (lane & 3);
                #pragma unroll
                for (int nt = 0; nt < 8; nt++) {
                    int wpos = ((nbase + nt * 8) & 63) + kw + 1;
                    bb[nt][0] = *(const uint32_t*)(pb + wpos * 24);
                    bb[nt][1] = *(const uint32_t*)(pb + wpos * 24 + 8);
                }
            }
            #pragma unroll
            for (int mt = 0; mt < 4; mt++)
                #pragma unroll
                for (int nt = 0; nt < 8; nt++)
                    mma_f16(c[mt][nt], a[mt][0], a[mt][1], a[mt][2], a[mt][3],
                            bb[nt][0], bb[nt][1]);
        }
        __syncthreads();
        if (chunk + 2 < 32) {
            int s = chunk & 1;
            #pragma unroll
            for (int j = 0; j < 18; j++) {
                int f = tid + 256 * j;
                int r = f / 18, q = (f % 18) * 8;
                cp16(smu_a + (s * CV_AS_H + r * CV_A_STRIDE + q) * 2,
                     wfh + (long)r * 4608 + (chunk + 2) * 144 + q);
            }
            #pragma unroll
            for (int j = 0; j < 2; j++) {
                int f = tid + 256 * j;
                int ww = f & 63, rq = (f >> 6) & 3, hf = (f >> 8) & 1;
                int h = h0 - 1 + rq;
                if (h >= 0 && h < 64)
                    cp16(smu_p + (s * CV_PT_H + (rq * 68 + ww + 2) * 24 + hf * 8) * 2,
                         Cb + ((long)h * 64 + ww) * 512 + (chunk + 2) * 16 + hf * 8);
            }
            CP_COMMIT();
        }
    }

    #pragma unroll
    for (int mt = 0; mt < 4; mt++) {
        #pragma unroll
        for (int nt = 0; nt < 8; nt++) {
            int row = wm * 64 + mt * 16 + (lane >> 2);
            int col = p0 + wn * 64 + nt * 8 + 2 * (lane & 3);
            long yo = ((long)b * 256 + row) * 4096 + col;
            *(float2*)(y + yo) = make_float2(c[mt][nt][0], c[mt][nt][1]);
            *(float2*)(y + yo + 8 * 4096) = make_float2(c[mt][nt][2], c[mt][nt][3]);
        }
    }
}

// ---------------- helpers ----------------
__device__ __forceinline__ float warpMax(float v) {
    #pragma unroll
    for (int o = 16; o; o >>= 1) v = fmaxf(v, __shfl_xor_sync(0xffffffffu, v, o));
    return v;
}
__device__ __forceinline__ float warpSum(float v) {
    #pragma unroll
    for (int o = 16; o; o >>= 1) v += __shfl_xor_sync(0xffffffffu, v, o);
    return v;
}

// ---------------- merged q+k projection (fp32 SIMT, M=64) ----------------
__global__ void qk_proj(const float* __restrict__ wq, const float* __restrict__ bq,
                        const float* __restrict__ wk, const float* __restrict__ bk,
                        const float* __restrict__ x, float* __restrict__ q,
                        float* __restrict__ k) {
    __shared__ float As[16][64];
    __shared__ float Bs[16][64];
    int b = blockIdx.z;
    const float* Bm = x + (long)b * C_ * N_;
    int tid = threadIdx.x;
    int tx = tid & 15, ty = tid >> 4;
    int n0 = blockIdx.x * 64;
    int arow = tid >> 2, ak = (tid & 3) * 4;
    int brow = tid >> 4, bn = (tid & 15) * 4;
    const float* Arow = (arow < 32) ? (wq + (long)arow * C_)
                                    : (wk + (long)(arow - 32) * C_);
    float acc[4][4] = {};
    for (int k0 = 0; k0 < C_; k0 += 16) {
        float4 av = *(const float4*)(Arow + k0 + ak);
        As[ak + 0][arow] = av.x; As[ak + 1][arow] = av.y;
        As[ak + 2][arow] = av.z; As[ak + 3][arow] = av.w;
        *(float4*)&Bs[brow][bn] = *(const float4*)(Bm + (long)(k0 + brow) * N_ + n0 + bn);
        __syncthreads();
        #pragma unroll
        for (int kk = 0; kk < 16; kk++) {
            float4 a = *(const float4*)&As[kk][ty * 4];
            float4 bv = *(const float4*)&Bs[kk][tx * 4];
            float ar[4] = {a.x, a.y, a.z, a.w};
            float br[4] = {bv.x, bv.y, bv.z, bv.w};
            #pragma unroll
            for (int i = 0; i < 4; i++)
                #pragma unroll
                for (int j = 0; j < 4; j++)
                    acc[i][j] = fmaf(ar[i], br[j], acc[i][j]);
        }
        __syncthreads();
    }
    #pragma unroll
    for (int i = 0; i < 4; i++) {
        int m = ty * 4 + i;
        float bv = (m < 32) ? bq[m] : bk[m - 32];
        float* Out = (m < 32) ? (q + ((long)b * CQ_ + m) * N_)
                              : (k + ((long)b * CQ_ + m - 32) * N_);
        *(float4*)(Out + n0 + tx * 4) = make_float4(
            acc[i][0] + bv, acc[i][1] + bv, acc[i][2] + bv, acc[i][3] + bv);
    }
}

// ---------------- softmax over 256 with split-K reduction ----------------
__global__ void softmax256(const float* __restrict__ part, float* __restrict__ out) {
    __shared__ float sh[8];
    int tid = threadIdx.x;
    int row = blockIdx.x;
    int b = row >> 8, i = row & 255;
    float v = 0.f;
    #pragma unroll
    for (int ks = 0; ks < 8; ks++)
        v += part[((long)(b * 8 + ks) * C_ + i) * C_ + tid];
    float m = warpMax(v);
    if ((tid & 31) == 0) sh[tid >> 5] = m;
    __syncthreads();
    m = sh[tid & 7];
    #pragma unroll
    for (int o = 4; o; o >>= 1) m = fmaxf(m, __shfl_xor_sync(0xffffffffu, m, o));
    __syncthreads();
    float e = __expf(v - m);
    float s = warpSum(e);
    if ((tid & 31) == 0) sh[tid >> 5] = s;
    __syncthreads();
    s = sh[tid & 7];
    #pragma unroll
    for (int o = 4; o; o >>= 1) s += __shfl_xor_sync(0xffffffffu, s, o);
    out[(long)row * 256 + tid] = e / s;
}

// ---------------- BN (train-mode batch stats) + ReLU ----------------
__global__ void bnstats(const float* __restrict__ y, float* __restrict__ meanp,
                        float* __restrict__ rstdp) {
    __shared__ float sh[16];
    int o = blockIdx.x, tid = threadIdx.x;
    float s = 0.f, sq = 0.f;
    for (int b = 0; b < 4; b++) {
        const float4* p = (const float4*)(y + ((size_t)b * 256 + o) * 4096);
        for (int i = tid; i < 1024; i += 256) {
            float4 v = p[i];
            s += v.x + v.y + v.z + v.w;
            sq += v.x * v.x + v.y * v.y + v.z * v.z + v.w * v.w;
        }
    }
    s = warpSum(s); sq = warpSum(sq);
    if ((tid & 31) == 0) { sh[tid >> 5] = s; sh[8 + (tid >> 5)] = sq; }
    __syncthreads();
    if (tid == 0) {
        float S = 0.f, SQ = 0.f;
        for (int i = 0; i < 8; i++) { S += sh[i]; SQ += sh[8 + i]; }
        float mean = S / 16384.f;
        float var = SQ / 16384.f - mean * mean;
        meanp[o] = mean;
        rstdp[o] = rsqrtf(var + 1e-5f);
    }
}

__global__ void bnapply(const float* __restrict__ y, const float* __restrict__ gam,
                        const float* __restrict__ bet, const float* __restrict__ meanp,
                        const float* __restrict__ rstdp, float* __restrict__ out) {
    size_t i = (size_t)blockIdx.x * 256 + threadIdx.x;
    int o = (int)((i >> 10) & 255);
    float mu = meanp[o], rs = rstdp[o], g = gam[o], be = bet[o];
    float4 v = ((const float4*)y)[i];
    float4 r;
    r.x = fmaxf(0.f, fmaf((v.x - mu) * rs, g, be));
    r.y = fmaxf(0.f, fmaf((v.y - mu) * rs, g, be));
    r.z = fmaxf(0.f, fmaf((v.z - mu) * rs, g, be));
    r.w = fmaxf(0.f, fmaf((v.w - mu) * rs, g, be));
    ((float4*)out)[i] = r;
}

// ---------------- launcher ----------------
extern "C" void kernel_launch(void* const* d_in, const int* in_sizes, int n_in,
                              void* d_out, int out_size) {
    const float* x   = (const float*)d_in[0];
    const float* wq  = (const float*)d_in[1];
    const float* bq  = (const float*)d_in[2];
    const float* wk  = (const float*)d_in[3];
    const float* bk  = (const float*)d_in[4];
    const float* wv  = (const float*)d_in[5];
    const float* bv  = (const float*)d_in[6];
    const float* gpa = (const float*)d_in[7];
    const float* gca = (const float*)d_in[8];
    const float* wf  = (const float*)d_in[9];
    const float* bng = (const float*)d_in[10];
    const float* bnb = (const float*)d_in[11];
    float* out = (float*)d_out;

    float *q, *k, *cat, *cattn, *cattn_part, *y, *mean, *rstd;
    __nv_bfloat16* v;
    __half *catsh, *wfh;
    cudaGetSymbolAddress((void**)&q, g_q);
    cudaGetSymbolAddress((void**)&k, g_k);
    cudaGetSymbolAddress((void**)&v, g_v);
    cudaGetSymbolAddress((void**)&cat, g_cat);
    cudaGetSymbolAddress((void**)&catsh, g_catsh);
    cudaGetSymbolAddress((void**)&wfh, g_wfh);
    cudaGetSymbolAddress((void**)&cattn, g_cattn);
    cudaGetSymbolAddress((void**)&cattn_part, g_cattn_part);
    cudaGetSymbolAddress((void**)&y, g_y);
    cudaGetSymbolAddress((void**)&mean, g_mean);
    cudaGetSymbolAddress((void**)&rstd, g_rstd);

    cudaFuncSetAttribute(pa_flash, cudaFuncAttributeMaxDynamicSharedMemorySize,
                         PF_SMEM_BYTES);
    cudaFuncSetAttribute(v_proj, cudaFuncAttributeMaxDynamicSharedMemorySize,
                         NN_SMEM_BYTES);
    cudaFuncSetAttribute(gemm_nn_mma, cudaFuncAttributeMaxDynamicSharedMemorySize,
                         NN_SMEM_BYTES);
    cudaFuncSetAttribute(xxT_mma, cudaFuncAttributeMaxDynamicSharedMemorySize,
                         XT_SMEM_BYTES);
    cudaFuncSetAttribute(conv_mma, cudaFuncAttributeMaxDynamicSharedMemorySize,
                         CV_SMEM_BYTES);

    dim3 blk(256);
    long sx = (long)C_ * N_;
    long scat = (long)2 * C_ * N_;

    // weight reorder+fp16 (independent; overlaps with projections)
    wf2h_k<<<256, 256>>>(wf, wfh);
    // q + k projections in one kernel
    qk_proj<<<dim3(64, 1, 4), blk>>>(wq, bq, wk, bk, x, q, k);
    // v projection on tensor cores, bf16 output
    v_proj<<<dim3(32, 2, 4), blk, NN_SMEM_BYTES>>>(wv, x, v, bv, sx, sx);
    // fused flash position-attention (PV in bf16) -> cat[:, 0:256]
    pa_flash<<<dim3(32, 1, 4), blk, PF_SMEM_BYTES>>>(q, k, v, x, gpa, cat);
    // channel attention: split-K x.xT partials, fused-reduce softmax, apply
    xxT_mma<<<dim3(2, 2, 32), blk, XT_SMEM_BYTES>>>(x, cattn_part);
    softmax256<<<B_ * C_, 256>>>(cattn_part, cattn);
    gemm_nn_mma<<<dim3(32, 2, 4), blk, NN_SMEM_BYTES>>>(
        cattn, x, cat + (size_t)C_ * N_, C_, 1, nullptr, gca, x,
        (long)C_ * C_, sx, scat, sx);
    // cat -> fp16 NHWC
    cat2h_k<<<dim3(128, 16, 4), dim3(32, 8)>>>(cat, catsh);
    // 3x3 conv 512->256 (implicit GEMM v4, fp16 m16n8k16)
    conv_mma<<<dim3(32, 1, 4), blk, CV_SMEM_BYTES>>>(catsh, wfh, y);
    // BN train-mode + ReLU
    bnstats<<<256, 256>>>(y, mean, rstd);
    bnapply<<<4096, 256>>>(y, bng, bnb, mean, rstd, out);
}